// round 2
// baseline (speedup 1.0000x reference)
#include <cuda_runtime.h>
#include <math.h>

#define B_   32
#define SX_  2048
#define SY_  2048
#define DD   160

// Scratch for projected Q, K, V (static device globals: allowed, no runtime alloc)
__device__ float g_q[(size_t)B_ * SX_ * DD];
__device__ float g_k[(size_t)B_ * SY_ * DD];
__device__ float g_v[(size_t)B_ * SY_ * DD];

// ---------------------------------------------------------------------------
// Projection: out[m, n] = sum_d A[m, d] * W[n, d] + bias[n]
// (torch Linear: W is [out, in], NT gemm, both operands K-contiguous)
// BM=64, BN=160(all), BK=32, 256 threads, each thread 8 rows x 5 cols
// ---------------------------------------------------------------------------
__global__ __launch_bounds__(256) void proj_kernel(
    const float* __restrict__ A, const float* __restrict__ W,
    const float* __restrict__ bias, float* __restrict__ out)
{
    __shared__ float As[64][33];    // pad 33: conflict-free column reads
    __shared__ float Ws[160][33];

    const int tid = threadIdx.x;
    const int tx  = tid & 31;       // col group: cols tx + 32u
    const int ty  = tid >> 5;       // row group: rows ty*8 + i
    const size_t m0 = (size_t)blockIdx.x * 64;

    float acc[8][5];
#pragma unroll
    for (int i = 0; i < 8; i++)
#pragma unroll
        for (int u = 0; u < 5; u++) acc[i][u] = 0.f;

    for (int k0 = 0; k0 < DD; k0 += 32) {
        // A tile 64x32: 512 float4, 2 per thread
#pragma unroll
        for (int i = 0; i < 2; i++) {
            int idx = tid + i * 256;
            int r = idx >> 3, c = (idx & 7) << 2;
            float4 t = *(const float4*)(A + (m0 + r) * DD + k0 + c);
            As[r][c] = t.x; As[r][c+1] = t.y; As[r][c+2] = t.z; As[r][c+3] = t.w;
        }
        // W tile 160x32: 1280 float4, 5 per thread
#pragma unroll
        for (int i = 0; i < 5; i++) {
            int idx = tid + i * 256;
            int r = idx >> 3, c = (idx & 7) << 2;
            float4 t = *(const float4*)(W + (size_t)r * DD + k0 + c);
            Ws[r][c] = t.x; Ws[r][c+1] = t.y; Ws[r][c+2] = t.z; Ws[r][c+3] = t.w;
        }
        __syncthreads();

#pragma unroll
        for (int d = 0; d < 32; d++) {
            float a[8], w[5];
#pragma unroll
            for (int i = 0; i < 8; i++) a[i] = As[ty * 8 + i][d];   // broadcast
#pragma unroll
            for (int u = 0; u < 5; u++) w[u] = Ws[tx + 32 * u][d];  // conflict-free
#pragma unroll
            for (int i = 0; i < 8; i++)
#pragma unroll
                for (int u = 0; u < 5; u++)
                    acc[i][u] = fmaf(a[i], w[u], acc[i][u]);
        }
        __syncthreads();
    }

#pragma unroll
    for (int u = 0; u < 5; u++) {
        float bv = bias[tx + 32 * u];
#pragma unroll
        for (int i = 0; i < 8; i++)
            out[(m0 + ty * 8 + i) * DD + tx + 32 * u] = acc[i][u] + bv;
    }
}

// ---------------------------------------------------------------------------
// Flash attention + residual.
// Block: 64 query rows of one batch. 256 threads.
//   ty = tid/16 -> rows  {ty + 16i},  i<4   (row group = 16-lane half warp)
//   tx = tid%16 -> Scols {tx + 16u},  u<4 ; Ocols {tx + 16u}, u<10
// SMEM paddings: Qs/Ks stride 161 (conflict-free strided col reads),
//                Vs stride 164 (float4 stores, conflict-free reads),
//                Ps stride 65.
// ---------------------------------------------------------------------------
#define QS_LD 161
#define KS_LD 161
#define VS_LD 164
#define PS_LD 65
#define SMEM_FLOATS (64*QS_LD + 64*KS_LD + 64*VS_LD + 64*PS_LD)

__global__ __launch_bounds__(256) void attn_kernel(
    const float* __restrict__ gq, const float* __restrict__ gk,
    const float* __restrict__ gv, const float* __restrict__ gx,
    float* __restrict__ gout)
{
    extern __shared__ float sm[];
    float* Qs = sm;                     // [64][161]
    float* Ks = Qs + 64 * QS_LD;        // [64][161]
    float* Vs = Ks + 64 * KS_LD;        // [64][164]
    float* Ps = Vs + 64 * VS_LD;        // [64][65]

    const int tid = threadIdx.x;
    const int tx  = tid & 15;
    const int ty  = tid >> 4;
    const int b   = blockIdx.y;
    const size_t m0 = (size_t)blockIdx.x * 64;

    // Load Q tile (64 x 160), coalesced float4
    const float* qbase = gq + ((size_t)b * SX_ + m0) * DD;
#pragma unroll
    for (int i = 0; i < 10; i++) {
        int idx = tid + i * 256;
        int r = idx / 40, c = (idx % 40) * 4;
        float4 t = *(const float4*)(qbase + (size_t)r * DD + c);
        float* dst = Qs + r * QS_LD + c;
        dst[0] = t.x; dst[1] = t.y; dst[2] = t.z; dst[3] = t.w;
    }

    float m_r[4], l_r[4], O[4][10];
#pragma unroll
    for (int i = 0; i < 4; i++) {
        m_r[i] = -INFINITY; l_r[i] = 0.f;
#pragma unroll
        for (int u = 0; u < 10; u++) O[i][u] = 0.f;
    }

    const float* kbase = gk + (size_t)b * SY_ * DD;
    const float* vbase = gv + (size_t)b * SY_ * DD;

    for (int j0 = 0; j0 < SY_; j0 += 64) {
        __syncthreads();   // prev-iter PV done (and Q visible on iter 0)

        // Load K, V tiles (64 x 160 each)
#pragma unroll
        for (int i = 0; i < 10; i++) {
            int idx = tid + i * 256;
            int r = idx / 40, c = (idx % 40) * 4;
            float4 tk = *(const float4*)(kbase + (size_t)(j0 + r) * DD + c);
            float* dk = Ks + r * KS_LD + c;
            dk[0] = tk.x; dk[1] = tk.y; dk[2] = tk.z; dk[3] = tk.w;
            float4 tv = *(const float4*)(vbase + (size_t)(j0 + r) * DD + c);
            *(float4*)(Vs + r * VS_LD + c) = tv;
        }
        __syncthreads();

        // S = Q K^T  (64x64 over D=160), 4x4 per thread
        float S[4][4];
#pragma unroll
        for (int i = 0; i < 4; i++)
#pragma unroll
            for (int u = 0; u < 4; u++) S[i][u] = 0.f;

#pragma unroll 8
        for (int d = 0; d < DD; d++) {
            float qv[4], kv[4];
#pragma unroll
            for (int i = 0; i < 4; i++) qv[i] = Qs[(ty + 16 * i) * QS_LD + d];
#pragma unroll
            for (int u = 0; u < 4; u++) kv[u] = Ks[(tx + 16 * u) * KS_LD + d];
#pragma unroll
            for (int i = 0; i < 4; i++)
#pragma unroll
                for (int u = 0; u < 4; u++)
                    S[i][u] = fmaf(qv[i], kv[u], S[i][u]);
        }

        // Online softmax (row = 16 lanes sharing ty; xor-shfl over {8,4,2,1})
#pragma unroll
        for (int i = 0; i < 4; i++) {
            float mt = fmaxf(fmaxf(S[i][0], S[i][1]), fmaxf(S[i][2], S[i][3]));
#pragma unroll
            for (int off = 8; off >= 1; off >>= 1)
                mt = fmaxf(mt, __shfl_xor_sync(0xffffffffu, mt, off));
            float mnew  = fmaxf(m_r[i], mt);
            float alpha = __expf(m_r[i] - mnew);
            float p[4], ps = 0.f;
#pragma unroll
            for (int u = 0; u < 4; u++) { p[u] = __expf(S[i][u] - mnew); ps += p[u]; }
#pragma unroll
            for (int off = 8; off >= 1; off >>= 1)
                ps += __shfl_xor_sync(0xffffffffu, ps, off);
            l_r[i] = l_r[i] * alpha + ps;
            m_r[i] = mnew;
#pragma unroll
            for (int u = 0; u < 4; u++)
                Ps[(ty + 16 * i) * PS_LD + tx + 16 * u] = p[u];
#pragma unroll
            for (int u = 0; u < 10; u++) O[i][u] *= alpha;
        }
        __syncthreads();

        // O += P @ V  (64x160 over 64), 4 rows x 10 cols per thread
#pragma unroll 4
        for (int j = 0; j < 64; j++) {
            float pv[4], vv[10];
#pragma unroll
            for (int i = 0; i < 4; i++) pv[i] = Ps[(ty + 16 * i) * PS_LD + j];
#pragma unroll
            for (int u = 0; u < 10; u++) vv[u] = Vs[j * VS_LD + tx + 16 * u];
#pragma unroll
            for (int i = 0; i < 4; i++)
#pragma unroll
                for (int u = 0; u < 10; u++)
                    O[i][u] = fmaf(pv[i], vv[u], O[i][u]);
        }
    }

    // Epilogue: normalize, add residual, write out
    const float* xbase = gx   + ((size_t)b * SX_ + m0) * DD;
    float*       obase = gout + ((size_t)b * SX_ + m0) * DD;
#pragma unroll
    for (int i = 0; i < 4; i++) {
        float inv = 1.f / l_r[i];
        int r = ty + 16 * i;
#pragma unroll
        for (int u = 0; u < 10; u++) {
            int e = tx + 16 * u;
            obase[(size_t)r * DD + e] = O[i][u] * inv + xbase[(size_t)r * DD + e];
        }
    }
}

// ---------------------------------------------------------------------------
extern "C" void kernel_launch(void* const* d_in, const int* in_sizes, int n_in,
                              void* d_out, int out_size)
{
    const float* x  = (const float*)d_in[0];
    const float* y  = (const float*)d_in[1];
    const float* Wq = (const float*)d_in[2];
    const float* bq = (const float*)d_in[3];
    const float* Wk = (const float*)d_in[4];
    const float* bk = (const float*)d_in[5];
    const float* Wv = (const float*)d_in[6];
    const float* bv = (const float*)d_in[7];
    float* out = (float*)d_out;

    float *qp, *kp, *vp;
    cudaGetSymbolAddress((void**)&qp, g_q);
    cudaGetSymbolAddress((void**)&kp, g_k);
    cudaGetSymbolAddress((void**)&vp, g_v);

    proj_kernel<<<(B_ * SX_) / 64, 256>>>(x, Wq, bq, qp);
    proj_kernel<<<(B_ * SY_) / 64, 256>>>(y, Wk, bk, kp);
    proj_kernel<<<(B_ * SY_) / 64, 256>>>(y, Wv, bv, vp);

    const int smem_bytes = SMEM_FLOATS * (int)sizeof(float);  // 141056 B
    cudaFuncSetAttribute(attn_kernel,
                         cudaFuncAttributeMaxDynamicSharedMemorySize, smem_bytes);
    dim3 grid(SX_ / 64, B_);
    attn_kernel<<<grid, 256, smem_bytes>>>(qp, kp, vp, x, out);
}

// round 4
// speedup vs baseline: 3.1501x; 3.1501x over previous
#include <cuda_runtime.h>
#include <cuda_bf16.h>
#include <math.h>
#include <stdint.h>

#define B_    32
#define SXX   2048
#define SYY   2048
#define DD    160
#define BM    128
#define BN    32
#define NT    (SYY / BN)
#define ROWB  336          // padded row pitch in bytes (168 bf16)

// hi/lo bf16 decompositions of projected Q, K, V (natural [b][m][d] layout)
__device__ __nv_bfloat16 g_qhi[(size_t)B_ * SXX * DD];
__device__ __nv_bfloat16 g_qlo[(size_t)B_ * SXX * DD];
__device__ __nv_bfloat16 g_khi[(size_t)B_ * SYY * DD];
__device__ __nv_bfloat16 g_klo[(size_t)B_ * SYY * DD];
__device__ __nv_bfloat16 g_vhi[(size_t)B_ * SYY * DD];
__device__ __nv_bfloat16 g_vlo[(size_t)B_ * SYY * DD];

// ---------------------------------------------------------------------------
// low-level helpers (all base-target sm_80+ instructions; no 'a' features)
// ---------------------------------------------------------------------------
__device__ __forceinline__ uint32_t smem_u32(const void* p) {
    uint32_t r;
    asm("{ .reg .u64 t; cvta.to.shared.u64 t, %1; cvt.u32.u64 %0, t; }"
        : "=r"(r) : "l"(p));
    return r;
}
__device__ __forceinline__ void cp16(uint32_t s, const void* g) {
    asm volatile("cp.async.cg.shared.global [%0], [%1], 16;" :: "r"(s), "l"(g));
}
__device__ __forceinline__ void cp_commit() {
    asm volatile("cp.async.commit_group;" ::: "memory");
}
__device__ __forceinline__ void cp_wait_all() {
    asm volatile("cp.async.wait_group 0;" ::: "memory");
}
__device__ __forceinline__ void ldsm4(uint32_t* r, uint32_t a) {
    asm volatile("ldmatrix.sync.aligned.m8n8.x4.shared.b16 {%0,%1,%2,%3}, [%4];"
                 : "=r"(r[0]), "=r"(r[1]), "=r"(r[2]), "=r"(r[3]) : "r"(a));
}
__device__ __forceinline__ void ldsm4t(uint32_t* r, uint32_t a) {
    asm volatile("ldmatrix.sync.aligned.m8n8.x4.trans.shared.b16 {%0,%1,%2,%3}, [%4];"
                 : "=r"(r[0]), "=r"(r[1]), "=r"(r[2]), "=r"(r[3]) : "r"(a));
}
__device__ __forceinline__ void mma_bf16(float* c, const uint32_t* a,
                                         uint32_t b0, uint32_t b1) {
    asm volatile("mma.sync.aligned.m16n8k16.row.col.f32.bf16.bf16.f32 "
                 "{%0,%1,%2,%3}, {%4,%5,%6,%7}, {%8,%9}, {%0,%1,%2,%3};"
                 : "+f"(c[0]), "+f"(c[1]), "+f"(c[2]), "+f"(c[3])
                 : "r"(a[0]), "r"(a[1]), "r"(a[2]), "r"(a[3]), "r"(b0), "r"(b1));
}
__device__ __forceinline__ uint32_t packbf(float a, float b) {
    __nv_bfloat162 t = __floats2bfloat162_rn(a, b);
    return *reinterpret_cast<uint32_t*>(&t);
}

// ---------------------------------------------------------------------------
// Projection (exact fp32 GEMM; emits bf16 hi/lo)
// out[m,n] = sum_d A[m,d] * W[n,d] + bias[n]
// ---------------------------------------------------------------------------
__global__ __launch_bounds__(256) void proj_kernel(
    const float* __restrict__ A, const float* __restrict__ W,
    const float* __restrict__ bias,
    __nv_bfloat16* __restrict__ ohi, __nv_bfloat16* __restrict__ olo)
{
    __shared__ float As[64][33];
    __shared__ float Ws[160][33];

    const int tid = threadIdx.x;
    const int tx  = tid & 31;
    const int ty  = tid >> 5;
    const size_t m0 = (size_t)blockIdx.x * 64;

    float acc[8][5];
#pragma unroll
    for (int i = 0; i < 8; i++)
#pragma unroll
        for (int u = 0; u < 5; u++) acc[i][u] = 0.f;

    for (int k0 = 0; k0 < DD; k0 += 32) {
#pragma unroll
        for (int i = 0; i < 2; i++) {
            int idx = tid + i * 256;
            int r = idx >> 3, c = (idx & 7) << 2;
            float4 t = *(const float4*)(A + (m0 + r) * DD + k0 + c);
            As[r][c] = t.x; As[r][c+1] = t.y; As[r][c+2] = t.z; As[r][c+3] = t.w;
        }
#pragma unroll
        for (int i = 0; i < 5; i++) {
            int idx = tid + i * 256;
            int r = idx >> 3, c = (idx & 7) << 2;
            float4 t = *(const float4*)(W + (size_t)r * DD + k0 + c);
            Ws[r][c] = t.x; Ws[r][c+1] = t.y; Ws[r][c+2] = t.z; Ws[r][c+3] = t.w;
        }
        __syncthreads();
#pragma unroll
        for (int d = 0; d < 32; d++) {
            float a[8], w[5];
#pragma unroll
            for (int i = 0; i < 8; i++) a[i] = As[ty * 8 + i][d];
#pragma unroll
            for (int u = 0; u < 5; u++) w[u] = Ws[tx + 32 * u][d];
#pragma unroll
            for (int i = 0; i < 8; i++)
#pragma unroll
                for (int u = 0; u < 5; u++)
                    acc[i][u] = fmaf(a[i], w[u], acc[i][u]);
        }
        __syncthreads();
    }

#pragma unroll
    for (int u = 0; u < 5; u++) {
        int n = tx + 32 * u;
        float bv = bias[n];
#pragma unroll
        for (int i = 0; i < 8; i++) {
            size_t idx = (m0 + ty * 8 + i) * DD + n;
            float val = acc[i][u] + bv;
            __nv_bfloat16 h = __float2bfloat16_rn(val);
            ohi[idx] = h;
            olo[idx] = __float2bfloat16_rn(val - __bfloat162float(h));
        }
    }
}

// ---------------------------------------------------------------------------
// HMMA flash attention.
// SMEM bytes: Qh [128][336] @0, Ql @43008,
//             buf{0,1} @86016/@129024: Kh +0, Kl +10752, Vh +21504, Vl +32256
// ---------------------------------------------------------------------------
#define SQH   0
#define SQL   43008
#define SB0   86016
#define SB1   129024
#define MKH   0
#define MKL   10752
#define MVH   21504
#define MVL   32256
#define SMEM_TOTAL 172032

__global__ __launch_bounds__(256, 1) void attn_kernel(
    const __nv_bfloat16* __restrict__ qhi, const __nv_bfloat16* __restrict__ qlo,
    const __nv_bfloat16* __restrict__ khi, const __nv_bfloat16* __restrict__ klo,
    const __nv_bfloat16* __restrict__ vhi, const __nv_bfloat16* __restrict__ vlo,
    const float* __restrict__ gx, float* __restrict__ gout)
{
    extern __shared__ char smem[];
    const uint32_t sb = smem_u32(smem);
    const int tid  = threadIdx.x;
    const int lane = tid & 31;
    const int w    = tid >> 5;
    const int b    = blockIdx.y;
    const int m0   = blockIdx.x * BM;

    // ---- load Q (hi/lo) into SMEM ----
    {
        const size_t qrow = ((size_t)b * SXX + m0);
#pragma unroll
        for (int i = 0; i < 20; i++) {
            int idx  = i * 256 + tid;           // < 5120
            int half = idx / 2560;
            int rem  = idx - half * 2560;
            int row  = rem / 20, cc = rem - row * 20;
            const __nv_bfloat16* g =
                (half ? qlo : qhi) + (qrow + row) * DD + cc * 8;
            cp16(sb + (half ? SQL : SQH) + row * ROWB + cc * 16, g);
        }
    }

    const __nv_bfloat16* gsrc[4] = {
        khi + (size_t)b * SYY * DD, klo + (size_t)b * SYY * DD,
        vhi + (size_t)b * SYY * DD, vlo + (size_t)b * SYY * DD };
    const int moff[4] = { MKH, MKL, MVH, MVL };

    // ---- tile 0 ----
#pragma unroll
    for (int i = 0; i < 10; i++) {
        int idx = i * 256 + tid;                // < 2560
        int mat = idx / 640;
        int rem = idx - mat * 640;
        int row = rem / 20, cc = rem - row * 20;
        cp16(sb + SB0 + moff[mat] + row * ROWB + cc * 16,
             gsrc[mat] + (size_t)row * DD + cc * 8);
    }
    cp_commit();
    cp_wait_all();
    __syncthreads();

    // per-lane fragment address bases
    const uint32_t qOff = (uint32_t)((16 * w + (lane & 15)) * ROWB
                                     + ((lane >> 4) << 4));
    const uint32_t kOff = (uint32_t)(((lane & 7) + ((lane >> 4) << 3)) * ROWB
                                     + (((lane >> 3) & 1) << 4));
    const uint32_t vOff = (uint32_t)(((lane & 7) + (((lane >> 3) & 1) << 3)) * ROWB
                                     + ((lane >> 4) << 4));

    float o[20][4];
#pragma unroll
    for (int j = 0; j < 20; j++)
#pragma unroll
        for (int u = 0; u < 4; u++) o[j][u] = 0.f;

    float mh01 = 0.f, mh23 = 0.f, ls01 = 0.f, ls23 = 0.f;

    for (int t = 0; t < NT; t++) {
        const uint32_t buf = sb + ((t & 1) ? SB1 : SB0);

        // prefetch next tile into other buffer
        if (t + 1 < NT) {
            const uint32_t nbuf = sb + (((t + 1) & 1) ? SB1 : SB0);
            const size_t grow = (size_t)(t + 1) * BN;
#pragma unroll
            for (int i = 0; i < 10; i++) {
                int idx = i * 256 + tid;
                int mat = idx / 640;
                int rem = idx - mat * 640;
                int row = rem / 20, cc = rem - row * 20;
                cp16(nbuf + moff[mat] + row * ROWB + cc * 16,
                     gsrc[mat] + (grow + row) * DD + cc * 8);
            }
            cp_commit();
        }

        // ---- S = Q K^T (16x32 per warp, D=160) ----
        float c[4][4];
#pragma unroll
        for (int j = 0; j < 4; j++)
#pragma unroll
            for (int u = 0; u < 4; u++) c[j][u] = 0.f;

#pragma unroll
        for (int ks = 0; ks < 10; ks++) {
            uint32_t ah[4], al[4], bh[8], bl[8];
            ldsm4(ah, sb + SQH + qOff + ks * 32);
            ldsm4(al, sb + SQL + qOff + ks * 32);
            ldsm4(bh,     buf + MKH + kOff + ks * 32);
            ldsm4(bh + 4, buf + MKH + kOff + 16 * ROWB + ks * 32);
            ldsm4(bl,     buf + MKL + kOff + ks * 32);
            ldsm4(bl + 4, buf + MKL + kOff + 16 * ROWB + ks * 32);
#pragma unroll
            for (int j = 0; j < 4; j++) {
                mma_bf16(c[j], ah, bh[2 * j], bh[2 * j + 1]);
                mma_bf16(c[j], ah, bl[2 * j], bl[2 * j + 1]);
                mma_bf16(c[j], al, bh[2 * j], bh[2 * j + 1]);
            }
        }

        // ---- softmax (fixed mhat from tile 0) + P hi/lo a-frags ----
        if (t == 0) {
            float m01 = c[0][0], m23 = c[0][2];
#pragma unroll
            for (int j = 0; j < 4; j++) {
                m01 = fmaxf(m01, fmaxf(c[j][0], c[j][1]));
                m23 = fmaxf(m23, fmaxf(c[j][2], c[j][3]));
            }
            m01 = fmaxf(m01, __shfl_xor_sync(0xffffffffu, m01, 1));
            m01 = fmaxf(m01, __shfl_xor_sync(0xffffffffu, m01, 2));
            m23 = fmaxf(m23, __shfl_xor_sync(0xffffffffu, m23, 1));
            m23 = fmaxf(m23, __shfl_xor_sync(0xffffffffu, m23, 2));
            mh01 = m01; mh23 = m23;
        }

        uint32_t pah[2][4], pal[2][4];
#pragma unroll
        for (int j = 0; j < 4; j++) {
            float p0 = __expf(c[j][0] - mh01);
            float p1 = __expf(c[j][1] - mh01);
            float p2 = __expf(c[j][2] - mh23);
            float p3 = __expf(c[j][3] - mh23);
            ls01 += p0 + p1; ls23 += p2 + p3;
            __nv_bfloat16 h0 = __float2bfloat16_rn(p0);
            __nv_bfloat16 h1 = __float2bfloat16_rn(p1);
            __nv_bfloat16 h2 = __float2bfloat16_rn(p2);
            __nv_bfloat16 h3 = __float2bfloat16_rn(p3);
            int ks = j >> 1, sl = (j & 1) << 1;
            pah[ks][sl]     = ((uint32_t)__bfloat16_as_ushort(h1) << 16)
                            |  (uint32_t)__bfloat16_as_ushort(h0);
            pah[ks][sl + 1] = ((uint32_t)__bfloat16_as_ushort(h3) << 16)
                            |  (uint32_t)__bfloat16_as_ushort(h2);
            pal[ks][sl]     = packbf(p0 - __bfloat162float(h0),
                                     p1 - __bfloat162float(h1));
            pal[ks][sl + 1] = packbf(p2 - __bfloat162float(h2),
                                     p3 - __bfloat162float(h3));
        }

        // ---- O += P V  (k = 32, n = 160) ----
#pragma unroll
        for (int ks = 0; ks < 2; ks++) {
#pragma unroll
            for (int jp = 0; jp < 10; jp++) {
                uint32_t v4h[4], v4l[4];
                ldsm4t(v4h, buf + MVH + vOff + ks * (16 * ROWB) + jp * 32);
                ldsm4t(v4l, buf + MVL + vOff + ks * (16 * ROWB) + jp * 32);
                mma_bf16(o[2 * jp],     pah[ks], v4h[0], v4h[1]);
                mma_bf16(o[2 * jp + 1], pah[ks], v4h[2], v4h[3]);
                mma_bf16(o[2 * jp],     pah[ks], v4l[0], v4l[1]);
                mma_bf16(o[2 * jp + 1], pah[ks], v4l[2], v4l[3]);
                mma_bf16(o[2 * jp],     pal[ks], v4h[0], v4h[1]);
                mma_bf16(o[2 * jp + 1], pal[ks], v4h[2], v4h[3]);
            }
        }

        cp_wait_all();
        __syncthreads();
    }

    // ---- epilogue: normalize, residual, store ----
    ls01 += __shfl_xor_sync(0xffffffffu, ls01, 1);
    ls01 += __shfl_xor_sync(0xffffffffu, ls01, 2);
    ls23 += __shfl_xor_sync(0xffffffffu, ls23, 1);
    ls23 += __shfl_xor_sync(0xffffffffu, ls23, 2);
    const float inv01 = 1.f / ls01;
    const float inv23 = 1.f / ls23;

    const int r0 = m0 + 16 * w + (lane >> 2);
    const size_t row0 = ((size_t)b * SXX + r0) * DD;
    const size_t row1 = row0 + 8 * DD;
    const int cb = 2 * (lane & 3);
#pragma unroll
    for (int j = 0; j < 20; j++) {
        int cc = 8 * j + cb;
        float2 x0 = *(const float2*)(gx + row0 + cc);
        float2 x1 = *(const float2*)(gx + row1 + cc);
        float2 r0v, r1v;
        r0v.x = o[j][0] * inv01 + x0.x;
        r0v.y = o[j][1] * inv01 + x0.y;
        r1v.x = o[j][2] * inv23 + x1.x;
        r1v.y = o[j][3] * inv23 + x1.y;
        *(float2*)(gout + row0 + cc) = r0v;
        *(float2*)(gout + row1 + cc) = r1v;
    }
}

// ---------------------------------------------------------------------------
extern "C" void kernel_launch(void* const* d_in, const int* in_sizes, int n_in,
                              void* d_out, int out_size)
{
    const float* x  = (const float*)d_in[0];
    const float* y  = (const float*)d_in[1];
    const float* Wq = (const float*)d_in[2];
    const float* bq = (const float*)d_in[3];
    const float* Wk = (const float*)d_in[4];
    const float* bk = (const float*)d_in[5];
    const float* Wv = (const float*)d_in[6];
    const float* bv = (const float*)d_in[7];
    float* out = (float*)d_out;

    __nv_bfloat16 *qh, *ql, *kh, *kl, *vh, *vl;
    cudaGetSymbolAddress((void**)&qh, g_qhi);
    cudaGetSymbolAddress((void**)&ql, g_qlo);
    cudaGetSymbolAddress((void**)&kh, g_khi);
    cudaGetSymbolAddress((void**)&kl, g_klo);
    cudaGetSymbolAddress((void**)&vh, g_vhi);
    cudaGetSymbolAddress((void**)&vl, g_vlo);

    proj_kernel<<<(B_ * SXX) / 64, 256>>>(x, Wq, bq, qh, ql);
    proj_kernel<<<(B_ * SYY) / 64, 256>>>(y, Wk, bk, kh, kl);
    proj_kernel<<<(B_ * SYY) / 64, 256>>>(y, Wv, bv, vh, vl);

    cudaFuncSetAttribute(attn_kernel,
                         cudaFuncAttributeMaxDynamicSharedMemorySize, SMEM_TOTAL);
    dim3 grid(SXX / BM, B_);
    attn_kernel<<<grid, 256, SMEM_TOTAL>>>(qh, ql, kh, kl, vh, vl, x, out);
}

// round 5
// speedup vs baseline: 3.1997x; 1.0158x over previous
#include <cuda_runtime.h>
#include <cuda_bf16.h>
#include <math.h>
#include <stdint.h>

#define B_    32
#define SXX   2048
#define SYY   2048
#define DD    160
#define BM    128
#define BN    32
#define NT    (SYY / BN)
#define ROWB  336          // padded row pitch in bytes (168 bf16)

// hi/lo bf16 splits of inputs and projections (natural [b][m][d] layout)
__device__ __nv_bfloat16 g_xhi[(size_t)B_ * SXX * DD];
__device__ __nv_bfloat16 g_xlo[(size_t)B_ * SXX * DD];
__device__ __nv_bfloat16 g_yhi[(size_t)B_ * SYY * DD];
__device__ __nv_bfloat16 g_ylo[(size_t)B_ * SYY * DD];
__device__ __nv_bfloat16 g_wqhi[DD * DD];
__device__ __nv_bfloat16 g_wqlo[DD * DD];
__device__ __nv_bfloat16 g_wkhi[DD * DD];
__device__ __nv_bfloat16 g_wklo[DD * DD];
__device__ __nv_bfloat16 g_wvhi[DD * DD];
__device__ __nv_bfloat16 g_wvlo[DD * DD];
__device__ __nv_bfloat16 g_qhi[(size_t)B_ * SXX * DD];
__device__ __nv_bfloat16 g_qlo[(size_t)B_ * SXX * DD];
__device__ __nv_bfloat16 g_khi[(size_t)B_ * SYY * DD];
__device__ __nv_bfloat16 g_klo[(size_t)B_ * SYY * DD];
__device__ __nv_bfloat16 g_vhi[(size_t)B_ * SYY * DD];
__device__ __nv_bfloat16 g_vlo[(size_t)B_ * SYY * DD];

// ---------------------------------------------------------------------------
// low-level helpers (base-target sm_80+ instructions only)
// ---------------------------------------------------------------------------
__device__ __forceinline__ uint32_t smem_u32(const void* p) {
    uint32_t r;
    asm("{ .reg .u64 t; cvta.to.shared.u64 t, %1; cvt.u32.u64 %0, t; }"
        : "=r"(r) : "l"(p));
    return r;
}
__device__ __forceinline__ void cp16(uint32_t s, const void* g) {
    asm volatile("cp.async.cg.shared.global [%0], [%1], 16;" :: "r"(s), "l"(g));
}
__device__ __forceinline__ void cp_commit() {
    asm volatile("cp.async.commit_group;" ::: "memory");
}
__device__ __forceinline__ void cp_wait_all() {
    asm volatile("cp.async.wait_group 0;" ::: "memory");
}
__device__ __forceinline__ void ldsm4(uint32_t* r, uint32_t a) {
    asm volatile("ldmatrix.sync.aligned.m8n8.x4.shared.b16 {%0,%1,%2,%3}, [%4];"
                 : "=r"(r[0]), "=r"(r[1]), "=r"(r[2]), "=r"(r[3]) : "r"(a));
}
__device__ __forceinline__ void ldsm4t(uint32_t* r, uint32_t a) {
    asm volatile("ldmatrix.sync.aligned.m8n8.x4.trans.shared.b16 {%0,%1,%2,%3}, [%4];"
                 : "=r"(r[0]), "=r"(r[1]), "=r"(r[2]), "=r"(r[3]) : "r"(a));
}
__device__ __forceinline__ void mma_bf16(float* c, const uint32_t* a,
                                         uint32_t b0, uint32_t b1) {
    asm volatile("mma.sync.aligned.m16n8k16.row.col.f32.bf16.bf16.f32 "
                 "{%0,%1,%2,%3}, {%4,%5,%6,%7}, {%8,%9}, {%0,%1,%2,%3};"
                 : "+f"(c[0]), "+f"(c[1]), "+f"(c[2]), "+f"(c[3])
                 : "r"(a[0]), "r"(a[1]), "r"(a[2]), "r"(a[3]), "r"(b0), "r"(b1));
}
__device__ __forceinline__ uint32_t packbf(float a, float b) {
    __nv_bfloat162 t = __floats2bfloat162_rn(a, b);
    return *reinterpret_cast<uint32_t*>(&t);
}

// ---------------------------------------------------------------------------
// fp32 -> (hi, lo) bf16 elementwise split (vectorized)
// ---------------------------------------------------------------------------
__global__ __launch_bounds__(256) void split_kernel(
    const float* __restrict__ src,
    __nv_bfloat16* __restrict__ hi, __nv_bfloat16* __restrict__ lo, int n4)
{
    int i = blockIdx.x * blockDim.x + threadIdx.x;
    if (i >= n4) return;
    float4 v = ((const float4*)src)[i];
    __nv_bfloat16 h0 = __float2bfloat16_rn(v.x);
    __nv_bfloat16 h1 = __float2bfloat16_rn(v.y);
    __nv_bfloat16 h2 = __float2bfloat16_rn(v.z);
    __nv_bfloat16 h3 = __float2bfloat16_rn(v.w);
    uint2 hp, lp;
    hp.x = ((uint32_t)__bfloat16_as_ushort(h1) << 16) | __bfloat16_as_ushort(h0);
    hp.y = ((uint32_t)__bfloat16_as_ushort(h3) << 16) | __bfloat16_as_ushort(h2);
    lp.x = packbf(v.x - __bfloat162float(h0), v.y - __bfloat162float(h1));
    lp.y = packbf(v.z - __bfloat162float(h2), v.w - __bfloat162float(h3));
    ((uint2*)hi)[i] = hp;
    ((uint2*)lo)[i] = lp;
}

// ---------------------------------------------------------------------------
// Tensor-core projection: C[m,n] = sum_d A[m,d] * W[n,d] + bias[n]
// 3-term bf16 hi/lo HMMA. BM=128, BN=160(all), k=160. 256 threads.
// SMEM: Ahi @0, Alo @43008, Whi @86016, Wlo @139776 -> total 193536 B
// ---------------------------------------------------------------------------
#define PSAH 0
#define PSAL 43008
#define PSWH 86016
#define PSWL 139776
#define PROJ_SMEM 193536

__global__ __launch_bounds__(256, 1) void proj_mma(
    const __nv_bfloat16* __restrict__ Ahi, const __nv_bfloat16* __restrict__ Alo,
    const __nv_bfloat16* __restrict__ Whi, const __nv_bfloat16* __restrict__ Wlo,
    const float* __restrict__ bias,
    __nv_bfloat16* __restrict__ Chi, __nv_bfloat16* __restrict__ Clo)
{
    extern __shared__ char smem[];
    const uint32_t sb = smem_u32(smem);
    const int tid  = threadIdx.x;
    const int lane = tid & 31;
    const int w    = tid >> 5;
    const size_t m0 = (size_t)blockIdx.x * BM;

    // load A tile hi/lo (128 x 160)
#pragma unroll
    for (int i = 0; i < 20; i++) {
        int idx  = i * 256 + tid;               // < 5120
        int half = idx / 2560;
        int rem  = idx - half * 2560;
        int row  = rem / 20, cc = rem - row * 20;
        cp16(sb + (half ? PSAL : PSAH) + row * ROWB + cc * 16,
             (half ? Alo : Ahi) + (m0 + row) * DD + cc * 8);
    }
    // load W tile hi/lo (160 x 160)
    for (int idx = tid; idx < 6400; idx += 256) {
        int half = idx / 3200;
        int rem  = idx - half * 3200;
        int row  = rem / 20, cc = rem - row * 20;
        cp16(sb + (half ? PSWL : PSWH) + row * ROWB + cc * 16,
             (half ? Wlo : Whi) + (size_t)row * DD + cc * 8);
    }
    cp_commit();
    cp_wait_all();
    __syncthreads();

    const uint32_t aOff = (uint32_t)((16 * w + (lane & 15)) * ROWB
                                     + ((lane >> 4) << 4));
    const uint32_t bOff = (uint32_t)(((lane & 7) + ((lane >> 4) << 3)) * ROWB
                                     + (((lane >> 3) & 1) << 4));

    float c[20][4];
#pragma unroll
    for (int j = 0; j < 20; j++)
#pragma unroll
        for (int u = 0; u < 4; u++) c[j][u] = 0.f;

#pragma unroll
    for (int ks = 0; ks < 10; ks++) {
        uint32_t ah[4], al[4];
        ldsm4(ah, sb + PSAH + aOff + ks * 32);
        ldsm4(al, sb + PSAL + aOff + ks * 32);
#pragma unroll
        for (int nb = 0; nb < 10; nb++) {
            uint32_t bh[4], bl[4];
            ldsm4(bh, sb + PSWH + bOff + nb * (16 * ROWB) + ks * 32);
            ldsm4(bl, sb + PSWL + bOff + nb * (16 * ROWB) + ks * 32);
            mma_bf16(c[2 * nb],     ah, bh[0], bh[1]);
            mma_bf16(c[2 * nb + 1], ah, bh[2], bh[3]);
            mma_bf16(c[2 * nb],     ah, bl[0], bl[1]);
            mma_bf16(c[2 * nb + 1], ah, bl[2], bl[3]);
            mma_bf16(c[2 * nb],     al, bh[0], bh[1]);
            mma_bf16(c[2 * nb + 1], al, bh[2], bh[3]);
        }
    }

    // epilogue: bias add, hi/lo split, packed u32 stores
    const size_t r0 = m0 + 16 * w + (lane >> 2);
    const int cb = 2 * (lane & 3);
#pragma unroll
    for (int j = 0; j < 20; j++) {
        int n = 8 * j + cb;
        float2 bv = *(const float2*)(bias + n);
        float v0 = c[j][0] + bv.x, v1 = c[j][1] + bv.y;   // row r0
        float v2 = c[j][2] + bv.x, v3 = c[j][3] + bv.y;   // row r0+8
        __nv_bfloat16 h0 = __float2bfloat16_rn(v0);
        __nv_bfloat16 h1 = __float2bfloat16_rn(v1);
        __nv_bfloat16 h2 = __float2bfloat16_rn(v2);
        __nv_bfloat16 h3 = __float2bfloat16_rn(v3);
        *(uint32_t*)(Chi + r0 * DD + n) =
            ((uint32_t)__bfloat16_as_ushort(h1) << 16) | __bfloat16_as_ushort(h0);
        *(uint32_t*)(Chi + (r0 + 8) * DD + n) =
            ((uint32_t)__bfloat16_as_ushort(h3) << 16) | __bfloat16_as_ushort(h2);
        *(uint32_t*)(Clo + r0 * DD + n) =
            packbf(v0 - __bfloat162float(h0), v1 - __bfloat162float(h1));
        *(uint32_t*)(Clo + (r0 + 8) * DD + n) =
            packbf(v2 - __bfloat162float(h2), v3 - __bfloat162float(h3));
    }
}

// ---------------------------------------------------------------------------
// HMMA flash attention, deferred-PV pipelined, triple-buffered K/V.
// SMEM: Qh @0, Ql @43008, buf{0,1,2} @86016/@129024/@172032
//   each buf: Kh +0, Kl +10752, Vh +21504, Vl +32256 (43008 B)
// ---------------------------------------------------------------------------
#define SQH   0
#define SQL   43008
#define MKH   0
#define MKL   10752
#define MVH   21504
#define MVL   32256
#define SMEM_TOTAL 215040

__global__ __launch_bounds__(256, 1) void attn_kernel(
    const __nv_bfloat16* __restrict__ qhi, const __nv_bfloat16* __restrict__ qlo,
    const __nv_bfloat16* __restrict__ khi, const __nv_bfloat16* __restrict__ klo,
    const __nv_bfloat16* __restrict__ vhi, const __nv_bfloat16* __restrict__ vlo,
    const float* __restrict__ gx, float* __restrict__ gout)
{
    extern __shared__ char smem[];
    const uint32_t sb = smem_u32(smem);
    const int tid  = threadIdx.x;
    const int lane = tid & 31;
    const int w    = tid >> 5;
    const int b    = blockIdx.y;
    const int m0   = blockIdx.x * BM;
    const uint32_t bufoff[3] = { 86016u, 129024u, 172032u };

    // ---- load Q (hi/lo) into SMEM ----
    {
        const size_t qrow = ((size_t)b * SXX + m0);
#pragma unroll
        for (int i = 0; i < 20; i++) {
            int idx  = i * 256 + tid;
            int half = idx / 2560;
            int rem  = idx - half * 2560;
            int row  = rem / 20, cc = rem - row * 20;
            cp16(sb + (half ? SQL : SQH) + row * ROWB + cc * 16,
                 (half ? qlo : qhi) + (qrow + row) * DD + cc * 8);
        }
    }

    const __nv_bfloat16* gsrc[4] = {
        khi + (size_t)b * SYY * DD, klo + (size_t)b * SYY * DD,
        vhi + (size_t)b * SYY * DD, vlo + (size_t)b * SYY * DD };
    const int moff[4] = { MKH, MKL, MVH, MVL };

    // ---- tile 0 ----
#pragma unroll
    for (int i = 0; i < 10; i++) {
        int idx = i * 256 + tid;
        int mat = idx / 640;
        int rem = idx - mat * 640;
        int row = rem / 20, cc = rem - row * 20;
        cp16(sb + bufoff[0] + moff[mat] + row * ROWB + cc * 16,
             gsrc[mat] + (size_t)row * DD + cc * 8);
    }
    cp_commit();
    cp_wait_all();
    __syncthreads();

    const uint32_t qOff = (uint32_t)((16 * w + (lane & 15)) * ROWB
                                     + ((lane >> 4) << 4));
    const uint32_t kOff = (uint32_t)(((lane & 7) + ((lane >> 4) << 3)) * ROWB
                                     + (((lane >> 3) & 1) << 4));
    const uint32_t vOff = (uint32_t)(((lane & 7) + (((lane >> 3) & 1) << 3)) * ROWB
                                     + ((lane >> 4) << 4));

    float o[20][4];
#pragma unroll
    for (int j = 0; j < 20; j++)
#pragma unroll
        for (int u = 0; u < 4; u++) o[j][u] = 0.f;

    float mh01 = 0.f, mh23 = 0.f, ls01 = 0.f, ls23 = 0.f;
    uint32_t pah[2][4], pal[2][4];

    for (int t = 0; t < NT; t++) {
        const uint32_t buf  = sb + bufoff[t % 3];
        const uint32_t pbuf = sb + bufoff[(t + 2) % 3];   // (t-1) % 3

        // prefetch tile t+1
        if (t + 1 < NT) {
            const uint32_t nbuf = sb + bufoff[(t + 1) % 3];
            const size_t grow = (size_t)(t + 1) * BN;
#pragma unroll
            for (int i = 0; i < 10; i++) {
                int idx = i * 256 + tid;
                int mat = idx / 640;
                int rem = idx - mat * 640;
                int row = rem / 20, cc = rem - row * 20;
                cp16(nbuf + moff[mat] + row * ROWB + cc * 16,
                     gsrc[mat] + (grow + row) * DD + cc * 8);
            }
            cp_commit();
        }

        // ---- S(t) = Q K^T ----
        float c[4][4];
#pragma unroll
        for (int j = 0; j < 4; j++)
#pragma unroll
            for (int u = 0; u < 4; u++) c[j][u] = 0.f;

#pragma unroll
        for (int ks = 0; ks < 10; ks++) {
            uint32_t ah[4], al[4], bh[8], bl[8];
            ldsm4(ah, sb + SQH + qOff + ks * 32);
            ldsm4(al, sb + SQL + qOff + ks * 32);
            ldsm4(bh,     buf + MKH + kOff + ks * 32);
            ldsm4(bh + 4, buf + MKH + kOff + 16 * ROWB + ks * 32);
            ldsm4(bl,     buf + MKL + kOff + ks * 32);
            ldsm4(bl + 4, buf + MKL + kOff + 16 * ROWB + ks * 32);
#pragma unroll
            for (int j = 0; j < 4; j++) {
                mma_bf16(c[j], ah, bh[2 * j], bh[2 * j + 1]);
                mma_bf16(c[j], ah, bl[2 * j], bl[2 * j + 1]);
                mma_bf16(c[j], al, bh[2 * j], bh[2 * j + 1]);
            }
        }

        // ---- PV(t-1): fills tensor pipe during S drain + softmax below ----
        if (t > 0) {
#pragma unroll
            for (int ks = 0; ks < 2; ks++) {
#pragma unroll
                for (int jp = 0; jp < 10; jp++) {
                    uint32_t v4h[4], v4l[4];
                    ldsm4t(v4h, pbuf + MVH + vOff + ks * (16 * ROWB) + jp * 32);
                    ldsm4t(v4l, pbuf + MVL + vOff + ks * (16 * ROWB) + jp * 32);
                    mma_bf16(o[2 * jp],     pah[ks], v4h[0], v4h[1]);
                    mma_bf16(o[2 * jp + 1], pah[ks], v4h[2], v4h[3]);
                    mma_bf16(o[2 * jp],     pah[ks], v4l[0], v4l[1]);
                    mma_bf16(o[2 * jp + 1], pah[ks], v4l[2], v4l[3]);
                    mma_bf16(o[2 * jp],     pal[ks], v4h[0], v4h[1]);
                    mma_bf16(o[2 * jp + 1], pal[ks], v4h[2], v4h[3]);
                }
            }
        }

        // ---- softmax(t) (fixed mhat from tile 0) -> P(t) a-frags ----
        if (t == 0) {
            float m01 = c[0][0], m23 = c[0][2];
#pragma unroll
            for (int j = 0; j < 4; j++) {
                m01 = fmaxf(m01, fmaxf(c[j][0], c[j][1]));
                m23 = fmaxf(m23, fmaxf(c[j][2], c[j][3]));
            }
            m01 = fmaxf(m01, __shfl_xor_sync(0xffffffffu, m01, 1));
            m01 = fmaxf(m01, __shfl_xor_sync(0xffffffffu, m01, 2));
            m23 = fmaxf(m23, __shfl_xor_sync(0xffffffffu, m23, 1));
            m23 = fmaxf(m23, __shfl_xor_sync(0xffffffffu, m23, 2));
            mh01 = m01; mh23 = m23;
        }

#pragma unroll
        for (int j = 0; j < 4; j++) {
            float p0 = __expf(c[j][0] - mh01);
            float p1 = __expf(c[j][1] - mh01);
            float p2 = __expf(c[j][2] - mh23);
            float p3 = __expf(c[j][3] - mh23);
            ls01 += p0 + p1; ls23 += p2 + p3;
            __nv_bfloat16 h0 = __float2bfloat16_rn(p0);
            __nv_bfloat16 h1 = __float2bfloat16_rn(p1);
            __nv_bfloat16 h2 = __float2bfloat16_rn(p2);
            __nv_bfloat16 h3 = __float2bfloat16_rn(p3);
            int ks = j >> 1, sl = (j & 1) << 1;
            pah[ks][sl]     = ((uint32_t)__bfloat16_as_ushort(h1) << 16)
                            |  (uint32_t)__bfloat16_as_ushort(h0);
            pah[ks][sl + 1] = ((uint32_t)__bfloat16_as_ushort(h3) << 16)
                            |  (uint32_t)__bfloat16_as_ushort(h2);
            pal[ks][sl]     = packbf(p0 - __bfloat162float(h0),
                                     p1 - __bfloat162float(h1));
            pal[ks][sl + 1] = packbf(p2 - __bfloat162float(h2),
                                     p3 - __bfloat162float(h3));
        }

        cp_wait_all();
        __syncthreads();
    }

    // ---- final PV (tile NT-1) ----
    {
        const uint32_t pbuf = sb + bufoff[(NT - 1) % 3];
#pragma unroll
        for (int ks = 0; ks < 2; ks++) {
#pragma unroll
            for (int jp = 0; jp < 10; jp++) {
                uint32_t v4h[4], v4l[4];
                ldsm4t(v4h, pbuf + MVH + vOff + ks * (16 * ROWB) + jp * 32);
                ldsm4t(v4l, pbuf + MVL + vOff + ks * (16 * ROWB) + jp * 32);
                mma_bf16(o[2 * jp],     pah[ks], v4h[0], v4h[1]);
                mma_bf16(o[2 * jp + 1], pah[ks], v4h[2], v4h[3]);
                mma_bf16(o[2 * jp],     pah[ks], v4l[0], v4l[1]);
                mma_bf16(o[2 * jp + 1], pah[ks], v4l[2], v4l[3]);
                mma_bf16(o[2 * jp],     pal[ks], v4h[0], v4h[1]);
                mma_bf16(o[2 * jp + 1], pal[ks], v4h[2], v4h[3]);
            }
        }
    }

    // ---- epilogue: normalize, residual, store ----
    ls01 += __shfl_xor_sync(0xffffffffu, ls01, 1);
    ls01 += __shfl_xor_sync(0xffffffffu, ls01, 2);
    ls23 += __shfl_xor_sync(0xffffffffu, ls23, 1);
    ls23 += __shfl_xor_sync(0xffffffffu, ls23, 2);
    const float inv01 = 1.f / ls01;
    const float inv23 = 1.f / ls23;

    const int r0 = m0 + 16 * w + (lane >> 2);
    const size_t row0 = ((size_t)b * SXX + r0) * DD;
    const size_t row1 = row0 + 8 * DD;
    const int cb = 2 * (lane & 3);
#pragma unroll
    for (int j = 0; j < 20; j++) {
        int cc = 8 * j + cb;
        float2 x0 = *(const float2*)(gx + row0 + cc);
        float2 x1 = *(const float2*)(gx + row1 + cc);
        float2 r0v, r1v;
        r0v.x = o[j][0] * inv01 + x0.x;
        r0v.y = o[j][1] * inv01 + x0.y;
        r1v.x = o[j][2] * inv23 + x1.x;
        r1v.y = o[j][3] * inv23 + x1.y;
        *(float2*)(gout + row0 + cc) = r0v;
        *(float2*)(gout + row1 + cc) = r1v;
    }
}

// ---------------------------------------------------------------------------
extern "C" void kernel_launch(void* const* d_in, const int* in_sizes, int n_in,
                              void* d_out, int out_size)
{
    const float* x  = (const float*)d_in[0];
    const float* y  = (const float*)d_in[1];
    const float* Wq = (const float*)d_in[2];
    const float* bq = (const float*)d_in[3];
    const float* Wk = (const float*)d_in[4];
    const float* bk = (const float*)d_in[5];
    const float* Wv = (const float*)d_in[6];
    const float* bv = (const float*)d_in[7];
    float* out = (float*)d_out;

    __nv_bfloat16 *xh, *xl, *yh, *yl;
    __nv_bfloat16 *wqh, *wql, *wkh, *wkl, *wvh, *wvl;
    __nv_bfloat16 *qh, *ql, *kh, *kl, *vh, *vl;
    cudaGetSymbolAddress((void**)&xh, g_xhi);  cudaGetSymbolAddress((void**)&xl, g_xlo);
    cudaGetSymbolAddress((void**)&yh, g_yhi);  cudaGetSymbolAddress((void**)&yl, g_ylo);
    cudaGetSymbolAddress((void**)&wqh, g_wqhi); cudaGetSymbolAddress((void**)&wql, g_wqlo);
    cudaGetSymbolAddress((void**)&wkh, g_wkhi); cudaGetSymbolAddress((void**)&wkl, g_wklo);
    cudaGetSymbolAddress((void**)&wvh, g_wvhi); cudaGetSymbolAddress((void**)&wvl, g_wvlo);
    cudaGetSymbolAddress((void**)&qh, g_qhi);  cudaGetSymbolAddress((void**)&ql, g_qlo);
    cudaGetSymbolAddress((void**)&kh, g_khi);  cudaGetSymbolAddress((void**)&kl, g_klo);
    cudaGetSymbolAddress((void**)&vh, g_vhi);  cudaGetSymbolAddress((void**)&vl, g_vlo);

    const int nxy4 = (B_ * SXX * DD) / 4;
    const int nw4  = (DD * DD) / 4;
    split_kernel<<<(nxy4 + 255) / 256, 256>>>(x,  xh,  xl,  nxy4);
    split_kernel<<<(nxy4 + 255) / 256, 256>>>(y,  yh,  yl,  nxy4);
    split_kernel<<<(nw4  + 255) / 256, 256>>>(Wq, wqh, wql, nw4);
    split_kernel<<<(nw4  + 255) / 256, 256>>>(Wk, wkh, wkl, nw4);
    split_kernel<<<(nw4  + 255) / 256, 256>>>(Wv, wvh, wvl, nw4);

    cudaFuncSetAttribute(proj_mma,
                         cudaFuncAttributeMaxDynamicSharedMemorySize, PROJ_SMEM);
    const int pgrid = (B_ * SXX) / BM;   // 512
    proj_mma<<<pgrid, 256, PROJ_SMEM>>>(xh, xl, wqh, wql, bq, qh, ql);
    proj_mma<<<pgrid, 256, PROJ_SMEM>>>(yh, yl, wkh, wkl, bk, kh, kl);
    proj_mma<<<pgrid, 256, PROJ_SMEM>>>(yh, yl, wvh, wvl, bv, vh, vl);

    cudaFuncSetAttribute(attn_kernel,
                         cudaFuncAttributeMaxDynamicSharedMemorySize, SMEM_TOTAL);
    dim3 grid(SXX / BM, B_);
    attn_kernel<<<grid, 256, SMEM_TOTAL>>>(qh, ql, kh, kl, vh, vl, x, out);
}

// round 6
// speedup vs baseline: 3.4454x; 1.0768x over previous
#include <cuda_runtime.h>
#include <cuda_fp16.h>
#include <math.h>
#include <stdint.h>

#define B_    32
#define SXX   2048
#define SYY   2048
#define DD    160
#define BM    128
#define BN    32
#define NT    (SYY / BN)
#define ROWB  336          // padded row pitch in bytes (168 f16)

// hi/lo f16 splits of inputs and projections (natural [b][m][d] layout)
__device__ __half g_xhi[(size_t)B_ * SXX * DD];
__device__ __half g_xlo[(size_t)B_ * SXX * DD];
__device__ __half g_yhi[(size_t)B_ * SYY * DD];
__device__ __half g_ylo[(size_t)B_ * SYY * DD];
__device__ __half g_wqhi[DD * DD];
__device__ __half g_wqlo[DD * DD];
__device__ __half g_wkhi[DD * DD];
__device__ __half g_wklo[DD * DD];
__device__ __half g_wvhi[DD * DD];
__device__ __half g_wvlo[DD * DD];
__device__ __half g_qhi[(size_t)B_ * SXX * DD];
__device__ __half g_qlo[(size_t)B_ * SXX * DD];
__device__ __half g_khi[(size_t)B_ * SYY * DD];
__device__ __half g_klo[(size_t)B_ * SYY * DD];
__device__ __half g_vhi[(size_t)B_ * SYY * DD];
__device__ __half g_vlo[(size_t)B_ * SYY * DD];

// ---------------------------------------------------------------------------
// low-level helpers (base-target sm_80+ instructions only)
// ---------------------------------------------------------------------------
__device__ __forceinline__ uint32_t smem_u32(const void* p) {
    uint32_t r;
    asm("{ .reg .u64 t; cvta.to.shared.u64 t, %1; cvt.u32.u64 %0, t; }"
        : "=r"(r) : "l"(p));
    return r;
}
__device__ __forceinline__ void cp16(uint32_t s, const void* g) {
    asm volatile("cp.async.cg.shared.global [%0], [%1], 16;" :: "r"(s), "l"(g));
}
__device__ __forceinline__ void cp_commit() {
    asm volatile("cp.async.commit_group;" ::: "memory");
}
__device__ __forceinline__ void cp_wait_all() {
    asm volatile("cp.async.wait_group 0;" ::: "memory");
}
__device__ __forceinline__ void ldsm4(uint32_t* r, uint32_t a) {
    asm volatile("ldmatrix.sync.aligned.m8n8.x4.shared.b16 {%0,%1,%2,%3}, [%4];"
                 : "=r"(r[0]), "=r"(r[1]), "=r"(r[2]), "=r"(r[3]) : "r"(a));
}
__device__ __forceinline__ void ldsm4t(uint32_t* r, uint32_t a) {
    asm volatile("ldmatrix.sync.aligned.m8n8.x4.trans.shared.b16 {%0,%1,%2,%3}, [%4];"
                 : "=r"(r[0]), "=r"(r[1]), "=r"(r[2]), "=r"(r[3]) : "r"(a));
}
__device__ __forceinline__ void mma_f16(float* c, const uint32_t* a,
                                        uint32_t b0, uint32_t b1) {
    asm volatile("mma.sync.aligned.m16n8k16.row.col.f32.f16.f16.f32 "
                 "{%0,%1,%2,%3}, {%4,%5,%6,%7}, {%8,%9}, {%0,%1,%2,%3};"
                 : "+f"(c[0]), "+f"(c[1]), "+f"(c[2]), "+f"(c[3])
                 : "r"(a[0]), "r"(a[1]), "r"(a[2]), "r"(a[3]), "r"(b0), "r"(b1));
}
__device__ __forceinline__ float ex2f(float x) {
    float r;
    asm("ex2.approx.ftz.f32 %0, %1;" : "=f"(r) : "f"(x));
    return r;
}
__device__ __forceinline__ uint32_t packh(float a, float b) {
    __half2 t = __floats2half2_rn(a, b);
    return *reinterpret_cast<uint32_t*>(&t);
}

// ---------------------------------------------------------------------------
// fp32 -> (hi, lo) f16 split, all five tensors in ONE launch
// blocks: [0,10240) x | [10240,20480) y | 25 each for Wq, Wk, Wv
// ---------------------------------------------------------------------------
__global__ __launch_bounds__(256) void split_all(
    const float* __restrict__ x, const float* __restrict__ y,
    const float* __restrict__ wq, const float* __restrict__ wk,
    const float* __restrict__ wv,
    __half* __restrict__ xh, __half* __restrict__ xl,
    __half* __restrict__ yh, __half* __restrict__ yl,
    __half* __restrict__ wqh, __half* __restrict__ wql,
    __half* __restrict__ wkh, __half* __restrict__ wkl,
    __half* __restrict__ wvh, __half* __restrict__ wvl)
{
    int bid = blockIdx.x;
    const float* src; __half *hi, *lo; int base;
    if (bid < 10240)      { src = x;  hi = xh;  lo = xl;  base = 0; }
    else if (bid < 20480) { src = y;  hi = yh;  lo = yl;  base = 10240; }
    else if (bid < 20505) { src = wq; hi = wqh; lo = wql; base = 20480; }
    else if (bid < 20530) { src = wk; hi = wkh; lo = wkl; base = 20505; }
    else                  { src = wv; hi = wvh; lo = wvl; base = 20530; }
    int i = (bid - base) * 256 + threadIdx.x;
    float4 v = ((const float4*)src)[i];
    __half h0 = __float2half_rn(v.x);
    __half h1 = __float2half_rn(v.y);
    __half h2 = __float2half_rn(v.z);
    __half h3 = __float2half_rn(v.w);
    uint2 hp, lp;
    hp.x = ((uint32_t)__half_as_ushort(h1) << 16) | __half_as_ushort(h0);
    hp.y = ((uint32_t)__half_as_ushort(h3) << 16) | __half_as_ushort(h2);
    lp.x = packh(v.x - __half2float(h0), v.y - __half2float(h1));
    lp.y = packh(v.z - __half2float(h2), v.w - __half2float(h3));
    ((uint2*)hi)[i] = hp;
    ((uint2*)lo)[i] = lp;
}

// ---------------------------------------------------------------------------
// Tensor-core projection: C[m,n] = (sum_d A[m,d]*W[n,d] + bias[n]) * ascale
// 3-term f16 hi/lo HMMA. BM=128, BN=160(all), k=160. 256 threads.
// ---------------------------------------------------------------------------
#define PSAH 0
#define PSAL 43008
#define PSWH 86016
#define PSWL 139776
#define PROJ_SMEM 193536

__global__ __launch_bounds__(256, 1) void proj_mma(
    const __half* __restrict__ Ahi, const __half* __restrict__ Alo,
    const __half* __restrict__ Whi, const __half* __restrict__ Wlo,
    const float* __restrict__ bias, float ascale,
    __half* __restrict__ Chi, __half* __restrict__ Clo)
{
    extern __shared__ char smem[];
    const uint32_t sb = smem_u32(smem);
    const int tid  = threadIdx.x;
    const int lane = tid & 31;
    const int w    = tid >> 5;
    const size_t m0 = (size_t)blockIdx.x * BM;

#pragma unroll
    for (int i = 0; i < 20; i++) {
        int idx  = i * 256 + tid;
        int half = idx / 2560;
        int rem  = idx - half * 2560;
        int row  = rem / 20, cc = rem - row * 20;
        cp16(sb + (half ? PSAL : PSAH) + row * ROWB + cc * 16,
             (half ? Alo : Ahi) + (m0 + row) * DD + cc * 8);
    }
    for (int idx = tid; idx < 6400; idx += 256) {
        int half = idx / 3200;
        int rem  = idx - half * 3200;
        int row  = rem / 20, cc = rem - row * 20;
        cp16(sb + (half ? PSWL : PSWH) + row * ROWB + cc * 16,
             (half ? Wlo : Whi) + (size_t)row * DD + cc * 8);
    }
    cp_commit();
    cp_wait_all();
    __syncthreads();

    const uint32_t aOff = (uint32_t)((16 * w + (lane & 15)) * ROWB
                                     + ((lane >> 4) << 4));
    const uint32_t bOff = (uint32_t)(((lane & 7) + ((lane >> 4) << 3)) * ROWB
                                     + (((lane >> 3) & 1) << 4));

    float c[20][4];
#pragma unroll
    for (int j = 0; j < 20; j++)
#pragma unroll
        for (int u = 0; u < 4; u++) c[j][u] = 0.f;

#pragma unroll
    for (int ks = 0; ks < 10; ks++) {
        uint32_t ah[4], al[4];
        ldsm4(ah, sb + PSAH + aOff + ks * 32);
        ldsm4(al, sb + PSAL + aOff + ks * 32);
#pragma unroll
        for (int nb = 0; nb < 10; nb++) {
            uint32_t bh[4], bl[4];
            ldsm4(bh, sb + PSWH + bOff + nb * (16 * ROWB) + ks * 32);
            ldsm4(bl, sb + PSWL + bOff + nb * (16 * ROWB) + ks * 32);
            mma_f16(c[2 * nb],     ah, bh[0], bh[1]);
            mma_f16(c[2 * nb + 1], ah, bh[2], bh[3]);
            mma_f16(c[2 * nb],     ah, bl[0], bl[1]);
            mma_f16(c[2 * nb + 1], ah, bl[2], bl[3]);
            mma_f16(c[2 * nb],     al, bh[0], bh[1]);
            mma_f16(c[2 * nb + 1], al, bh[2], bh[3]);
        }
    }

    const size_t r0 = m0 + 16 * w + (lane >> 2);
    const int cb = 2 * (lane & 3);
#pragma unroll
    for (int j = 0; j < 20; j++) {
        int n = 8 * j + cb;
        float2 bv = *(const float2*)(bias + n);
        float v0 = (c[j][0] + bv.x) * ascale, v1 = (c[j][1] + bv.y) * ascale;
        float v2 = (c[j][2] + bv.x) * ascale, v3 = (c[j][3] + bv.y) * ascale;
        __half h0 = __float2half_rn(v0);
        __half h1 = __float2half_rn(v1);
        __half h2 = __float2half_rn(v2);
        __half h3 = __float2half_rn(v3);
        *(uint32_t*)(Chi + r0 * DD + n) =
            ((uint32_t)__half_as_ushort(h1) << 16) | __half_as_ushort(h0);
        *(uint32_t*)(Chi + (r0 + 8) * DD + n) =
            ((uint32_t)__half_as_ushort(h3) << 16) | __half_as_ushort(h2);
        *(uint32_t*)(Clo + r0 * DD + n) =
            packh(v0 - __half2float(h0), v1 - __half2float(h1));
        *(uint32_t*)(Clo + (r0 + 8) * DD + n) =
            packh(v2 - __half2float(h2), v3 - __half2float(h3));
    }
}

// ---------------------------------------------------------------------------
// f16 HMMA flash attention: online max, S 3-term, PV 2-term, deferred PV,
// triple-buffered K/V. Q pre-scaled by log2e (exp == ex2).
// ---------------------------------------------------------------------------
#define SQH   0
#define SQL   43008
#define MKH   0
#define MKL   10752
#define MVH   21504
#define MVL   32256
#define SMEM_TOTAL 215040

__global__ __launch_bounds__(256, 1) void attn_kernel(
    const __half* __restrict__ qhi, const __half* __restrict__ qlo,
    const __half* __restrict__ khi, const __half* __restrict__ klo,
    const __half* __restrict__ vhi, const __half* __restrict__ vlo,
    const float* __restrict__ gx, float* __restrict__ gout)
{
    extern __shared__ char smem[];
    const uint32_t sb = smem_u32(smem);
    const int tid  = threadIdx.x;
    const int lane = tid & 31;
    const int w    = tid >> 5;
    const int b    = blockIdx.y;
    const int m0   = blockIdx.x * BM;
    const uint32_t bufoff[3] = { 86016u, 129024u, 172032u };

    {
        const size_t qrow = ((size_t)b * SXX + m0);
#pragma unroll
        for (int i = 0; i < 20; i++) {
            int idx  = i * 256 + tid;
            int half = idx / 2560;
            int rem  = idx - half * 2560;
            int row  = rem / 20, cc = rem - row * 20;
            cp16(sb + (half ? SQL : SQH) + row * ROWB + cc * 16,
                 (half ? qlo : qhi) + (qrow + row) * DD + cc * 8);
        }
    }

    const __half* gsrc[4] = {
        khi + (size_t)b * SYY * DD, klo + (size_t)b * SYY * DD,
        vhi + (size_t)b * SYY * DD, vlo + (size_t)b * SYY * DD };
    const int moff[4] = { MKH, MKL, MVH, MVL };

#pragma unroll
    for (int i = 0; i < 10; i++) {
        int idx = i * 256 + tid;
        int mat = idx / 640;
        int rem = idx - mat * 640;
        int row = rem / 20, cc = rem - row * 20;
        cp16(sb + bufoff[0] + moff[mat] + row * ROWB + cc * 16,
             gsrc[mat] + (size_t)row * DD + cc * 8);
    }
    cp_commit();
    cp_wait_all();
    __syncthreads();

    const uint32_t qOff = (uint32_t)((16 * w + (lane & 15)) * ROWB
                                     + ((lane >> 4) << 4));
    const uint32_t kOff = (uint32_t)(((lane & 7) + ((lane >> 4) << 3)) * ROWB
                                     + (((lane >> 3) & 1) << 4));
    const uint32_t vOff = (uint32_t)(((lane & 7) + (((lane >> 3) & 1) << 3)) * ROWB
                                     + ((lane >> 4) << 4));

    float o[20][4];
#pragma unroll
    for (int j = 0; j < 20; j++)
#pragma unroll
        for (int u = 0; u < 4; u++) o[j][u] = 0.f;

    float mh01 = -INFINITY, mh23 = -INFINITY, ls01 = 0.f, ls23 = 0.f;
    uint32_t pah[2][4];

    for (int t = 0; t < NT; t++) {
        const uint32_t buf  = sb + bufoff[t % 3];
        const uint32_t pbuf = sb + bufoff[(t + 2) % 3];

        if (t + 1 < NT) {
            const uint32_t nbuf = sb + bufoff[(t + 1) % 3];
            const size_t grow = (size_t)(t + 1) * BN;
#pragma unroll
            for (int i = 0; i < 10; i++) {
                int idx = i * 256 + tid;
                int mat = idx / 640;
                int rem = idx - mat * 640;
                int row = rem / 20, cc = rem - row * 20;
                cp16(nbuf + moff[mat] + row * ROWB + cc * 16,
                     gsrc[mat] + (grow + row) * DD + cc * 8);
            }
            cp_commit();
        }

        // ---- S(t) = Q K^T : 3-term f16 hi/lo ----
        float c[4][4];
#pragma unroll
        for (int j = 0; j < 4; j++)
#pragma unroll
            for (int u = 0; u < 4; u++) c[j][u] = 0.f;

#pragma unroll
        for (int ks = 0; ks < 10; ks++) {
            uint32_t ah[4], al[4], bh[8], bl[8];
            ldsm4(ah, sb + SQH + qOff + ks * 32);
            ldsm4(al, sb + SQL + qOff + ks * 32);
            ldsm4(bh,     buf + MKH + kOff + ks * 32);
            ldsm4(bh + 4, buf + MKH + kOff + 16 * ROWB + ks * 32);
            ldsm4(bl,     buf + MKL + kOff + ks * 32);
            ldsm4(bl + 4, buf + MKL + kOff + 16 * ROWB + ks * 32);
#pragma unroll
            for (int j = 0; j < 4; j++) {
                mma_f16(c[j], ah, bh[2 * j], bh[2 * j + 1]);
                mma_f16(c[j], ah, bl[2 * j], bl[2 * j + 1]);
                mma_f16(c[j], al, bh[2 * j], bh[2 * j + 1]);
            }
        }

        // ---- PV(t-1): 2-term (ph*vh + ph*vl), fills pipe during softmax ----
        if (t > 0) {
#pragma unroll
            for (int ks = 0; ks < 2; ks++) {
#pragma unroll
                for (int jp = 0; jp < 10; jp++) {
                    uint32_t v4h[4], v4l[4];
                    ldsm4t(v4h, pbuf + MVH + vOff + ks * (16 * ROWB) + jp * 32);
                    ldsm4t(v4l, pbuf + MVL + vOff + ks * (16 * ROWB) + jp * 32);
                    mma_f16(o[2 * jp],     pah[ks], v4h[0], v4h[1]);
                    mma_f16(o[2 * jp + 1], pah[ks], v4h[2], v4h[3]);
                    mma_f16(o[2 * jp],     pah[ks], v4l[0], v4l[1]);
                    mma_f16(o[2 * jp + 1], pah[ks], v4l[2], v4l[3]);
                }
            }
        }

        // ---- online softmax(t): scores already in log2 units ----
        float mt01 = fmaxf(c[0][0], c[0][1]);
        float mt23 = fmaxf(c[0][2], c[0][3]);
#pragma unroll
        for (int j = 1; j < 4; j++) {
            mt01 = fmaxf(mt01, fmaxf(c[j][0], c[j][1]));
            mt23 = fmaxf(mt23, fmaxf(c[j][2], c[j][3]));
        }
        mt01 = fmaxf(mt01, __shfl_xor_sync(0xffffffffu, mt01, 1));
        mt01 = fmaxf(mt01, __shfl_xor_sync(0xffffffffu, mt01, 2));
        mt23 = fmaxf(mt23, __shfl_xor_sync(0xffffffffu, mt23, 1));
        mt23 = fmaxf(mt23, __shfl_xor_sync(0xffffffffu, mt23, 2));
        float mn01 = fmaxf(mh01, mt01);
        float mn23 = fmaxf(mh23, mt23);
        float a01 = ex2f(mh01 - mn01);
        float a23 = ex2f(mh23 - mn23);
        mh01 = mn01; mh23 = mn23;

        float p[4][4], ps01 = 0.f, ps23 = 0.f;
#pragma unroll
        for (int j = 0; j < 4; j++) {
            p[j][0] = ex2f(c[j][0] - mn01);
            p[j][1] = ex2f(c[j][1] - mn01);
            p[j][2] = ex2f(c[j][2] - mn23);
            p[j][3] = ex2f(c[j][3] - mn23);
            ps01 += p[j][0] + p[j][1];
            ps23 += p[j][2] + p[j][3];
        }
        ls01 = ls01 * a01 + ps01;
        ls23 = ls23 * a23 + ps23;

#pragma unroll
        for (int j = 0; j < 4; j++) {
            int ks = j >> 1, sl = (j & 1) << 1;
            pah[ks][sl]     = packh(p[j][0], p[j][1]);
            pah[ks][sl + 1] = packh(p[j][2], p[j][3]);
        }

        // rescale O (waits on PV(t-1) results; tensor drained during exp)
#pragma unroll
        for (int j = 0; j < 20; j++) {
            o[j][0] *= a01; o[j][1] *= a01;
            o[j][2] *= a23; o[j][3] *= a23;
        }

        cp_wait_all();
        __syncthreads();
    }

    // ---- final PV (tile NT-1) ----
    {
        const uint32_t pbuf = sb + bufoff[(NT - 1) % 3];
#pragma unroll
        for (int ks = 0; ks < 2; ks++) {
#pragma unroll
            for (int jp = 0; jp < 10; jp++) {
                uint32_t v4h[4], v4l[4];
                ldsm4t(v4h, pbuf + MVH + vOff + ks * (16 * ROWB) + jp * 32);
                ldsm4t(v4l, pbuf + MVL + vOff + ks * (16 * ROWB) + jp * 32);
                mma_f16(o[2 * jp],     pah[ks], v4h[0], v4h[1]);
                mma_f16(o[2 * jp + 1], pah[ks], v4h[2], v4h[3]);
                mma_f16(o[2 * jp],     pah[ks], v4l[0], v4l[1]);
                mma_f16(o[2 * jp + 1], pah[ks], v4l[2], v4l[3]);
            }
        }
    }

    // ---- epilogue ----
    ls01 += __shfl_xor_sync(0xffffffffu, ls01, 1);
    ls01 += __shfl_xor_sync(0xffffffffu, ls01, 2);
    ls23 += __shfl_xor_sync(0xffffffffu, ls23, 1);
    ls23 += __shfl_xor_sync(0xffffffffu, ls23, 2);
    const float inv01 = 1.f / ls01;
    const float inv23 = 1.f / ls23;

    const int r0 = m0 + 16 * w + (lane >> 2);
    const size_t row0 = ((size_t)b * SXX + r0) * DD;
    const size_t row1 = row0 + 8 * DD;
    const int cb = 2 * (lane & 3);
#pragma unroll
    for (int j = 0; j < 20; j++) {
        int cc = 8 * j + cb;
        float2 x0 = *(const float2*)(gx + row0 + cc);
        float2 x1 = *(const float2*)(gx + row1 + cc);
        float2 r0v, r1v;
        r0v.x = o[j][0] * inv01 + x0.x;
        r0v.y = o[j][1] * inv01 + x0.y;
        r1v.x = o[j][2] * inv23 + x1.x;
        r1v.y = o[j][3] * inv23 + x1.y;
        *(float2*)(gout + row0 + cc) = r0v;
        *(float2*)(gout + row1 + cc) = r1v;
    }
}

// ---------------------------------------------------------------------------
extern "C" void kernel_launch(void* const* d_in, const int* in_sizes, int n_in,
                              void* d_out, int out_size)
{
    const float* x  = (const float*)d_in[0];
    const float* y  = (const float*)d_in[1];
    const float* Wq = (const float*)d_in[2];
    const float* bq = (const float*)d_in[3];
    const float* Wk = (const float*)d_in[4];
    const float* bk = (const float*)d_in[5];
    const float* Wv = (const float*)d_in[6];
    const float* bv = (const float*)d_in[7];
    float* out = (float*)d_out;

    __half *xh, *xl, *yh, *yl;
    __half *wqh, *wql, *wkh, *wkl, *wvh, *wvl;
    __half *qh, *ql, *kh, *kl, *vh, *vl;
    cudaGetSymbolAddress((void**)&xh, g_xhi);  cudaGetSymbolAddress((void**)&xl, g_xlo);
    cudaGetSymbolAddress((void**)&yh, g_yhi);  cudaGetSymbolAddress((void**)&yl, g_ylo);
    cudaGetSymbolAddress((void**)&wqh, g_wqhi); cudaGetSymbolAddress((void**)&wql, g_wqlo);
    cudaGetSymbolAddress((void**)&wkh, g_wkhi); cudaGetSymbolAddress((void**)&wkl, g_wklo);
    cudaGetSymbolAddress((void**)&wvh, g_wvhi); cudaGetSymbolAddress((void**)&wvl, g_wvlo);
    cudaGetSymbolAddress((void**)&qh, g_qhi);  cudaGetSymbolAddress((void**)&ql, g_qlo);
    cudaGetSymbolAddress((void**)&kh, g_khi);  cudaGetSymbolAddress((void**)&kl, g_klo);
    cudaGetSymbolAddress((void**)&vh, g_vhi);  cudaGetSymbolAddress((void**)&vl, g_vlo);

    split_all<<<20555, 256>>>(x, y, Wq, Wk, Wv,
                              xh, xl, yh, yl,
                              wqh, wql, wkh, wkl, wvh, wvl);

    cudaFuncSetAttribute(proj_mma,
                         cudaFuncAttributeMaxDynamicSharedMemorySize, PROJ_SMEM);
    const int pgrid = (B_ * SXX) / BM;   // 512
    const float LOG2E = 1.4426950408889634f;
    proj_mma<<<pgrid, 256, PROJ_SMEM>>>(xh, xl, wqh, wql, bq, LOG2E, qh, ql);
    proj_mma<<<pgrid, 256, PROJ_SMEM>>>(yh, yl, wkh, wkl, bk, 1.0f, kh, kl);
    proj_mma<<<pgrid, 256, PROJ_SMEM>>>(yh, yl, wvh, wvl, bv, 1.0f, vh, vl);

    cudaFuncSetAttribute(attn_kernel,
                         cudaFuncAttributeMaxDynamicSharedMemorySize, SMEM_TOTAL);
    dim3 grid(SXX / BM, B_);
    attn_kernel<<<grid, 256, SMEM_TOTAL>>>(qh, ql, kh, kl, vh, vl, x, out);
}

// round 7
// speedup vs baseline: 4.2905x; 1.2453x over previous
#include <cuda_runtime.h>
#include <cuda_fp16.h>
#include <math.h>
#include <stdint.h>

#define B_    32
#define SXX   2048
#define SYY   2048
#define DD    160
#define BM    128
#define BN    32
#define NT    (SYY / BN)
#define ROWB  336          // padded row pitch in bytes (168 f16)

// hi/lo f16 splits of inputs and projections (natural [b][m][d] layout)
__device__ __half g_xhi[(size_t)B_ * SXX * DD];
__device__ __half g_xlo[(size_t)B_ * SXX * DD];
__device__ __half g_yhi[(size_t)B_ * SYY * DD];
__device__ __half g_ylo[(size_t)B_ * SYY * DD];
__device__ __half g_wqhi[DD * DD];
__device__ __half g_wqlo[DD * DD];
__device__ __half g_wkhi[DD * DD];
__device__ __half g_wklo[DD * DD];
__device__ __half g_wvhi[DD * DD];
__device__ __half g_wvlo[DD * DD];
__device__ __half g_qhi[(size_t)B_ * SXX * DD];
__device__ __half g_qlo[(size_t)B_ * SXX * DD];
__device__ __half g_khi[(size_t)B_ * SYY * DD];
__device__ __half g_klo[(size_t)B_ * SYY * DD];
__device__ __half g_vhi[(size_t)B_ * SYY * DD];

// ---------------------------------------------------------------------------
// low-level helpers
// ---------------------------------------------------------------------------
__device__ __forceinline__ uint32_t smem_u32(const void* p) {
    uint32_t r;
    asm("{ .reg .u64 t; cvta.to.shared.u64 t, %1; cvt.u32.u64 %0, t; }"
        : "=r"(r) : "l"(p));
    return r;
}
__device__ __forceinline__ void cp16(uint32_t s, const void* g) {
    asm volatile("cp.async.cg.shared.global [%0], [%1], 16;" :: "r"(s), "l"(g));
}
__device__ __forceinline__ void cp_commit() {
    asm volatile("cp.async.commit_group;" ::: "memory");
}
__device__ __forceinline__ void cp_wait_all() {
    asm volatile("cp.async.wait_group 0;" ::: "memory");
}
__device__ __forceinline__ void ldsm4(uint32_t* r, uint32_t a) {
    asm volatile("ldmatrix.sync.aligned.m8n8.x4.shared.b16 {%0,%1,%2,%3}, [%4];"
                 : "=r"(r[0]), "=r"(r[1]), "=r"(r[2]), "=r"(r[3]) : "r"(a));
}
__device__ __forceinline__ void ldsm4t(uint32_t* r, uint32_t a) {
    asm volatile("ldmatrix.sync.aligned.m8n8.x4.trans.shared.b16 {%0,%1,%2,%3}, [%4];"
                 : "=r"(r[0]), "=r"(r[1]), "=r"(r[2]), "=r"(r[3]) : "r"(a));
}
__device__ __forceinline__ void mma_f16(float* c, const uint32_t* a,
                                        uint32_t b0, uint32_t b1) {
    asm volatile("mma.sync.aligned.m16n8k16.row.col.f32.f16.f16.f32 "
                 "{%0,%1,%2,%3}, {%4,%5,%6,%7}, {%8,%9}, {%0,%1,%2,%3};"
                 : "+f"(c[0]), "+f"(c[1]), "+f"(c[2]), "+f"(c[3])
                 : "r"(a[0]), "r"(a[1]), "r"(a[2]), "r"(a[3]), "r"(b0), "r"(b1));
}
__device__ __forceinline__ float ex2f(float x) {
    float r;
    asm("ex2.approx.ftz.f32 %0, %1;" : "=f"(r) : "f"(x));
    return r;
}
__device__ __forceinline__ uint32_t packh(float a, float b) {
    __half2 t = __floats2half2_rn(a, b);
    return *reinterpret_cast<uint32_t*>(&t);
}

// ---------------------------------------------------------------------------
// fp32 -> (hi, lo) f16 split, all five tensors in ONE launch
// ---------------------------------------------------------------------------
__global__ __launch_bounds__(256) void split_all(
    const float* __restrict__ x, const float* __restrict__ y,
    const float* __restrict__ wq, const float* __restrict__ wk,
    const float* __restrict__ wv,
    __half* __restrict__ xh, __half* __restrict__ xl,
    __half* __restrict__ yh, __half* __restrict__ yl,
    __half* __restrict__ wqh, __half* __restrict__ wql,
    __half* __restrict__ wkh, __half* __restrict__ wkl,
    __half* __restrict__ wvh, __half* __restrict__ wvl)
{
    int bid = blockIdx.x;
    const float* src; __half *hi, *lo; int base;
    if (bid < 10240)      { src = x;  hi = xh;  lo = xl;  base = 0; }
    else if (bid < 20480) { src = y;  hi = yh;  lo = yl;  base = 10240; }
    else if (bid < 20505) { src = wq; hi = wqh; lo = wql; base = 20480; }
    else if (bid < 20530) { src = wk; hi = wkh; lo = wkl; base = 20505; }
    else                  { src = wv; hi = wvh; lo = wvl; base = 20530; }
    int i = (bid - base) * 256 + threadIdx.x;
    float4 v = ((const float4*)src)[i];
    __half h0 = __float2half_rn(v.x);
    __half h1 = __float2half_rn(v.y);
    __half h2 = __float2half_rn(v.z);
    __half h3 = __float2half_rn(v.w);
    uint2 hp, lp;
    hp.x = ((uint32_t)__half_as_ushort(h1) << 16) | __half_as_ushort(h0);
    hp.y = ((uint32_t)__half_as_ushort(h3) << 16) | __half_as_ushort(h2);
    lp.x = packh(v.x - __half2float(h0), v.y - __half2float(h1));
    lp.y = packh(v.z - __half2float(h2), v.w - __half2float(h3));
    ((uint2*)hi)[i] = hp;
    ((uint2*)lo)[i] = lp;
}

// ---------------------------------------------------------------------------
// Merged tensor-core projections: blockIdx.y selects {Q, K, V}
// C[m,n] = (sum_d A[m,d]*W[n,d] + bias[n]) * ascale
// ---------------------------------------------------------------------------
#define PSAH 0
#define PSAL 43008
#define PSWH 86016
#define PSWL 139776
#define PROJ_SMEM 193536

__global__ __launch_bounds__(256, 1) void proj_mma(
    const __half* __restrict__ xhi, const __half* __restrict__ xlo,
    const __half* __restrict__ yhi, const __half* __restrict__ ylo,
    const __half* __restrict__ wqh, const __half* __restrict__ wql,
    const __half* __restrict__ wkh, const __half* __restrict__ wkl,
    const __half* __restrict__ wvh, const __half* __restrict__ wvl,
    const float* __restrict__ bq, const float* __restrict__ bk,
    const float* __restrict__ bv,
    __half* __restrict__ qh, __half* __restrict__ ql,
    __half* __restrict__ kh, __half* __restrict__ kl,
    __half* __restrict__ vh)
{
    extern __shared__ char smem[];
    const uint32_t sb = smem_u32(smem);
    const int tid  = threadIdx.x;
    const int lane = tid & 31;
    const int w    = tid >> 5;
    const size_t m0 = (size_t)blockIdx.x * BM;

    const __half *Ahi, *Alo, *Whi, *Wlo;
    const float* bias;
    __half *Chi, *Clo;
    float ascale = 1.0f;
    if (blockIdx.y == 0) {
        Ahi = xhi; Alo = xlo; Whi = wqh; Wlo = wql; bias = bq;
        Chi = qh; Clo = ql; ascale = 1.4426950408889634f;   // log2(e)
    } else if (blockIdx.y == 1) {
        Ahi = yhi; Alo = ylo; Whi = wkh; Wlo = wkl; bias = bk;
        Chi = kh; Clo = kl;
    } else {
        Ahi = yhi; Alo = ylo; Whi = wvh; Wlo = wvl; bias = bv;
        Chi = vh; Clo = nullptr;
    }

#pragma unroll
    for (int i = 0; i < 20; i++) {
        int idx  = i * 256 + tid;
        int half = idx / 2560;
        int rem  = idx - half * 2560;
        int row  = rem / 20, cc = rem - row * 20;
        cp16(sb + (half ? PSAL : PSAH) + row * ROWB + cc * 16,
             (half ? Alo : Ahi) + (m0 + row) * DD + cc * 8);
    }
    for (int idx = tid; idx < 6400; idx += 256) {
        int half = idx / 3200;
        int rem  = idx - half * 3200;
        int row  = rem / 20, cc = rem - row * 20;
        cp16(sb + (half ? PSWL : PSWH) + row * ROWB + cc * 16,
             (half ? Wlo : Whi) + (size_t)row * DD + cc * 8);
    }
    cp_commit();
    cp_wait_all();
    __syncthreads();

    const uint32_t aOff = (uint32_t)((16 * w + (lane & 15)) * ROWB
                                     + ((lane >> 4) << 4));
    const uint32_t bOff = (uint32_t)(((lane & 7) + ((lane >> 4) << 3)) * ROWB
                                     + (((lane >> 3) & 1) << 4));

    float c[20][4];
#pragma unroll
    for (int j = 0; j < 20; j++)
#pragma unroll
        for (int u = 0; u < 4; u++) c[j][u] = 0.f;

#pragma unroll
    for (int ks = 0; ks < 10; ks++) {
        uint32_t ah[4], al[4];
        ldsm4(ah, sb + PSAH + aOff + ks * 32);
        ldsm4(al, sb + PSAL + aOff + ks * 32);
#pragma unroll
        for (int nb = 0; nb < 10; nb++) {
            uint32_t bh[4], bl[4];
            ldsm4(bh, sb + PSWH + bOff + nb * (16 * ROWB) + ks * 32);
            ldsm4(bl, sb + PSWL + bOff + nb * (16 * ROWB) + ks * 32);
            mma_f16(c[2 * nb],     ah, bh[0], bh[1]);
            mma_f16(c[2 * nb + 1], ah, bh[2], bh[3]);
            mma_f16(c[2 * nb],     ah, bl[0], bl[1]);
            mma_f16(c[2 * nb + 1], ah, bl[2], bl[3]);
            mma_f16(c[2 * nb],     al, bh[0], bh[1]);
            mma_f16(c[2 * nb + 1], al, bh[2], bh[3]);
        }
    }

    const size_t r0 = m0 + 16 * w + (lane >> 2);
    const int cb = 2 * (lane & 3);
#pragma unroll
    for (int j = 0; j < 20; j++) {
        int n = 8 * j + cb;
        float2 bvv = *(const float2*)(bias + n);
        float v0 = (c[j][0] + bvv.x) * ascale, v1 = (c[j][1] + bvv.y) * ascale;
        float v2 = (c[j][2] + bvv.x) * ascale, v3 = (c[j][3] + bvv.y) * ascale;
        __half h0 = __float2half_rn(v0);
        __half h1 = __float2half_rn(v1);
        __half h2 = __float2half_rn(v2);
        __half h3 = __float2half_rn(v3);
        *(uint32_t*)(Chi + r0 * DD + n) =
            ((uint32_t)__half_as_ushort(h1) << 16) | __half_as_ushort(h0);
        *(uint32_t*)(Chi + (r0 + 8) * DD + n) =
            ((uint32_t)__half_as_ushort(h3) << 16) | __half_as_ushort(h2);
        if (Clo) {
            *(uint32_t*)(Clo + r0 * DD + n) =
                packh(v0 - __half2float(h0), v1 - __half2float(h1));
            *(uint32_t*)(Clo + (r0 + 8) * DD + n) =
                packh(v2 - __half2float(h2), v3 - __half2float(h3));
        }
    }
}

// ---------------------------------------------------------------------------
// f16 HMMA flash attention: online max, S 3-term, PV 1-term (V = f16),
// deferred PV, triple-buffered K/V. Q pre-scaled by log2e.
// SMEM: Qh @0, Ql @43008; buf{0,1,2} @86016/@118272/@150528
//   each buf: Kh +0, Kl +10752, Vh +21504  (32256 B)
// ---------------------------------------------------------------------------
#define SQH   0
#define SQL   43008
#define MKH   0
#define MKL   10752
#define MVH   21504
#define SMEM_TOTAL 182784

__global__ __launch_bounds__(256, 1) void attn_kernel(
    const __half* __restrict__ qhi, const __half* __restrict__ qlo,
    const __half* __restrict__ khi, const __half* __restrict__ klo,
    const __half* __restrict__ vhi,
    const float* __restrict__ gx, float* __restrict__ gout)
{
    extern __shared__ char smem[];
    const uint32_t sb = smem_u32(smem);
    const int tid  = threadIdx.x;
    const int lane = tid & 31;
    const int w    = tid >> 5;
    const int b    = blockIdx.y;
    const int m0   = blockIdx.x * BM;
    const uint32_t bufoff[3] = { 86016u, 118272u, 150528u };

    {
        const size_t qrow = ((size_t)b * SXX + m0);
#pragma unroll
        for (int i = 0; i < 20; i++) {
            int idx  = i * 256 + tid;
            int half = idx / 2560;
            int rem  = idx - half * 2560;
            int row  = rem / 20, cc = rem - row * 20;
            cp16(sb + (half ? SQL : SQH) + row * ROWB + cc * 16,
                 (half ? qlo : qhi) + (qrow + row) * DD + cc * 8);
        }
    }

    const __half* gsrc[3] = {
        khi + (size_t)b * SYY * DD, klo + (size_t)b * SYY * DD,
        vhi + (size_t)b * SYY * DD };
    const int moff[3] = { MKH, MKL, MVH };

#pragma unroll
    for (int i = 0; i < 8; i++) {
        int idx = i * 256 + tid;
        if (idx < 1920) {
            int mat = idx / 640;
            int rem = idx - mat * 640;
            int row = rem / 20, cc = rem - row * 20;
            cp16(sb + bufoff[0] + moff[mat] + row * ROWB + cc * 16,
                 gsrc[mat] + (size_t)row * DD + cc * 8);
        }
    }
    cp_commit();
    cp_wait_all();
    __syncthreads();

    const uint32_t qOff = (uint32_t)((16 * w + (lane & 15)) * ROWB
                                     + ((lane >> 4) << 4));
    const uint32_t kOff = (uint32_t)(((lane & 7) + ((lane >> 4) << 3)) * ROWB
                                     + (((lane >> 3) & 1) << 4));
    const uint32_t vOff = (uint32_t)(((lane & 7) + (((lane >> 3) & 1) << 3)) * ROWB
                                     + ((lane >> 4) << 4));

    float o[20][4];
#pragma unroll
    for (int j = 0; j < 20; j++)
#pragma unroll
        for (int u = 0; u < 4; u++) o[j][u] = 0.f;

    float mh01 = -INFINITY, mh23 = -INFINITY, ls01 = 0.f, ls23 = 0.f;
    uint32_t pah[2][4];

    for (int t = 0; t < NT; t++) {
        const uint32_t buf  = sb + bufoff[t % 3];
        const uint32_t pbuf = sb + bufoff[(t + 2) % 3];

        if (t + 1 < NT) {
            const uint32_t nbuf = sb + bufoff[(t + 1) % 3];
            const size_t grow = (size_t)(t + 1) * BN;
#pragma unroll
            for (int i = 0; i < 8; i++) {
                int idx = i * 256 + tid;
                if (idx < 1920) {
                    int mat = idx / 640;
                    int rem = idx - mat * 640;
                    int row = rem / 20, cc = rem - row * 20;
                    cp16(nbuf + moff[mat] + row * ROWB + cc * 16,
                         gsrc[mat] + (grow + row) * DD + cc * 8);
                }
            }
            cp_commit();
        }

        // ---- S(t) = Q K^T : 3-term f16 hi/lo ----
        float c[4][4];
#pragma unroll
        for (int j = 0; j < 4; j++)
#pragma unroll
            for (int u = 0; u < 4; u++) c[j][u] = 0.f;

#pragma unroll
        for (int ks = 0; ks < 10; ks++) {
            uint32_t ah[4], al[4], bh[8], bl[8];
            ldsm4(ah, sb + SQH + qOff + ks * 32);
            ldsm4(al, sb + SQL + qOff + ks * 32);
            ldsm4(bh,     buf + MKH + kOff + ks * 32);
            ldsm4(bh + 4, buf + MKH + kOff + 16 * ROWB + ks * 32);
            ldsm4(bl,     buf + MKL + kOff + ks * 32);
            ldsm4(bl + 4, buf + MKL + kOff + 16 * ROWB + ks * 32);
#pragma unroll
            for (int j = 0; j < 4; j++) {
                mma_f16(c[j], ah, bh[2 * j], bh[2 * j + 1]);
                mma_f16(c[j], ah, bl[2 * j], bl[2 * j + 1]);
                mma_f16(c[j], al, bh[2 * j], bh[2 * j + 1]);
            }
        }

        // ---- PV(t-1): 1-term (ph*vh) ----
        if (t > 0) {
#pragma unroll
            for (int ks = 0; ks < 2; ks++) {
#pragma unroll
                for (int jp = 0; jp < 10; jp++) {
                    uint32_t v4h[4];
                    ldsm4t(v4h, pbuf + MVH + vOff + ks * (16 * ROWB) + jp * 32);
                    mma_f16(o[2 * jp],     pah[ks], v4h[0], v4h[1]);
                    mma_f16(o[2 * jp + 1], pah[ks], v4h[2], v4h[3]);
                }
            }
        }

        // ---- online softmax(t): scores in log2 units ----
        float mt01 = fmaxf(c[0][0], c[0][1]);
        float mt23 = fmaxf(c[0][2], c[0][3]);
#pragma unroll
        for (int j = 1; j < 4; j++) {
            mt01 = fmaxf(mt01, fmaxf(c[j][0], c[j][1]));
            mt23 = fmaxf(mt23, fmaxf(c[j][2], c[j][3]));
        }
        mt01 = fmaxf(mt01, __shfl_xor_sync(0xffffffffu, mt01, 1));
        mt01 = fmaxf(mt01, __shfl_xor_sync(0xffffffffu, mt01, 2));
        mt23 = fmaxf(mt23, __shfl_xor_sync(0xffffffffu, mt23, 1));
        mt23 = fmaxf(mt23, __shfl_xor_sync(0xffffffffu, mt23, 2));
        float mn01 = fmaxf(mh01, mt01);
        float mn23 = fmaxf(mh23, mt23);
        float a01 = ex2f(mh01 - mn01);
        float a23 = ex2f(mh23 - mn23);
        mh01 = mn01; mh23 = mn23;

        float p[4][4], ps01 = 0.f, ps23 = 0.f;
#pragma unroll
        for (int j = 0; j < 4; j++) {
            p[j][0] = ex2f(c[j][0] - mn01);
            p[j][1] = ex2f(c[j][1] - mn01);
            p[j][2] = ex2f(c[j][2] - mn23);
            p[j][3] = ex2f(c[j][3] - mn23);
            ps01 += p[j][0] + p[j][1];
            ps23 += p[j][2] + p[j][3];
        }
        ls01 = ls01 * a01 + ps01;
        ls23 = ls23 * a23 + ps23;

#pragma unroll
        for (int j = 0; j < 4; j++) {
            int ks = j >> 1, sl = (j & 1) << 1;
            pah[ks][sl]     = packh(p[j][0], p[j][1]);
            pah[ks][sl + 1] = packh(p[j][2], p[j][3]);
        }

#pragma unroll
        for (int j = 0; j < 20; j++) {
            o[j][0] *= a01; o[j][1] *= a01;
            o[j][2] *= a23; o[j][3] *= a23;
        }

        cp_wait_all();
        __syncthreads();
    }

    // ---- final PV (tile NT-1) ----
    {
        const uint32_t pbuf = sb + bufoff[(NT - 1) % 3];
#pragma unroll
        for (int ks = 0; ks < 2; ks++) {
#pragma unroll
            for (int jp = 0; jp < 10; jp++) {
                uint32_t v4h[4];
                ldsm4t(v4h, pbuf + MVH + vOff + ks * (16 * ROWB) + jp * 32);
                mma_f16(o[2 * jp],     pah[ks], v4h[0], v4h[1]);
                mma_f16(o[2 * jp + 1], pah[ks], v4h[2], v4h[3]);
            }
        }
    }

    // ---- epilogue ----
    ls01 += __shfl_xor_sync(0xffffffffu, ls01, 1);
    ls01 += __shfl_xor_sync(0xffffffffu, ls01, 2);
    ls23 += __shfl_xor_sync(0xffffffffu, ls23, 1);
    ls23 += __shfl_xor_sync(0xffffffffu, ls23, 2);
    const float inv01 = 1.f / ls01;
    const float inv23 = 1.f / ls23;

    const int r0 = m0 + 16 * w + (lane >> 2);
    const size_t row0 = ((size_t)b * SXX + r0) * DD;
    const size_t row1 = row0 + 8 * DD;
    const int cb = 2 * (lane & 3);
#pragma unroll
    for (int j = 0; j < 20; j++) {
        int cc = 8 * j + cb;
        float2 x0 = *(const float2*)(gx + row0 + cc);
        float2 x1 = *(const float2*)(gx + row1 + cc);
        float2 r0v, r1v;
        r0v.x = o[j][0] * inv01 + x0.x;
        r0v.y = o[j][1] * inv01 + x0.y;
        r1v.x = o[j][2] * inv23 + x1.x;
        r1v.y = o[j][3] * inv23 + x1.y;
        *(float2*)(gout + row0 + cc) = r0v;
        *(float2*)(gout + row1 + cc) = r1v;
    }
}

// ---------------------------------------------------------------------------
extern "C" void kernel_launch(void* const* d_in, const int* in_sizes, int n_in,
                              void* d_out, int out_size)
{
    const float* x  = (const float*)d_in[0];
    const float* y  = (const float*)d_in[1];
    const float* Wq = (const float*)d_in[2];
    const float* bq = (const float*)d_in[3];
    const float* Wk = (const float*)d_in[4];
    const float* bk = (const float*)d_in[5];
    const float* Wv = (const float*)d_in[6];
    const float* bv = (const float*)d_in[7];
    float* out = (float*)d_out;

    __half *xh, *xl, *yh, *yl;
    __half *wqh, *wql, *wkh, *wkl, *wvh, *wvl;
    __half *qh, *ql, *kh, *kl, *vh;
    cudaGetSymbolAddress((void**)&xh, g_xhi);  cudaGetSymbolAddress((void**)&xl, g_xlo);
    cudaGetSymbolAddress((void**)&yh, g_yhi);  cudaGetSymbolAddress((void**)&yl, g_ylo);
    cudaGetSymbolAddress((void**)&wqh, g_wqhi); cudaGetSymbolAddress((void**)&wql, g_wqlo);
    cudaGetSymbolAddress((void**)&wkh, g_wkhi); cudaGetSymbolAddress((void**)&wkl, g_wklo);
    cudaGetSymbolAddress((void**)&wvh, g_wvhi); cudaGetSymbolAddress((void**)&wvl, g_wvlo);
    cudaGetSymbolAddress((void**)&qh, g_qhi);  cudaGetSymbolAddress((void**)&ql, g_qlo);
    cudaGetSymbolAddress((void**)&kh, g_khi);  cudaGetSymbolAddress((void**)&kl, g_klo);
    cudaGetSymbolAddress((void**)&vh, g_vhi);

    split_all<<<20555, 256>>>(x, y, Wq, Wk, Wv,
                              xh, xl, yh, yl,
                              wqh, wql, wkh, wkl, wvh, wvl);

    cudaFuncSetAttribute(proj_mma,
                         cudaFuncAttributeMaxDynamicSharedMemorySize, PROJ_SMEM);
    dim3 pgrid((B_ * SXX) / BM, 3);   // 512 x 3
    proj_mma<<<pgrid, 256, PROJ_SMEM>>>(xh, xl, yh, yl,
                                        wqh, wql, wkh, wkl, wvh, wvl,
                                        bq, bk, bv,
                                        qh, ql, kh, kl, vh);

    cudaFuncSetAttribute(attn_kernel,
                         cudaFuncAttributeMaxDynamicSharedMemorySize, SMEM_TOTAL);
    dim3 grid(SXX / BM, B_);
    attn_kernel<<<grid, 256, SMEM_TOTAL>>>(qh, ql, kh, kl, vh, x, out);
}

// round 8
// speedup vs baseline: 4.3687x; 1.0182x over previous
#include <cuda_runtime.h>
#include <cuda_fp16.h>
#include <math.h>
#include <stdint.h>

#define B_    32
#define SXX   2048
#define SYY   2048
#define DD    160
#define BM    128
#define BN    32
#define NT    (SYY / BN)
#define ROWB  336          // padded row pitch in bytes (168 f16)

// hi/lo f16 splits of inputs and projections (natural [b][m][d] layout)
__device__ __half g_xhi[(size_t)B_ * SXX * DD];
__device__ __half g_xlo[(size_t)B_ * SXX * DD];
__device__ __half g_yhi[(size_t)B_ * SYY * DD];
__device__ __half g_ylo[(size_t)B_ * SYY * DD];
__device__ __half g_wqhi[DD * DD];
__device__ __half g_wqlo[DD * DD];
__device__ __half g_wkhi[DD * DD];
__device__ __half g_wklo[DD * DD];
__device__ __half g_wvhi[DD * DD];
__device__ __half g_wvlo[DD * DD];
__device__ __half g_qhi[(size_t)B_ * SXX * DD];
__device__ __half g_qlo[(size_t)B_ * SXX * DD];
__device__ __half g_khi[(size_t)B_ * SYY * DD];
__device__ __half g_klo[(size_t)B_ * SYY * DD];
__device__ __half g_vhi[(size_t)B_ * SYY * DD];

// ---------------------------------------------------------------------------
// low-level helpers
// ---------------------------------------------------------------------------
__device__ __forceinline__ uint32_t smem_u32(const void* p) {
    uint32_t r;
    asm("{ .reg .u64 t; cvta.to.shared.u64 t, %1; cvt.u32.u64 %0, t; }"
        : "=r"(r) : "l"(p));
    return r;
}
__device__ __forceinline__ void cp16(uint32_t s, const void* g) {
    asm volatile("cp.async.cg.shared.global [%0], [%1], 16;" :: "r"(s), "l"(g));
}
__device__ __forceinline__ void cp_commit() {
    asm volatile("cp.async.commit_group;" ::: "memory");
}
__device__ __forceinline__ void cp_wait_all() {
    asm volatile("cp.async.wait_group 0;" ::: "memory");
}
__device__ __forceinline__ void ldsm4(uint32_t* r, uint32_t a) {
    asm volatile("ldmatrix.sync.aligned.m8n8.x4.shared.b16 {%0,%1,%2,%3}, [%4];"
                 : "=r"(r[0]), "=r"(r[1]), "=r"(r[2]), "=r"(r[3]) : "r"(a));
}
__device__ __forceinline__ void ldsm4t(uint32_t* r, uint32_t a) {
    asm volatile("ldmatrix.sync.aligned.m8n8.x4.trans.shared.b16 {%0,%1,%2,%3}, [%4];"
                 : "=r"(r[0]), "=r"(r[1]), "=r"(r[2]), "=r"(r[3]) : "r"(a));
}
__device__ __forceinline__ void mma_f16(float* c, const uint32_t* a,
                                        uint32_t b0, uint32_t b1) {
    asm volatile("mma.sync.aligned.m16n8k16.row.col.f32.f16.f16.f32 "
                 "{%0,%1,%2,%3}, {%4,%5,%6,%7}, {%8,%9}, {%0,%1,%2,%3};"
                 : "+f"(c[0]), "+f"(c[1]), "+f"(c[2]), "+f"(c[3])
                 : "r"(a[0]), "r"(a[1]), "r"(a[2]), "r"(a[3]), "r"(b0), "r"(b1));
}
__device__ __forceinline__ float ex2f(float x) {
    float r;
    asm("ex2.approx.ftz.f32 %0, %1;" : "=f"(r) : "f"(x));
    return r;
}
__device__ __forceinline__ uint32_t packh(float a, float b) {
    __half2 t = __floats2half2_rn(a, b);
    return *reinterpret_cast<uint32_t*>(&t);
}

// ---------------------------------------------------------------------------
// fp32 -> (hi, lo) f16 split, all five tensors in ONE launch
// ---------------------------------------------------------------------------
__global__ __launch_bounds__(256) void split_all(
    const float* __restrict__ x, const float* __restrict__ y,
    const float* __restrict__ wq, const float* __restrict__ wk,
    const float* __restrict__ wv,
    __half* __restrict__ xh, __half* __restrict__ xl,
    __half* __restrict__ yh, __half* __restrict__ yl,
    __half* __restrict__ wqh, __half* __restrict__ wql,
    __half* __restrict__ wkh, __half* __restrict__ wkl,
    __half* __restrict__ wvh, __half* __restrict__ wvl)
{
    int bid = blockIdx.x;
    const float* src; __half *hi, *lo; int base;
    if (bid < 10240)      { src = x;  hi = xh;  lo = xl;  base = 0; }
    else if (bid < 20480) { src = y;  hi = yh;  lo = yl;  base = 10240; }
    else if (bid < 20505) { src = wq; hi = wqh; lo = wql; base = 20480; }
    else if (bid < 20530) { src = wk; hi = wkh; lo = wkl; base = 20505; }
    else                  { src = wv; hi = wvh; lo = wvl; base = 20530; }
    int i = (bid - base) * 256 + threadIdx.x;
    float4 v = ((const float4*)src)[i];
    __half h0 = __float2half_rn(v.x);
    __half h1 = __float2half_rn(v.y);
    __half h2 = __float2half_rn(v.z);
    __half h3 = __float2half_rn(v.w);
    uint2 hp, lp;
    hp.x = ((uint32_t)__half_as_ushort(h1) << 16) | __half_as_ushort(h0);
    hp.y = ((uint32_t)__half_as_ushort(h3) << 16) | __half_as_ushort(h2);
    lp.x = packh(v.x - __half2float(h0), v.y - __half2float(h1));
    lp.y = packh(v.z - __half2float(h2), v.w - __half2float(h3));
    ((uint2*)hi)[i] = hp;
    ((uint2*)lo)[i] = lp;
}

// ---------------------------------------------------------------------------
// Merged tensor-core projections: blockIdx.y selects {Q, K, V}
// ---------------------------------------------------------------------------
#define PSAH 0
#define PSAL 43008
#define PSWH 86016
#define PSWL 139776
#define PROJ_SMEM 193536

__global__ __launch_bounds__(256, 1) void proj_mma(
    const __half* __restrict__ xhi, const __half* __restrict__ xlo,
    const __half* __restrict__ yhi, const __half* __restrict__ ylo,
    const __half* __restrict__ wqh, const __half* __restrict__ wql,
    const __half* __restrict__ wkh, const __half* __restrict__ wkl,
    const __half* __restrict__ wvh, const __half* __restrict__ wvl,
    const float* __restrict__ bq, const float* __restrict__ bk,
    const float* __restrict__ bv,
    __half* __restrict__ qh, __half* __restrict__ ql,
    __half* __restrict__ kh, __half* __restrict__ kl,
    __half* __restrict__ vh)
{
    extern __shared__ char smem[];
    const uint32_t sb = smem_u32(smem);
    const int tid  = threadIdx.x;
    const int lane = tid & 31;
    const int w    = tid >> 5;
    const size_t m0 = (size_t)blockIdx.x * BM;

    const __half *Ahi, *Alo, *Whi, *Wlo;
    const float* bias;
    __half *Chi, *Clo;
    float ascale = 1.0f;
    if (blockIdx.y == 0) {
        Ahi = xhi; Alo = xlo; Whi = wqh; Wlo = wql; bias = bq;
        Chi = qh; Clo = ql; ascale = 1.4426950408889634f;   // log2(e)
    } else if (blockIdx.y == 1) {
        Ahi = yhi; Alo = ylo; Whi = wkh; Wlo = wkl; bias = bk;
        Chi = kh; Clo = kl;
    } else {
        Ahi = yhi; Alo = ylo; Whi = wvh; Wlo = wvl; bias = bv;
        Chi = vh; Clo = nullptr;
    }

#pragma unroll
    for (int i = 0; i < 20; i++) {
        int idx  = i * 256 + tid;
        int half = idx / 2560;
        int rem  = idx - half * 2560;
        int row  = rem / 20, cc = rem - row * 20;
        cp16(sb + (half ? PSAL : PSAH) + row * ROWB + cc * 16,
             (half ? Alo : Ahi) + (m0 + row) * DD + cc * 8);
    }
    for (int idx = tid; idx < 6400; idx += 256) {
        int half = idx / 3200;
        int rem  = idx - half * 3200;
        int row  = rem / 20, cc = rem - row * 20;
        cp16(sb + (half ? PSWL : PSWH) + row * ROWB + cc * 16,
             (half ? Wlo : Whi) + (size_t)row * DD + cc * 8);
    }
    cp_commit();
    cp_wait_all();
    __syncthreads();

    const uint32_t aOff = (uint32_t)((16 * w + (lane & 15)) * ROWB
                                     + ((lane >> 4) << 4));
    const uint32_t bOff = (uint32_t)(((lane & 7) + ((lane >> 4) << 3)) * ROWB
                                     + (((lane >> 3) & 1) << 4));

    float c[20][4];
#pragma unroll
    for (int j = 0; j < 20; j++)
#pragma unroll
        for (int u = 0; u < 4; u++) c[j][u] = 0.f;

#pragma unroll
    for (int ks = 0; ks < 10; ks++) {
        uint32_t ah[4], al[4];
        ldsm4(ah, sb + PSAH + aOff + ks * 32);
        ldsm4(al, sb + PSAL + aOff + ks * 32);
#pragma unroll
        for (int nb = 0; nb < 10; nb++) {
            uint32_t bh[4], bl[4];
            ldsm4(bh, sb + PSWH + bOff + nb * (16 * ROWB) + ks * 32);
            ldsm4(bl, sb + PSWL + bOff + nb * (16 * ROWB) + ks * 32);
            mma_f16(c[2 * nb],     ah, bh[0], bh[1]);
            mma_f16(c[2 * nb + 1], ah, bh[2], bh[3]);
            mma_f16(c[2 * nb],     ah, bl[0], bl[1]);
            mma_f16(c[2 * nb + 1], ah, bl[2], bl[3]);
            mma_f16(c[2 * nb],     al, bh[0], bh[1]);
            mma_f16(c[2 * nb + 1], al, bh[2], bh[3]);
        }
    }

    const size_t r0 = m0 + 16 * w + (lane >> 2);
    const int cb = 2 * (lane & 3);
#pragma unroll
    for (int j = 0; j < 20; j++) {
        int n = 8 * j + cb;
        float2 bvv = *(const float2*)(bias + n);
        float v0 = (c[j][0] + bvv.x) * ascale, v1 = (c[j][1] + bvv.y) * ascale;
        float v2 = (c[j][2] + bvv.x) * ascale, v3 = (c[j][3] + bvv.y) * ascale;
        __half h0 = __float2half_rn(v0);
        __half h1 = __float2half_rn(v1);
        __half h2 = __float2half_rn(v2);
        __half h3 = __float2half_rn(v3);
        *(uint32_t*)(Chi + r0 * DD + n) =
            ((uint32_t)__half_as_ushort(h1) << 16) | __half_as_ushort(h0);
        *(uint32_t*)(Chi + (r0 + 8) * DD + n) =
            ((uint32_t)__half_as_ushort(h3) << 16) | __half_as_ushort(h2);
        if (Clo) {
            *(uint32_t*)(Clo + r0 * DD + n) =
                packh(v0 - __half2float(h0), v1 - __half2float(h1));
            *(uint32_t*)(Clo + (r0 + 8) * DD + n) =
                packh(v2 - __half2float(h2), v3 - __half2float(h3));
        }
    }
}

// ---------------------------------------------------------------------------
// f16 HMMA flash attention: Q hi/lo persistent in REGISTERS (loaded once via
// one-time smem staging), online max w/ rescale-skip, S 3-term, PV 1-term,
// deferred PV, triple-buffered K/V ring reusing the Q staging smem.
// SMEM: bufs @0 / @32256 / @64512, each: Kh +0, Kl +10752, Vh +21504.
// Q staging (pre-loop only): Qh @0, Ql @43008.
// ---------------------------------------------------------------------------
#define SQH   0
#define SQL   43008
#define MKH   0
#define MKL   10752
#define MVH   21504
#define SMEM_TOTAL 96768

__global__ __launch_bounds__(256, 1) void attn_kernel(
    const __half* __restrict__ qhi, const __half* __restrict__ qlo,
    const __half* __restrict__ khi, const __half* __restrict__ klo,
    const __half* __restrict__ vhi,
    const float* __restrict__ gx, float* __restrict__ gout)
{
    extern __shared__ char smem[];
    const uint32_t sb = smem_u32(smem);
    const int tid  = threadIdx.x;
    const int lane = tid & 31;
    const int w    = tid >> 5;
    const int b    = blockIdx.y;
    const int m0   = blockIdx.x * BM;
    const uint32_t bufoff[3] = { 0u, 32256u, 64512u };

    // ---- stage Q (hi/lo) into smem once ----
    {
        const size_t qrow = ((size_t)b * SXX + m0);
#pragma unroll
        for (int i = 0; i < 20; i++) {
            int idx  = i * 256 + tid;
            int half = idx / 2560;
            int rem  = idx - half * 2560;
            int row  = rem / 20, cc = rem - row * 20;
            cp16(sb + (half ? SQL : SQH) + row * ROWB + cc * 16,
                 (half ? qlo : qhi) + (qrow + row) * DD + cc * 8);
        }
    }
    cp_commit();
    cp_wait_all();
    __syncthreads();

    // ---- Q a-frags -> registers (persist across all KV tiles) ----
    const uint32_t qOff = (uint32_t)((16 * w + (lane & 15)) * ROWB
                                     + ((lane >> 4) << 4));
    uint32_t qh_f[10][4], ql_f[10][4];
#pragma unroll
    for (int ks = 0; ks < 10; ks++) {
        ldsm4(qh_f[ks], sb + SQH + qOff + ks * 32);
        ldsm4(ql_f[ks], sb + SQL + qOff + ks * 32);
    }
    __syncthreads();   // staging reads done; smem now owned by KV ring

    const __half* gsrc[3] = {
        khi + (size_t)b * SYY * DD, klo + (size_t)b * SYY * DD,
        vhi + (size_t)b * SYY * DD };
    const int moff[3] = { MKH, MKL, MVH };

    // ---- tile 0 load ----
#pragma unroll
    for (int i = 0; i < 8; i++) {
        int idx = i * 256 + tid;
        if (idx < 1920) {
            int mat = idx / 640;
            int rem = idx - mat * 640;
            int row = rem / 20, cc = rem - row * 20;
            cp16(sb + bufoff[0] + moff[mat] + row * ROWB + cc * 16,
                 gsrc[mat] + (size_t)row * DD + cc * 8);
        }
    }
    cp_commit();
    cp_wait_all();
    __syncthreads();

    const uint32_t kOff = (uint32_t)(((lane & 7) + ((lane >> 4) << 3)) * ROWB
                                     + (((lane >> 3) & 1) << 4));
    const uint32_t vOff = (uint32_t)(((lane & 7) + (((lane >> 3) & 1) << 3)) * ROWB
                                     + ((lane >> 4) << 4));

    float o[20][4];
#pragma unroll
    for (int j = 0; j < 20; j++)
#pragma unroll
        for (int u = 0; u < 4; u++) o[j][u] = 0.f;

    float mh01 = -INFINITY, mh23 = -INFINITY, ls01 = 0.f, ls23 = 0.f;
    uint32_t pah[2][4];

    for (int t = 0; t < NT; t++) {
        const uint32_t buf  = sb + bufoff[t % 3];
        const uint32_t pbuf = sb + bufoff[(t + 2) % 3];

        if (t + 1 < NT) {
            const uint32_t nbuf = sb + bufoff[(t + 1) % 3];
            const size_t grow = (size_t)(t + 1) * BN;
#pragma unroll
            for (int i = 0; i < 8; i++) {
                int idx = i * 256 + tid;
                if (idx < 1920) {
                    int mat = idx / 640;
                    int rem = idx - mat * 640;
                    int row = rem / 20, cc = rem - row * 20;
                    cp16(nbuf + moff[mat] + row * ROWB + cc * 16,
                         gsrc[mat] + (grow + row) * DD + cc * 8);
                }
            }
            cp_commit();
        }

        // ---- S(t) = Q K^T : 3-term f16 hi/lo, Q from registers ----
        float c[4][4];
#pragma unroll
        for (int j = 0; j < 4; j++)
#pragma unroll
            for (int u = 0; u < 4; u++) c[j][u] = 0.f;

#pragma unroll
        for (int ks = 0; ks < 10; ks++) {
            uint32_t bh[8], bl[8];
            ldsm4(bh,     buf + MKH + kOff + ks * 32);
            ldsm4(bh + 4, buf + MKH + kOff + 16 * ROWB + ks * 32);
            ldsm4(bl,     buf + MKL + kOff + ks * 32);
            ldsm4(bl + 4, buf + MKL + kOff + 16 * ROWB + ks * 32);
#pragma unroll
            for (int j = 0; j < 4; j++) {
                mma_f16(c[j], qh_f[ks], bh[2 * j], bh[2 * j + 1]);
                mma_f16(c[j], qh_f[ks], bl[2 * j], bl[2 * j + 1]);
                mma_f16(c[j], ql_f[ks], bh[2 * j], bh[2 * j + 1]);
            }
        }

        // ---- PV(t-1): 1-term (ph*vh) ----
        if (t > 0) {
#pragma unroll
            for (int ks = 0; ks < 2; ks++) {
#pragma unroll
                for (int jp = 0; jp < 10; jp++) {
                    uint32_t v4h[4];
                    ldsm4t(v4h, pbuf + MVH + vOff + ks * (16 * ROWB) + jp * 32);
                    mma_f16(o[2 * jp],     pah[ks], v4h[0], v4h[1]);
                    mma_f16(o[2 * jp + 1], pah[ks], v4h[2], v4h[3]);
                }
            }
        }

        // ---- online softmax(t): scores in log2 units ----
        float mt01 = fmaxf(c[0][0], c[0][1]);
        float mt23 = fmaxf(c[0][2], c[0][3]);
#pragma unroll
        for (int j = 1; j < 4; j++) {
            mt01 = fmaxf(mt01, fmaxf(c[j][0], c[j][1]));
            mt23 = fmaxf(mt23, fmaxf(c[j][2], c[j][3]));
        }
        mt01 = fmaxf(mt01, __shfl_xor_sync(0xffffffffu, mt01, 1));
        mt01 = fmaxf(mt01, __shfl_xor_sync(0xffffffffu, mt01, 2));
        mt23 = fmaxf(mt23, __shfl_xor_sync(0xffffffffu, mt23, 1));
        mt23 = fmaxf(mt23, __shfl_xor_sync(0xffffffffu, mt23, 2));
        const bool upd = (mt01 > mh01) || (mt23 > mh23);
        float mn01 = fmaxf(mh01, mt01);
        float mn23 = fmaxf(mh23, mt23);
        float a01 = ex2f(mh01 - mn01);
        float a23 = ex2f(mh23 - mn23);
        mh01 = mn01; mh23 = mn23;

        float ps01 = 0.f, ps23 = 0.f;
#pragma unroll
        for (int j = 0; j < 4; j++) {
            float p0 = ex2f(c[j][0] - mn01);
            float p1 = ex2f(c[j][1] - mn01);
            float p2 = ex2f(c[j][2] - mn23);
            float p3 = ex2f(c[j][3] - mn23);
            ps01 += p0 + p1;
            ps23 += p2 + p3;
            int ks = j >> 1, sl = (j & 1) << 1;
            pah[ks][sl]     = packh(p0, p1);
            pah[ks][sl + 1] = packh(p2, p3);
        }
        ls01 = ls01 * a01 + ps01;
        ls23 = ls23 * a23 + ps23;

        if (upd) {   // rescale only when running max advanced (~rare)
#pragma unroll
            for (int j = 0; j < 20; j++) {
                o[j][0] *= a01; o[j][1] *= a01;
                o[j][2] *= a23; o[j][3] *= a23;
            }
        }

        cp_wait_all();
        __syncthreads();
    }

    // ---- final PV (tile NT-1) ----
    {
        const uint32_t pbuf = sb + bufoff[(NT - 1) % 3];
#pragma unroll
        for (int ks = 0; ks < 2; ks++) {
#pragma unroll
            for (int jp = 0; jp < 10; jp++) {
                uint32_t v4h[4];
                ldsm4t(v4h, pbuf + MVH + vOff + ks * (16 * ROWB) + jp * 32);
                mma_f16(o[2 * jp],     pah[ks], v4h[0], v4h[1]);
                mma_f16(o[2 * jp + 1], pah[ks], v4h[2], v4h[3]);
            }
        }
    }

    // ---- epilogue ----
    ls01 += __shfl_xor_sync(0xffffffffu, ls01, 1);
    ls01 += __shfl_xor_sync(0xffffffffu, ls01, 2);
    ls23 += __shfl_xor_sync(0xffffffffu, ls23, 1);
    ls23 += __shfl_xor_sync(0xffffffffu, ls23, 2);
    const float inv01 = 1.f / ls01;
    const float inv23 = 1.f / ls23;

    const int r0 = m0 + 16 * w + (lane >> 2);
    const size_t row0 = ((size_t)b * SXX + r0) * DD;
    const size_t row1 = row0 + 8 * DD;
    const int cb = 2 * (lane & 3);
#pragma unroll
    for (int j = 0; j < 20; j++) {
        int cc = 8 * j + cb;
        float2 x0 = *(const float2*)(gx + row0 + cc);
        float2 x1 = *(const float2*)(gx + row1 + cc);
        float2 r0v, r1v;
        r0v.x = o[j][0] * inv01 + x0.x;
        r0v.y = o[j][1] * inv01 + x0.y;
        r1v.x = o[j][2] * inv23 + x1.x;
        r1v.y = o[j][3] * inv23 + x1.y;
        *(float2*)(gout + row0 + cc) = r0v;
        *(float2*)(gout + row1 + cc) = r1v;
    }
}

// ---------------------------------------------------------------------------
extern "C" void kernel_launch(void* const* d_in, const int* in_sizes, int n_in,
                              void* d_out, int out_size)
{
    const float* x  = (const float*)d_in[0];
    const float* y  = (const float*)d_in[1];
    const float* Wq = (const float*)d_in[2];
    const float* bq = (const float*)d_in[3];
    const float* Wk = (const float*)d_in[4];
    const float* bk = (const float*)d_in[5];
    const float* Wv = (const float*)d_in[6];
    const float* bv = (const float*)d_in[7];
    float* out = (float*)d_out;

    __half *xh, *xl, *yh, *yl;
    __half *wqh, *wql, *wkh, *wkl, *wvh, *wvl;
    __half *qh, *ql, *kh, *kl, *vh;
    cudaGetSymbolAddress((void**)&xh, g_xhi);  cudaGetSymbolAddress((void**)&xl, g_xlo);
    cudaGetSymbolAddress((void**)&yh, g_yhi);  cudaGetSymbolAddress((void**)&yl, g_ylo);
    cudaGetSymbolAddress((void**)&wqh, g_wqhi); cudaGetSymbolAddress((void**)&wql, g_wqlo);
    cudaGetSymbolAddress((void**)&wkh, g_wkhi); cudaGetSymbolAddress((void**)&wkl, g_wklo);
    cudaGetSymbolAddress((void**)&wvh, g_wvhi); cudaGetSymbolAddress((void**)&wvl, g_wvlo);
    cudaGetSymbolAddress((void**)&qh, g_qhi);  cudaGetSymbolAddress((void**)&ql, g_qlo);
    cudaGetSymbolAddress((void**)&kh, g_khi);  cudaGetSymbolAddress((void**)&kl, g_klo);
    cudaGetSymbolAddress((void**)&vh, g_vhi);

    split_all<<<20555, 256>>>(x, y, Wq, Wk, Wv,
                              xh, xl, yh, yl,
                              wqh, wql, wkh, wkl, wvh, wvl);

    cudaFuncSetAttribute(proj_mma,
                         cudaFuncAttributeMaxDynamicSharedMemorySize, PROJ_SMEM);
    dim3 pgrid((B_ * SXX) / BM, 3);   // 512 x 3
    proj_mma<<<pgrid, 256, PROJ_SMEM>>>(xh, xl, yh, yl,
                                        wqh, wql, wkh, wkl, wvh, wvl,
                                        bq, bk, bv,
                                        qh, ql, kh, kl, vh);

    cudaFuncSetAttribute(attn_kernel,
                         cudaFuncAttributeMaxDynamicSharedMemorySize, SMEM_TOTAL);
    dim3 grid(SXX / BM, B_);
    attn_kernel<<<grid, 256, SMEM_TOTAL>>>(qh, ql, kh, kl, vh, x, out);
}

// round 9
// speedup vs baseline: 4.5546x; 1.0425x over previous
#include <cuda_runtime.h>
#include <cuda_fp16.h>
#include <math.h>
#include <stdint.h>

#define B_    32
#define SXX   2048
#define SYY   2048
#define DD    160
#define BM    128
#define BN    64
#define NT    (SYY / BN)
#define ROWB  336          // padded row pitch in bytes (168 f16)

// hi/lo f16 splits of inputs and projections (natural [b][m][d] layout)
__device__ __half g_xhi[(size_t)B_ * SXX * DD];
__device__ __half g_xlo[(size_t)B_ * SXX * DD];
__device__ __half g_yhi[(size_t)B_ * SYY * DD];
__device__ __half g_ylo[(size_t)B_ * SYY * DD];
__device__ __half g_wqhi[DD * DD];
__device__ __half g_wqlo[DD * DD];
__device__ __half g_wkhi[DD * DD];
__device__ __half g_wklo[DD * DD];
__device__ __half g_wvhi[DD * DD];
__device__ __half g_wvlo[DD * DD];
__device__ __half g_qhi[(size_t)B_ * SXX * DD];
__device__ __half g_qlo[(size_t)B_ * SXX * DD];
__device__ __half g_khi[(size_t)B_ * SYY * DD];
__device__ __half g_klo[(size_t)B_ * SYY * DD];
__device__ __half g_vhi[(size_t)B_ * SYY * DD];

// ---------------------------------------------------------------------------
// low-level helpers
// ---------------------------------------------------------------------------
__device__ __forceinline__ uint32_t smem_u32(const void* p) {
    uint32_t r;
    asm("{ .reg .u64 t; cvta.to.shared.u64 t, %1; cvt.u32.u64 %0, t; }"
        : "=r"(r) : "l"(p));
    return r;
}
__device__ __forceinline__ void cp16(uint32_t s, const void* g) {
    asm volatile("cp.async.cg.shared.global [%0], [%1], 16;" :: "r"(s), "l"(g));
}
__device__ __forceinline__ void cp_commit() {
    asm volatile("cp.async.commit_group;" ::: "memory");
}
__device__ __forceinline__ void cp_wait_all() {
    asm volatile("cp.async.wait_group 0;" ::: "memory");
}
__device__ __forceinline__ void ldsm4(uint32_t* r, uint32_t a) {
    asm volatile("ldmatrix.sync.aligned.m8n8.x4.shared.b16 {%0,%1,%2,%3}, [%4];"
                 : "=r"(r[0]), "=r"(r[1]), "=r"(r[2]), "=r"(r[3]) : "r"(a));
}
__device__ __forceinline__ void ldsm4t(uint32_t* r, uint32_t a) {
    asm volatile("ldmatrix.sync.aligned.m8n8.x4.trans.shared.b16 {%0,%1,%2,%3}, [%4];"
                 : "=r"(r[0]), "=r"(r[1]), "=r"(r[2]), "=r"(r[3]) : "r"(a));
}
__device__ __forceinline__ void mma_f16(float* c, const uint32_t* a,
                                        uint32_t b0, uint32_t b1) {
    asm volatile("mma.sync.aligned.m16n8k16.row.col.f32.f16.f16.f32 "
                 "{%0,%1,%2,%3}, {%4,%5,%6,%7}, {%8,%9}, {%0,%1,%2,%3};"
                 : "+f"(c[0]), "+f"(c[1]), "+f"(c[2]), "+f"(c[3])
                 : "r"(a[0]), "r"(a[1]), "r"(a[2]), "r"(a[3]), "r"(b0), "r"(b1));
}
__device__ __forceinline__ float ex2f(float x) {
    float r;
    asm("ex2.approx.ftz.f32 %0, %1;" : "=f"(r) : "f"(x));
    return r;
}
__device__ __forceinline__ uint32_t packh(float a, float b) {
    __half2 t = __floats2half2_rn(a, b);
    return *reinterpret_cast<uint32_t*>(&t);
}

// ---------------------------------------------------------------------------
// fp32 -> (hi, lo) f16 split, all five tensors in ONE launch
// ---------------------------------------------------------------------------
__global__ __launch_bounds__(256) void split_all(
    const float* __restrict__ x, const float* __restrict__ y,
    const float* __restrict__ wq, const float* __restrict__ wk,
    const float* __restrict__ wv,
    __half* __restrict__ xh, __half* __restrict__ xl,
    __half* __restrict__ yh, __half* __restrict__ yl,
    __half* __restrict__ wqh, __half* __restrict__ wql,
    __half* __restrict__ wkh, __half* __restrict__ wkl,
    __half* __restrict__ wvh, __half* __restrict__ wvl)
{
    int bid = blockIdx.x;
    const float* src; __half *hi, *lo; int base;
    if (bid < 10240)      { src = x;  hi = xh;  lo = xl;  base = 0; }
    else if (bid < 20480) { src = y;  hi = yh;  lo = yl;  base = 10240; }
    else if (bid < 20505) { src = wq; hi = wqh; lo = wql; base = 20480; }
    else if (bid < 20530) { src = wk; hi = wkh; lo = wkl; base = 20505; }
    else                  { src = wv; hi = wvh; lo = wvl; base = 20530; }
    int i = (bid - base) * 256 + threadIdx.x;
    float4 v = ((const float4*)src)[i];
    __half h0 = __float2half_rn(v.x);
    __half h1 = __float2half_rn(v.y);
    __half h2 = __float2half_rn(v.z);
    __half h3 = __float2half_rn(v.w);
    uint2 hp, lp;
    hp.x = ((uint32_t)__half_as_ushort(h1) << 16) | __half_as_ushort(h0);
    hp.y = ((uint32_t)__half_as_ushort(h3) << 16) | __half_as_ushort(h2);
    lp.x = packh(v.x - __half2float(h0), v.y - __half2float(h1));
    lp.y = packh(v.z - __half2float(h2), v.w - __half2float(h3));
    ((uint2*)hi)[i] = hp;
    ((uint2*)lo)[i] = lp;
}

// ---------------------------------------------------------------------------
// Merged tensor-core projections: blockIdx.y selects {Q, K, V}
// ---------------------------------------------------------------------------
#define PSAH 0
#define PSAL 43008
#define PSWH 86016
#define PSWL 139776
#define PROJ_SMEM 193536

__global__ __launch_bounds__(256, 1) void proj_mma(
    const __half* __restrict__ xhi, const __half* __restrict__ xlo,
    const __half* __restrict__ yhi, const __half* __restrict__ ylo,
    const __half* __restrict__ wqh, const __half* __restrict__ wql,
    const __half* __restrict__ wkh, const __half* __restrict__ wkl,
    const __half* __restrict__ wvh, const __half* __restrict__ wvl,
    const float* __restrict__ bq, const float* __restrict__ bk,
    const float* __restrict__ bv,
    __half* __restrict__ qh, __half* __restrict__ ql,
    __half* __restrict__ kh, __half* __restrict__ kl,
    __half* __restrict__ vh)
{
    extern __shared__ char smem[];
    const uint32_t sb = smem_u32(smem);
    const int tid  = threadIdx.x;
    const int lane = tid & 31;
    const int w    = tid >> 5;
    const size_t m0 = (size_t)blockIdx.x * BM;

    const __half *Ahi, *Alo, *Whi, *Wlo;
    const float* bias;
    __half *Chi, *Clo;
    float ascale = 1.0f;
    if (blockIdx.y == 0) {
        Ahi = xhi; Alo = xlo; Whi = wqh; Wlo = wql; bias = bq;
        Chi = qh; Clo = ql; ascale = 1.4426950408889634f;   // log2(e)
    } else if (blockIdx.y == 1) {
        Ahi = yhi; Alo = ylo; Whi = wkh; Wlo = wkl; bias = bk;
        Chi = kh; Clo = kl;
    } else {
        Ahi = yhi; Alo = ylo; Whi = wvh; Wlo = wvl; bias = bv;
        Chi = vh; Clo = nullptr;
    }

#pragma unroll
    for (int i = 0; i < 20; i++) {
        int idx  = i * 256 + tid;
        int half = idx / 2560;
        int rem  = idx - half * 2560;
        int row  = rem / 20, cc = rem - row * 20;
        cp16(sb + (half ? PSAL : PSAH) + row * ROWB + cc * 16,
             (half ? Alo : Ahi) + (m0 + row) * DD + cc * 8);
    }
    for (int idx = tid; idx < 6400; idx += 256) {
        int half = idx / 3200;
        int rem  = idx - half * 3200;
        int row  = rem / 20, cc = rem - row * 20;
        cp16(sb + (half ? PSWL : PSWH) + row * ROWB + cc * 16,
             (half ? Wlo : Whi) + (size_t)row * DD + cc * 8);
    }
    cp_commit();
    cp_wait_all();
    __syncthreads();

    const uint32_t aOff = (uint32_t)((16 * w + (lane & 15)) * ROWB
                                     + ((lane >> 4) << 4));
    const uint32_t bOff = (uint32_t)(((lane & 7) + ((lane >> 4) << 3)) * ROWB
                                     + (((lane >> 3) & 1) << 4));

    float c[20][4];
#pragma unroll
    for (int j = 0; j < 20; j++)
#pragma unroll
        for (int u = 0; u < 4; u++) c[j][u] = 0.f;

#pragma unroll
    for (int ks = 0; ks < 10; ks++) {
        uint32_t ah[4], al[4];
        ldsm4(ah, sb + PSAH + aOff + ks * 32);
        ldsm4(al, sb + PSAL + aOff + ks * 32);
#pragma unroll
        for (int nb = 0; nb < 10; nb++) {
            uint32_t bh[4], bl[4];
            ldsm4(bh, sb + PSWH + bOff + nb * (16 * ROWB) + ks * 32);
            ldsm4(bl, sb + PSWL + bOff + nb * (16 * ROWB) + ks * 32);
            mma_f16(c[2 * nb],     ah, bh[0], bh[1]);
            mma_f16(c[2 * nb + 1], ah, bh[2], bh[3]);
            mma_f16(c[2 * nb],     ah, bl[0], bl[1]);
            mma_f16(c[2 * nb + 1], ah, bl[2], bl[3]);
            mma_f16(c[2 * nb],     al, bh[0], bh[1]);
            mma_f16(c[2 * nb + 1], al, bh[2], bh[3]);
        }
    }

    const size_t r0 = m0 + 16 * w + (lane >> 2);
    const int cb = 2 * (lane & 3);
#pragma unroll
    for (int j = 0; j < 20; j++) {
        int n = 8 * j + cb;
        float2 bvv = *(const float2*)(bias + n);
        float v0 = (c[j][0] + bvv.x) * ascale, v1 = (c[j][1] + bvv.y) * ascale;
        float v2 = (c[j][2] + bvv.x) * ascale, v3 = (c[j][3] + bvv.y) * ascale;
        __half h0 = __float2half_rn(v0);
        __half h1 = __float2half_rn(v1);
        __half h2 = __float2half_rn(v2);
        __half h3 = __float2half_rn(v3);
        *(uint32_t*)(Chi + r0 * DD + n) =
            ((uint32_t)__half_as_ushort(h1) << 16) | __half_as_ushort(h0);
        *(uint32_t*)(Chi + (r0 + 8) * DD + n) =
            ((uint32_t)__half_as_ushort(h3) << 16) | __half_as_ushort(h2);
        if (Clo) {
            *(uint32_t*)(Clo + r0 * DD + n) =
                packh(v0 - __half2float(h0), v1 - __half2float(h1));
            *(uint32_t*)(Clo + (r0 + 8) * DD + n) =
                packh(v2 - __half2float(h2), v3 - __half2float(h3));
        }
    }
}

// ---------------------------------------------------------------------------
// f16 HMMA flash attention, BN=64: Q hi/lo persistent in registers,
// online max w/ rescale-skip, S 3-term, PV 1-term, deferred PV,
// triple-buffered K/V ring (ring reuses the Q staging smem).
// Per buffer: Kh +0, Kl +21504, Vh +43008  (64512 B); bufs @0/@64512/@129024
// ---------------------------------------------------------------------------
#define SQH   0
#define SQL   43008
#define MKH   0
#define MKL   21504
#define MVH   43008
#define SMEM_TOTAL 193536

__global__ __launch_bounds__(256, 1) void attn_kernel(
    const __half* __restrict__ qhi, const __half* __restrict__ qlo,
    const __half* __restrict__ khi, const __half* __restrict__ klo,
    const __half* __restrict__ vhi,
    const float* __restrict__ gx, float* __restrict__ gout)
{
    extern __shared__ char smem[];
    const uint32_t sb = smem_u32(smem);
    const int tid  = threadIdx.x;
    const int lane = tid & 31;
    const int w    = tid >> 5;
    const int b    = blockIdx.y;
    const int m0   = blockIdx.x * BM;
    const uint32_t bufoff[3] = { 0u, 64512u, 129024u };

    // ---- stage Q (hi/lo) into smem once ----
    {
        const size_t qrow = ((size_t)b * SXX + m0);
#pragma unroll
        for (int i = 0; i < 20; i++) {
            int idx  = i * 256 + tid;
            int half = idx / 2560;
            int rem  = idx - half * 2560;
            int row  = rem / 20, cc = rem - row * 20;
            cp16(sb + (half ? SQL : SQH) + row * ROWB + cc * 16,
                 (half ? qlo : qhi) + (qrow + row) * DD + cc * 8);
        }
    }
    cp_commit();
    cp_wait_all();
    __syncthreads();

    // ---- Q a-frags -> registers (persist across all KV tiles) ----
    const uint32_t qOff = (uint32_t)((16 * w + (lane & 15)) * ROWB
                                     + ((lane >> 4) << 4));
    uint32_t qh_f[10][4], ql_f[10][4];
#pragma unroll
    for (int ks = 0; ks < 10; ks++) {
        ldsm4(qh_f[ks], sb + SQH + qOff + ks * 32);
        ldsm4(ql_f[ks], sb + SQL + qOff + ks * 32);
    }
    __syncthreads();   // staging reads done; smem now owned by KV ring

    const __half* gsrc[3] = {
        khi + (size_t)b * SYY * DD, klo + (size_t)b * SYY * DD,
        vhi + (size_t)b * SYY * DD };
    const int moff[3] = { MKH, MKL, MVH };

    // ---- tile 0 load: 3 matrices x 64 rows x 20 chunks = 3840 cp16 ----
#pragma unroll
    for (int i = 0; i < 15; i++) {
        int idx = i * 256 + tid;
        int mat = idx / 1280;
        int rem = idx - mat * 1280;
        int row = rem / 20, cc = rem - row * 20;
        cp16(sb + bufoff[0] + moff[mat] + row * ROWB + cc * 16,
             gsrc[mat] + (size_t)row * DD + cc * 8);
    }
    cp_commit();
    cp_wait_all();
    __syncthreads();

    const uint32_t kOff = (uint32_t)(((lane & 7) + ((lane >> 4) << 3)) * ROWB
                                     + (((lane >> 3) & 1) << 4));
    const uint32_t vOff = (uint32_t)(((lane & 7) + (((lane >> 3) & 1) << 3)) * ROWB
                                     + ((lane >> 4) << 4));

    float o[20][4];
#pragma unroll
    for (int j = 0; j < 20; j++)
#pragma unroll
        for (int u = 0; u < 4; u++) o[j][u] = 0.f;

    float mh01 = -INFINITY, mh23 = -INFINITY, ls01 = 0.f, ls23 = 0.f;
    uint32_t pah[4][4];

    for (int t = 0; t < NT; t++) {
        const uint32_t buf  = sb + bufoff[t % 3];
        const uint32_t pbuf = sb + bufoff[(t + 2) % 3];

        if (t + 1 < NT) {
            const uint32_t nbuf = sb + bufoff[(t + 1) % 3];
            const size_t grow = (size_t)(t + 1) * BN;
#pragma unroll
            for (int i = 0; i < 15; i++) {
                int idx = i * 256 + tid;
                int mat = idx / 1280;
                int rem = idx - mat * 1280;
                int row = rem / 20, cc = rem - row * 20;
                cp16(nbuf + moff[mat] + row * ROWB + cc * 16,
                     gsrc[mat] + (grow + row) * DD + cc * 8);
            }
            cp_commit();
        }

        // ---- S(t) = Q K^T : 3-term f16 hi/lo, Q from registers ----
        // 64 KV rows in two n-halves of 32 to cap live b-frag registers
        float c[8][4];
#pragma unroll
        for (int j = 0; j < 8; j++)
#pragma unroll
            for (int u = 0; u < 4; u++) c[j][u] = 0.f;

#pragma unroll
        for (int ks = 0; ks < 10; ks++) {
#pragma unroll
            for (int nh = 0; nh < 2; nh++) {
                uint32_t bh[8], bl[8];
                uint32_t kb = buf + MKH + kOff + nh * (32 * ROWB) + ks * 32;
                uint32_t lb = buf + MKL + kOff + nh * (32 * ROWB) + ks * 32;
                ldsm4(bh,     kb);
                ldsm4(bh + 4, kb + 16 * ROWB);
                ldsm4(bl,     lb);
                ldsm4(bl + 4, lb + 16 * ROWB);
#pragma unroll
                for (int j = 0; j < 4; j++) {
                    float* cj = c[4 * nh + j];
                    mma_f16(cj, qh_f[ks], bh[2 * j], bh[2 * j + 1]);
                    mma_f16(cj, qh_f[ks], bl[2 * j], bl[2 * j + 1]);
                    mma_f16(cj, ql_f[ks], bh[2 * j], bh[2 * j + 1]);
                }
            }
        }

        // ---- PV(t-1): 1-term (ph*vh), k = 64 ----
        if (t > 0) {
#pragma unroll
            for (int ks = 0; ks < 4; ks++) {
#pragma unroll
                for (int jp = 0; jp < 10; jp++) {
                    uint32_t v4h[4];
                    ldsm4t(v4h, pbuf + MVH + vOff + ks * (16 * ROWB) + jp * 32);
                    mma_f16(o[2 * jp],     pah[ks], v4h[0], v4h[1]);
                    mma_f16(o[2 * jp + 1], pah[ks], v4h[2], v4h[3]);
                }
            }
        }

        // ---- online softmax(t): scores in log2 units ----
        float mt01 = fmaxf(c[0][0], c[0][1]);
        float mt23 = fmaxf(c[0][2], c[0][3]);
#pragma unroll
        for (int j = 1; j < 8; j++) {
            mt01 = fmaxf(mt01, fmaxf(c[j][0], c[j][1]));
            mt23 = fmaxf(mt23, fmaxf(c[j][2], c[j][3]));
        }
        mt01 = fmaxf(mt01, __shfl_xor_sync(0xffffffffu, mt01, 1));
        mt01 = fmaxf(mt01, __shfl_xor_sync(0xffffffffu, mt01, 2));
        mt23 = fmaxf(mt23, __shfl_xor_sync(0xffffffffu, mt23, 1));
        mt23 = fmaxf(mt23, __shfl_xor_sync(0xffffffffu, mt23, 2));
        const bool upd = (mt01 > mh01) || (mt23 > mh23);
        float mn01 = fmaxf(mh01, mt01);
        float mn23 = fmaxf(mh23, mt23);
        float a01 = ex2f(mh01 - mn01);
        float a23 = ex2f(mh23 - mn23);
        mh01 = mn01; mh23 = mn23;

        float ps01 = 0.f, ps23 = 0.f;
#pragma unroll
        for (int j = 0; j < 8; j++) {
            float p0 = ex2f(c[j][0] - mn01);
            float p1 = ex2f(c[j][1] - mn01);
            float p2 = ex2f(c[j][2] - mn23);
            float p3 = ex2f(c[j][3] - mn23);
            ps01 += p0 + p1;
            ps23 += p2 + p3;
            int ks = j >> 1, sl = (j & 1) << 1;
            pah[ks][sl]     = packh(p0, p1);
            pah[ks][sl + 1] = packh(p2, p3);
        }
        ls01 = ls01 * a01 + ps01;
        ls23 = ls23 * a23 + ps23;

        if (upd) {   // rescale only when running max advanced (~rare)
#pragma unroll
            for (int j = 0; j < 20; j++) {
                o[j][0] *= a01; o[j][1] *= a01;
                o[j][2] *= a23; o[j][3] *= a23;
            }
        }

        cp_wait_all();
        __syncthreads();
    }

    // ---- final PV (tile NT-1) ----
    {
        const uint32_t pbuf = sb + bufoff[(NT - 1) % 3];
#pragma unroll
        for (int ks = 0; ks < 4; ks++) {
#pragma unroll
            for (int jp = 0; jp < 10; jp++) {
                uint32_t v4h[4];
                ldsm4t(v4h, pbuf + MVH + vOff + ks * (16 * ROWB) + jp * 32);
                mma_f16(o[2 * jp],     pah[ks], v4h[0], v4h[1]);
                mma_f16(o[2 * jp + 1], pah[ks], v4h[2], v4h[3]);
            }
        }
    }

    // ---- epilogue ----
    ls01 += __shfl_xor_sync(0xffffffffu, ls01, 1);
    ls01 += __shfl_xor_sync(0xffffffffu, ls01, 2);
    ls23 += __shfl_xor_sync(0xffffffffu, ls23, 1);
    ls23 += __shfl_xor_sync(0xffffffffu, ls23, 2);
    const float inv01 = 1.f / ls01;
    const float inv23 = 1.f / ls23;

    const int r0 = m0 + 16 * w + (lane >> 2);
    const size_t row0 = ((size_t)b * SXX + r0) * DD;
    const size_t row1 = row0 + 8 * DD;
    const int cb = 2 * (lane & 3);
#pragma unroll
    for (int j = 0; j < 20; j++) {
        int cc = 8 * j + cb;
        float2 x0 = *(const float2*)(gx + row0 + cc);
        float2 x1 = *(const float2*)(gx + row1 + cc);
        float2 r0v, r1v;
        r0v.x = o[j][0] * inv01 + x0.x;
        r0v.y = o[j][1] * inv01 + x0.y;
        r1v.x = o[j][2] * inv23 + x1.x;
        r1v.y = o[j][3] * inv23 + x1.y;
        *(float2*)(gout + row0 + cc) = r0v;
        *(float2*)(gout + row1 + cc) = r1v;
    }
}

// ---------------------------------------------------------------------------
extern "C" void kernel_launch(void* const* d_in, const int* in_sizes, int n_in,
                              void* d_out, int out_size)
{
    const float* x  = (const float*)d_in[0];
    const float* y  = (const float*)d_in[1];
    const float* Wq = (const float*)d_in[2];
    const float* bq = (const float*)d_in[3];
    const float* Wk = (const float*)d_in[4];
    const float* bk = (const float*)d_in[5];
    const float* Wv = (const float*)d_in[6];
    const float* bv = (const float*)d_in[7];
    float* out = (float*)d_out;

    __half *xh, *xl, *yh, *yl;
    __half *wqh, *wql, *wkh, *wkl, *wvh, *wvl;
    __half *qh, *ql, *kh, *kl, *vh;
    cudaGetSymbolAddress((void**)&xh, g_xhi);  cudaGetSymbolAddress((void**)&xl, g_xlo);
    cudaGetSymbolAddress((void**)&yh, g_yhi);  cudaGetSymbolAddress((void**)&yl, g_ylo);
    cudaGetSymbolAddress((void**)&wqh, g_wqhi); cudaGetSymbolAddress((void**)&wql, g_wqlo);
    cudaGetSymbolAddress((void**)&wkh, g_wkhi); cudaGetSymbolAddress((void**)&wkl, g_wklo);
    cudaGetSymbolAddress((void**)&wvh, g_wvhi); cudaGetSymbolAddress((void**)&wvl, g_wvlo);
    cudaGetSymbolAddress((void**)&qh, g_qhi);  cudaGetSymbolAddress((void**)&ql, g_qlo);
    cudaGetSymbolAddress((void**)&kh, g_khi);  cudaGetSymbolAddress((void**)&kl, g_klo);
    cudaGetSymbolAddress((void**)&vh, g_vhi);

    split_all<<<20555, 256>>>(x, y, Wq, Wk, Wv,
                              xh, xl, yh, yl,
                              wqh, wql, wkh, wkl, wvh, wvl);

    cudaFuncSetAttribute(proj_mma,
                         cudaFuncAttributeMaxDynamicSharedMemorySize, PROJ_SMEM);
    dim3 pgrid((B_ * SXX) / BM, 3);   // 512 x 3
    proj_mma<<<pgrid, 256, PROJ_SMEM>>>(xh, xl, yh, yl,
                                        wqh, wql, wkh, wkl, wvh, wvl,
                                        bq, bk, bv,
                                        qh, ql, kh, kl, vh);

    cudaFuncSetAttribute(attn_kernel,
                         cudaFuncAttributeMaxDynamicSharedMemorySize, SMEM_TOTAL);
    dim3 grid(SXX / BM, B_);
    attn_kernel<<<grid, 256, SMEM_TOTAL>>>(qh, ql, kh, kl, vh, x, out);
}

// round 10
// speedup vs baseline: 4.5845x; 1.0066x over previous
#include <cuda_runtime.h>
#include <cuda_fp16.h>
#include <math.h>
#include <stdint.h>

#define B_    32
#define SXX   2048
#define SYY   2048
#define DD    160
#define BM    128
#define BN    64
#define NT    (SYY / BN)
#define ROWB  336          // padded row pitch in bytes (168 f16)

// hi/lo f16 splits of inputs and projections (natural [b][m][d] layout)
__device__ __half g_xhi[(size_t)B_ * SXX * DD];
__device__ __half g_xlo[(size_t)B_ * SXX * DD];
__device__ __half g_yhi[(size_t)B_ * SYY * DD];
__device__ __half g_ylo[(size_t)B_ * SYY * DD];
__device__ __half g_wqhi[DD * DD];
__device__ __half g_wqlo[DD * DD];
__device__ __half g_wkhi[DD * DD];
__device__ __half g_wklo[DD * DD];
__device__ __half g_wvhi[DD * DD];
__device__ __half g_wvlo[DD * DD];
__device__ __half g_qhi[(size_t)B_ * SXX * DD];
__device__ __half g_qlo[(size_t)B_ * SXX * DD];
__device__ __half g_khi[(size_t)B_ * SYY * DD];
__device__ __half g_klo[(size_t)B_ * SYY * DD];
__device__ __half g_vhi[(size_t)B_ * SYY * DD];

// ---------------------------------------------------------------------------
// low-level helpers
// ---------------------------------------------------------------------------
__device__ __forceinline__ uint32_t smem_u32(const void* p) {
    uint32_t r;
    asm("{ .reg .u64 t; cvta.to.shared.u64 t, %1; cvt.u32.u64 %0, t; }"
        : "=r"(r) : "l"(p));
    return r;
}
__device__ __forceinline__ void cp16(uint32_t s, const void* g) {
    asm volatile("cp.async.cg.shared.global [%0], [%1], 16;" :: "r"(s), "l"(g));
}
__device__ __forceinline__ void cp_commit() {
    asm volatile("cp.async.commit_group;" ::: "memory");
}
__device__ __forceinline__ void cp_wait_all() {
    asm volatile("cp.async.wait_group 0;" ::: "memory");
}
__device__ __forceinline__ void ldsm4(uint32_t* r, uint32_t a) {
    asm volatile("ldmatrix.sync.aligned.m8n8.x4.shared.b16 {%0,%1,%2,%3}, [%4];"
                 : "=r"(r[0]), "=r"(r[1]), "=r"(r[2]), "=r"(r[3]) : "r"(a));
}
__device__ __forceinline__ void ldsm4t(uint32_t* r, uint32_t a) {
    asm volatile("ldmatrix.sync.aligned.m8n8.x4.trans.shared.b16 {%0,%1,%2,%3}, [%4];"
                 : "=r"(r[0]), "=r"(r[1]), "=r"(r[2]), "=r"(r[3]) : "r"(a));
}
__device__ __forceinline__ void ldsm2t(uint32_t* r, uint32_t a) {
    asm volatile("ldmatrix.sync.aligned.m8n8.x2.trans.shared.b16 {%0,%1}, [%2];"
                 : "=r"(r[0]), "=r"(r[1]) : "r"(a));
}
__device__ __forceinline__ void mma_f16(float* c, const uint32_t* a,
                                        uint32_t b0, uint32_t b1) {
    asm volatile("mma.sync.aligned.m16n8k16.row.col.f32.f16.f16.f32 "
                 "{%0,%1,%2,%3}, {%4,%5,%6,%7}, {%8,%9}, {%0,%1,%2,%3};"
                 : "+f"(c[0]), "+f"(c[1]), "+f"(c[2]), "+f"(c[3])
                 : "r"(a[0]), "r"(a[1]), "r"(a[2]), "r"(a[3]), "r"(b0), "r"(b1));
}
__device__ __forceinline__ float ex2f(float x) {
    float r;
    asm("ex2.approx.ftz.f32 %0, %1;" : "=f"(r) : "f"(x));
    return r;
}
__device__ __forceinline__ uint32_t ex2h2(uint32_t x) {
    uint32_t r;
    asm("ex2.approx.f16x2 %0, %1;" : "=r"(r) : "r"(x));
    return r;
}
__device__ __forceinline__ uint32_t packh(float a, float b) {
    __half2 t = __floats2half2_rn(a, b);
    return *reinterpret_cast<uint32_t*>(&t);
}

// ---------------------------------------------------------------------------
// fp32 -> (hi, lo) f16 split, all five tensors in ONE launch
// ---------------------------------------------------------------------------
__global__ __launch_bounds__(256) void split_all(
    const float* __restrict__ x, const float* __restrict__ y,
    const float* __restrict__ wq, const float* __restrict__ wk,
    const float* __restrict__ wv,
    __half* __restrict__ xh, __half* __restrict__ xl,
    __half* __restrict__ yh, __half* __restrict__ yl,
    __half* __restrict__ wqh, __half* __restrict__ wql,
    __half* __restrict__ wkh, __half* __restrict__ wkl,
    __half* __restrict__ wvh, __half* __restrict__ wvl)
{
    int bid = blockIdx.x;
    const float* src; __half *hi, *lo; int base;
    if (bid < 10240)      { src = x;  hi = xh;  lo = xl;  base = 0; }
    else if (bid < 20480) { src = y;  hi = yh;  lo = yl;  base = 10240; }
    else if (bid < 20505) { src = wq; hi = wqh; lo = wql; base = 20480; }
    else if (bid < 20530) { src = wk; hi = wkh; lo = wkl; base = 20505; }
    else                  { src = wv; hi = wvh; lo = wvl; base = 20530; }
    int i = (bid - base) * 256 + threadIdx.x;
    float4 v = ((const float4*)src)[i];
    __half h0 = __float2half_rn(v.x);
    __half h1 = __float2half_rn(v.y);
    __half h2 = __float2half_rn(v.z);
    __half h3 = __float2half_rn(v.w);
    uint2 hp, lp;
    hp.x = ((uint32_t)__half_as_ushort(h1) << 16) | __half_as_ushort(h0);
    hp.y = ((uint32_t)__half_as_ushort(h3) << 16) | __half_as_ushort(h2);
    lp.x = packh(v.x - __half2float(h0), v.y - __half2float(h1));
    lp.y = packh(v.z - __half2float(h2), v.w - __half2float(h3));
    ((uint2*)hi)[i] = hp;
    ((uint2*)lo)[i] = lp;
}

// ---------------------------------------------------------------------------
// Merged tensor-core projections: blockIdx.y selects {Q, K, V}
// ---------------------------------------------------------------------------
#define PSAH 0
#define PSAL 43008
#define PSWH 86016
#define PSWL 139776
#define PROJ_SMEM 193536

__global__ __launch_bounds__(256, 1) void proj_mma(
    const __half* __restrict__ xhi, const __half* __restrict__ xlo,
    const __half* __restrict__ yhi, const __half* __restrict__ ylo,
    const __half* __restrict__ wqh, const __half* __restrict__ wql,
    const __half* __restrict__ wkh, const __half* __restrict__ wkl,
    const __half* __restrict__ wvh, const __half* __restrict__ wvl,
    const float* __restrict__ bq, const float* __restrict__ bk,
    const float* __restrict__ bv,
    __half* __restrict__ qh, __half* __restrict__ ql,
    __half* __restrict__ kh, __half* __restrict__ kl,
    __half* __restrict__ vh)
{
    extern __shared__ char smem[];
    const uint32_t sb = smem_u32(smem);
    const int tid  = threadIdx.x;
    const int lane = tid & 31;
    const int w    = tid >> 5;
    const size_t m0 = (size_t)blockIdx.x * BM;

    const __half *Ahi, *Alo, *Whi, *Wlo;
    const float* bias;
    __half *Chi, *Clo;
    float ascale = 1.0f;
    if (blockIdx.y == 0) {
        Ahi = xhi; Alo = xlo; Whi = wqh; Wlo = wql; bias = bq;
        Chi = qh; Clo = ql; ascale = 1.4426950408889634f;   // log2(e)
    } else if (blockIdx.y == 1) {
        Ahi = yhi; Alo = ylo; Whi = wkh; Wlo = wkl; bias = bk;
        Chi = kh; Clo = kl;
    } else {
        Ahi = yhi; Alo = ylo; Whi = wvh; Wlo = wvl; bias = bv;
        Chi = vh; Clo = nullptr;
    }

#pragma unroll
    for (int i = 0; i < 20; i++) {
        int idx  = i * 256 + tid;
        int half = idx / 2560;
        int rem  = idx - half * 2560;
        int row  = rem / 20, cc = rem - row * 20;
        cp16(sb + (half ? PSAL : PSAH) + row * ROWB + cc * 16,
             (half ? Alo : Ahi) + (m0 + row) * DD + cc * 8);
    }
    for (int idx = tid; idx < 6400; idx += 256) {
        int half = idx / 3200;
        int rem  = idx - half * 3200;
        int row  = rem / 20, cc = rem - row * 20;
        cp16(sb + (half ? PSWL : PSWH) + row * ROWB + cc * 16,
             (half ? Wlo : Whi) + (size_t)row * DD + cc * 8);
    }
    cp_commit();
    cp_wait_all();
    __syncthreads();

    const uint32_t aOff = (uint32_t)((16 * w + (lane & 15)) * ROWB
                                     + ((lane >> 4) << 4));
    const uint32_t bOff = (uint32_t)(((lane & 7) + ((lane >> 4) << 3)) * ROWB
                                     + (((lane >> 3) & 1) << 4));

    float c[20][4];
#pragma unroll
    for (int j = 0; j < 20; j++)
#pragma unroll
        for (int u = 0; u < 4; u++) c[j][u] = 0.f;

#pragma unroll
    for (int ks = 0; ks < 10; ks++) {
        uint32_t ah[4], al[4];
        ldsm4(ah, sb + PSAH + aOff + ks * 32);
        ldsm4(al, sb + PSAL + aOff + ks * 32);
#pragma unroll
        for (int nb = 0; nb < 10; nb++) {
            uint32_t bh[4], bl[4];
            ldsm4(bh, sb + PSWH + bOff + nb * (16 * ROWB) + ks * 32);
            ldsm4(bl, sb + PSWL + bOff + nb * (16 * ROWB) + ks * 32);
            mma_f16(c[2 * nb],     ah, bh[0], bh[1]);
            mma_f16(c[2 * nb + 1], ah, bh[2], bh[3]);
            mma_f16(c[2 * nb],     ah, bl[0], bl[1]);
            mma_f16(c[2 * nb + 1], ah, bl[2], bl[3]);
            mma_f16(c[2 * nb],     al, bh[0], bh[1]);
            mma_f16(c[2 * nb + 1], al, bh[2], bh[3]);
        }
    }

    const size_t r0 = m0 + 16 * w + (lane >> 2);
    const int cb = 2 * (lane & 3);
#pragma unroll
    for (int j = 0; j < 20; j++) {
        int n = 8 * j + cb;
        float2 bvv = *(const float2*)(bias + n);
        float v0 = (c[j][0] + bvv.x) * ascale, v1 = (c[j][1] + bvv.y) * ascale;
        float v2 = (c[j][2] + bvv.x) * ascale, v3 = (c[j][3] + bvv.y) * ascale;
        __half h0 = __float2half_rn(v0);
        __half h1 = __float2half_rn(v1);
        __half h2 = __float2half_rn(v2);
        __half h3 = __float2half_rn(v3);
        *(uint32_t*)(Chi + r0 * DD + n) =
            ((uint32_t)__half_as_ushort(h1) << 16) | __half_as_ushort(h0);
        *(uint32_t*)(Chi + (r0 + 8) * DD + n) =
            ((uint32_t)__half_as_ushort(h3) << 16) | __half_as_ushort(h2);
        if (Clo) {
            *(uint32_t*)(Clo + r0 * DD + n) =
                packh(v0 - __half2float(h0), v1 - __half2float(h1));
            *(uint32_t*)(Clo + (r0 + 8) * DD + n) =
                packh(v2 - __half2float(h2), v3 - __half2float(h3));
        }
    }
}

// ---------------------------------------------------------------------------
// f16 HMMA flash attention, BN=64: Q hi/lo persistent in registers,
// online max w/ rescale-skip, S 3-term, PV 1-term + ones-column (l via MMA),
// f16x2 exp, deferred PV, triple-buffered K/V ring.
// Per buffer: Kh +0, Kl +21504, Vh +43008  (64512 B); bufs @0/@64512/@129024
// V pad cols 160-167 hold {1,0,...,0} -> O col 160 = row-sum of P = l.
// ---------------------------------------------------------------------------
#define SQH   0
#define SQL   43008
#define MKH   0
#define MKL   21504
#define MVH   43008
#define SMEM_TOTAL 193536

__global__ __launch_bounds__(256, 1) void attn_kernel(
    const __half* __restrict__ qhi, const __half* __restrict__ qlo,
    const __half* __restrict__ khi, const __half* __restrict__ klo,
    const __half* __restrict__ vhi,
    const float* __restrict__ gx, float* __restrict__ gout)
{
    extern __shared__ char smem[];
    const uint32_t sb = smem_u32(smem);
    const int tid  = threadIdx.x;
    const int lane = tid & 31;
    const int w    = tid >> 5;
    const int b    = blockIdx.y;
    const int m0   = blockIdx.x * BM;
    const uint32_t bufoff[3] = { 0u, 64512u, 129024u };

    // ---- stage Q (hi/lo) into smem once ----
    {
        const size_t qrow = ((size_t)b * SXX + m0);
#pragma unroll
        for (int i = 0; i < 20; i++) {
            int idx  = i * 256 + tid;
            int half = idx / 2560;
            int rem  = idx - half * 2560;
            int row  = rem / 20, cc = rem - row * 20;
            cp16(sb + (half ? SQL : SQH) + row * ROWB + cc * 16,
                 (half ? qlo : qhi) + (qrow + row) * DD + cc * 8);
        }
    }
    cp_commit();
    cp_wait_all();
    __syncthreads();

    // ---- Q a-frags -> registers (persist across all KV tiles) ----
    const uint32_t qOff = (uint32_t)((16 * w + (lane & 15)) * ROWB
                                     + ((lane >> 4) << 4));
    uint32_t qh_f[10][4], ql_f[10][4];
#pragma unroll
    for (int ks = 0; ks < 10; ks++) {
        ldsm4(qh_f[ks], sb + SQH + qOff + ks * 32);
        ldsm4(ql_f[ks], sb + SQL + qOff + ks * 32);
    }
    __syncthreads();   // staging reads done; smem now owned by KV ring

    // ---- init V pad cols 160-167 of every ring buffer: {1,0,...,0} ----
    if (tid < 192) {
        int bufi = tid / 64, row = tid % 64;
        uint4* p = (uint4*)(smem + bufoff[bufi] + MVH + row * ROWB + 320);
        *p = make_uint4(0x00003C00u, 0u, 0u, 0u);   // half 1.0 at col 160
    }

    const __half* gsrc[3] = {
        khi + (size_t)b * SYY * DD, klo + (size_t)b * SYY * DD,
        vhi + (size_t)b * SYY * DD };
    const int moff[3] = { MKH, MKL, MVH };

    // ---- tile 0 load ----
#pragma unroll
    for (int i = 0; i < 15; i++) {
        int idx = i * 256 + tid;
        int mat = idx / 1280;
        int rem = idx - mat * 1280;
        int row = rem / 20, cc = rem - row * 20;
        cp16(sb + bufoff[0] + moff[mat] + row * ROWB + cc * 16,
             gsrc[mat] + (size_t)row * DD + cc * 8);
    }
    cp_commit();
    cp_wait_all();
    __syncthreads();

    const uint32_t kOff = (uint32_t)(((lane & 7) + ((lane >> 4) << 3)) * ROWB
                                     + (((lane >> 3) & 1) << 4));
    const uint32_t vOff = (uint32_t)(((lane & 7) + (((lane >> 3) & 1) << 3)) * ROWB
                                     + ((lane >> 4) << 4));
    // x2 ldsm: addresses from lanes 0-15 only; same row formula for all lanes
    const uint32_t vOff2 = (uint32_t)(((lane & 7) + (((lane >> 3) & 1) << 3)) * ROWB);

    float o[21][4];   // blocks 0..19 = O cols 0..159; block 20 = l (col 160)
#pragma unroll
    for (int j = 0; j < 21; j++)
#pragma unroll
        for (int u = 0; u < 4; u++) o[j][u] = 0.f;

    float mh01 = -INFINITY, mh23 = -INFINITY;
    uint32_t pah[4][4];

    for (int t = 0; t < NT; t++) {
        const uint32_t buf  = sb + bufoff[t % 3];
        const uint32_t pbuf = sb + bufoff[(t + 2) % 3];

        if (t + 1 < NT) {
            const uint32_t nbuf = sb + bufoff[(t + 1) % 3];
            const size_t grow = (size_t)(t + 1) * BN;
#pragma unroll
            for (int i = 0; i < 15; i++) {
                int idx = i * 256 + tid;
                int mat = idx / 1280;
                int rem = idx - mat * 1280;
                int row = rem / 20, cc = rem - row * 20;
                cp16(nbuf + moff[mat] + row * ROWB + cc * 16,
                     gsrc[mat] + (grow + row) * DD + cc * 8);
            }
            cp_commit();
        }

        // ---- S(t) = Q K^T : 3-term f16 hi/lo, Q from registers ----
        float c[8][4];
#pragma unroll
        for (int j = 0; j < 8; j++)
#pragma unroll
            for (int u = 0; u < 4; u++) c[j][u] = 0.f;

#pragma unroll
        for (int ks = 0; ks < 10; ks++) {
#pragma unroll
            for (int nh = 0; nh < 2; nh++) {
                uint32_t bh[8], bl[8];
                uint32_t kb = buf + MKH + kOff + nh * (32 * ROWB) + ks * 32;
                uint32_t lb = buf + MKL + kOff + nh * (32 * ROWB) + ks * 32;
                ldsm4(bh,     kb);
                ldsm4(bh + 4, kb + 16 * ROWB);
                ldsm4(bl,     lb);
                ldsm4(bl + 4, lb + 16 * ROWB);
#pragma unroll
                for (int j = 0; j < 4; j++) {
                    float* cj = c[4 * nh + j];
                    mma_f16(cj, qh_f[ks], bh[2 * j], bh[2 * j + 1]);
                    mma_f16(cj, qh_f[ks], bl[2 * j], bl[2 * j + 1]);
                    mma_f16(cj, ql_f[ks], bh[2 * j], bh[2 * j + 1]);
                }
            }
        }

        // ---- PV(t-1): 1-term (ph*vh) + ones column, k = 64 ----
        if (t > 0) {
#pragma unroll
            for (int ks = 0; ks < 4; ks++) {
#pragma unroll
                for (int jp = 0; jp < 10; jp++) {
                    uint32_t v4h[4];
                    ldsm4t(v4h, pbuf + MVH + vOff + ks * (16 * ROWB) + jp * 32);
                    mma_f16(o[2 * jp],     pah[ks], v4h[0], v4h[1]);
                    mma_f16(o[2 * jp + 1], pah[ks], v4h[2], v4h[3]);
                }
                uint32_t v2[2];
                ldsm2t(v2, pbuf + MVH + vOff2 + ks * (16 * ROWB) + 320);
                mma_f16(o[20], pah[ks], v2[0], v2[1]);
            }
        }

        // ---- online softmax(t): scores in log2 units; exp in f16x2 ----
        float mt01 = fmaxf(c[0][0], c[0][1]);
        float mt23 = fmaxf(c[0][2], c[0][3]);
#pragma unroll
        for (int j = 1; j < 8; j++) {
            mt01 = fmaxf(mt01, fmaxf(c[j][0], c[j][1]));
            mt23 = fmaxf(mt23, fmaxf(c[j][2], c[j][3]));
        }
        mt01 = fmaxf(mt01, __shfl_xor_sync(0xffffffffu, mt01, 1));
        mt01 = fmaxf(mt01, __shfl_xor_sync(0xffffffffu, mt01, 2));
        mt23 = fmaxf(mt23, __shfl_xor_sync(0xffffffffu, mt23, 1));
        mt23 = fmaxf(mt23, __shfl_xor_sync(0xffffffffu, mt23, 2));
        const bool upd = (mt01 > mh01) || (mt23 > mh23);
        float mn01 = fmaxf(mh01, mt01);
        float mn23 = fmaxf(mh23, mt23);
        float a01 = ex2f(mh01 - mn01);
        float a23 = ex2f(mh23 - mn23);
        mh01 = mn01; mh23 = mn23;

#pragma unroll
        for (int j = 0; j < 8; j++) {
            float t0 = c[j][0] - mn01;
            float t1 = c[j][1] - mn01;
            float t2 = c[j][2] - mn23;
            float t3 = c[j][3] - mn23;
            int ks = j >> 1, sl = (j & 1) << 1;
            pah[ks][sl]     = ex2h2(packh(t0, t1));
            pah[ks][sl + 1] = ex2h2(packh(t2, t3));
        }

        if (upd) {   // rescale O (incl. l column) only when max advanced
#pragma unroll
            for (int j = 0; j < 21; j++) {
                o[j][0] *= a01; o[j][1] *= a01;
                o[j][2] *= a23; o[j][3] *= a23;
            }
        }

        cp_wait_all();
        __syncthreads();
    }

    // ---- final PV (tile NT-1) ----
    {
        const uint32_t pbuf = sb + bufoff[(NT - 1) % 3];
#pragma unroll
        for (int ks = 0; ks < 4; ks++) {
#pragma unroll
            for (int jp = 0; jp < 10; jp++) {
                uint32_t v4h[4];
                ldsm4t(v4h, pbuf + MVH + vOff + ks * (16 * ROWB) + jp * 32);
                mma_f16(o[2 * jp],     pah[ks], v4h[0], v4h[1]);
                mma_f16(o[2 * jp + 1], pah[ks], v4h[2], v4h[3]);
            }
            uint32_t v2[2];
            ldsm2t(v2, pbuf + MVH + vOff2 + ks * (16 * ROWB) + 320);
            mma_f16(o[20], pah[ks], v2[0], v2[1]);
        }
    }

    // ---- epilogue: l = O col 160 (held by lanes with lane&3 == 0) ----
    const int srcl = lane & ~3;
    const float l01 = __shfl_sync(0xffffffffu, o[20][0], srcl);
    const float l23 = __shfl_sync(0xffffffffu, o[20][2], srcl);
    const float inv01 = 1.f / l01;
    const float inv23 = 1.f / l23;

    const int r0 = m0 + 16 * w + (lane >> 2);
    const size_t row0 = ((size_t)b * SXX + r0) * DD;
    const size_t row1 = row0 + 8 * DD;
    const int cb = 2 * (lane & 3);
#pragma unroll
    for (int j = 0; j < 20; j++) {
        int cc = 8 * j + cb;
        float2 x0 = *(const float2*)(gx + row0 + cc);
        float2 x1 = *(const float2*)(gx + row1 + cc);
        float2 r0v, r1v;
        r0v.x = o[j][0] * inv01 + x0.x;
        r0v.y = o[j][1] * inv01 + x0.y;
        r1v.x = o[j][2] * inv23 + x1.x;
        r1v.y = o[j][3] * inv23 + x1.y;
        *(float2*)(gout + row0 + cc) = r0v;
        *(float2*)(gout + row1 + cc) = r1v;
    }
}

// ---------------------------------------------------------------------------
extern "C" void kernel_launch(void* const* d_in, const int* in_sizes, int n_in,
                              void* d_out, int out_size)
{
    const float* x  = (const float*)d_in[0];
    const float* y  = (const float*)d_in[1];
    const float* Wq = (const float*)d_in[2];
    const float* bq = (const float*)d_in[3];
    const float* Wk = (const float*)d_in[4];
    const float* bk = (const float*)d_in[5];
    const float* Wv = (const float*)d_in[6];
    const float* bv = (const float*)d_in[7];
    float* out = (float*)d_out;

    __half *xh, *xl, *yh, *yl;
    __half *wqh, *wql, *wkh, *wkl, *wvh, *wvl;
    __half *qh, *ql, *kh, *kl, *vh;
    cudaGetSymbolAddress((void**)&xh, g_xhi);  cudaGetSymbolAddress((void**)&xl, g_xlo);
    cudaGetSymbolAddress((void**)&yh, g_yhi);  cudaGetSymbolAddress((void**)&yl, g_ylo);
    cudaGetSymbolAddress((void**)&wqh, g_wqhi); cudaGetSymbolAddress((void**)&wql, g_wqlo);
    cudaGetSymbolAddress((void**)&wkh, g_wkhi); cudaGetSymbolAddress((void**)&wkl, g_wklo);
    cudaGetSymbolAddress((void**)&wvh, g_wvhi); cudaGetSymbolAddress((void**)&wvl, g_wvlo);
    cudaGetSymbolAddress((void**)&qh, g_qhi);  cudaGetSymbolAddress((void**)&ql, g_qlo);
    cudaGetSymbolAddress((void**)&kh, g_khi);  cudaGetSymbolAddress((void**)&kl, g_klo);
    cudaGetSymbolAddress((void**)&vh, g_vhi);

    split_all<<<20555, 256>>>(x, y, Wq, Wk, Wv,
                              xh, xl, yh, yl,
                              wqh, wql, wkh, wkl, wvh, wvl);

    cudaFuncSetAttribute(proj_mma,
                         cudaFuncAttributeMaxDynamicSharedMemorySize, PROJ_SMEM);
    dim3 pgrid((B_ * SXX) / BM, 3);   // 512 x 3
    proj_mma<<<pgrid, 256, PROJ_SMEM>>>(xh, xl, yh, yl,
                                        wqh, wql, wkh, wkl, wvh, wvl,
                                        bq, bk, bv,
                                        qh, ql, kh, kl, vh);

    cudaFuncSetAttribute(attn_kernel,
                         cudaFuncAttributeMaxDynamicSharedMemorySize, SMEM_TOTAL);
    dim3 grid(SXX / BM, B_);
    attn_kernel<<<grid, 256, SMEM_TOTAL>>>(qh, ql, kh, kl, vh, x, out);
}

// round 11
// speedup vs baseline: 4.6116x; 1.0059x over previous
#include <cuda_runtime.h>
#include <cuda_fp16.h>
#include <math.h>
#include <stdint.h>

#define B_    32
#define SXX   2048
#define SYY   2048
#define DD    160
#define BM    128
#define BN    64
#define NT    (SYY / BN)
#define ROWB  336          // padded row pitch in bytes (168 f16)

// hi/lo f16 splits of inputs and projections (natural [b][m][d] layout)
__device__ __half g_xhi[(size_t)B_ * SXX * DD];
__device__ __half g_xlo[(size_t)B_ * SXX * DD];
__device__ __half g_yhi[(size_t)B_ * SYY * DD];
__device__ __half g_ylo[(size_t)B_ * SYY * DD];
__device__ __half g_wqhi[DD * DD];
__device__ __half g_wqlo[DD * DD];
__device__ __half g_wkhi[DD * DD];
__device__ __half g_wklo[DD * DD];
__device__ __half g_wvhi[DD * DD];
__device__ __half g_wvlo[DD * DD];
__device__ __half g_qhi[(size_t)B_ * SXX * DD];
__device__ __half g_qlo[(size_t)B_ * SXX * DD];
__device__ __half g_khi[(size_t)B_ * SYY * DD];
__device__ __half g_klo[(size_t)B_ * SYY * DD];
__device__ __half g_vhi[(size_t)B_ * SYY * DD];

// ---------------------------------------------------------------------------
// low-level helpers
// ---------------------------------------------------------------------------
__device__ __forceinline__ uint32_t smem_u32(const void* p) {
    uint32_t r;
    asm("{ .reg .u64 t; cvta.to.shared.u64 t, %1; cvt.u32.u64 %0, t; }"
        : "=r"(r) : "l"(p));
    return r;
}
__device__ __forceinline__ void cp16(uint32_t s, const void* g) {
    asm volatile("cp.async.cg.shared.global [%0], [%1], 16;" :: "r"(s), "l"(g));
}
__device__ __forceinline__ void cp_commit() {
    asm volatile("cp.async.commit_group;" ::: "memory");
}
__device__ __forceinline__ void cp_wait_all() {
    asm volatile("cp.async.wait_group 0;" ::: "memory");
}
template <int N>
__device__ __forceinline__ void cp_wait_n() {
    asm volatile("cp.async.wait_group %0;" :: "n"(N) : "memory");
}
__device__ __forceinline__ void ldsm4(uint32_t* r, uint32_t a) {
    asm volatile("ldmatrix.sync.aligned.m8n8.x4.shared.b16 {%0,%1,%2,%3}, [%4];"
                 : "=r"(r[0]), "=r"(r[1]), "=r"(r[2]), "=r"(r[3]) : "r"(a));
}
__device__ __forceinline__ void ldsm4t(uint32_t* r, uint32_t a) {
    asm volatile("ldmatrix.sync.aligned.m8n8.x4.trans.shared.b16 {%0,%1,%2,%3}, [%4];"
                 : "=r"(r[0]), "=r"(r[1]), "=r"(r[2]), "=r"(r[3]) : "r"(a));
}
__device__ __forceinline__ void ldsm2t(uint32_t* r, uint32_t a) {
    asm volatile("ldmatrix.sync.aligned.m8n8.x2.trans.shared.b16 {%0,%1}, [%2];"
                 : "=r"(r[0]), "=r"(r[1]) : "r"(a));
}
__device__ __forceinline__ void mma_f16(float* c, const uint32_t* a,
                                        uint32_t b0, uint32_t b1) {
    asm volatile("mma.sync.aligned.m16n8k16.row.col.f32.f16.f16.f32 "
                 "{%0,%1,%2,%3}, {%4,%5,%6,%7}, {%8,%9}, {%0,%1,%2,%3};"
                 : "+f"(c[0]), "+f"(c[1]), "+f"(c[2]), "+f"(c[3])
                 : "r"(a[0]), "r"(a[1]), "r"(a[2]), "r"(a[3]), "r"(b0), "r"(b1));
}
__device__ __forceinline__ float ex2f(float x) {
    float r;
    asm("ex2.approx.ftz.f32 %0, %1;" : "=f"(r) : "f"(x));
    return r;
}
__device__ __forceinline__ uint32_t ex2h2(uint32_t x) {
    uint32_t r;
    asm("ex2.approx.f16x2 %0, %1;" : "=r"(r) : "r"(x));
    return r;
}
__device__ __forceinline__ uint32_t packh(float a, float b) {
    __half2 t = __floats2half2_rn(a, b);
    return *reinterpret_cast<uint32_t*>(&t);
}

// ---------------------------------------------------------------------------
// fp32 -> (hi, lo) f16 split, all five tensors in ONE launch
// ---------------------------------------------------------------------------
__global__ __launch_bounds__(256) void split_all(
    const float* __restrict__ x, const float* __restrict__ y,
    const float* __restrict__ wq, const float* __restrict__ wk,
    const float* __restrict__ wv,
    __half* __restrict__ xh, __half* __restrict__ xl,
    __half* __restrict__ yh, __half* __restrict__ yl,
    __half* __restrict__ wqh, __half* __restrict__ wql,
    __half* __restrict__ wkh, __half* __restrict__ wkl,
    __half* __restrict__ wvh, __half* __restrict__ wvl)
{
    int bid = blockIdx.x;
    const float* src; __half *hi, *lo; int base;
    if (bid < 10240)      { src = x;  hi = xh;  lo = xl;  base = 0; }
    else if (bid < 20480) { src = y;  hi = yh;  lo = yl;  base = 10240; }
    else if (bid < 20505) { src = wq; hi = wqh; lo = wql; base = 20480; }
    else if (bid < 20530) { src = wk; hi = wkh; lo = wkl; base = 20505; }
    else                  { src = wv; hi = wvh; lo = wvl; base = 20530; }
    int i = (bid - base) * 256 + threadIdx.x;
    float4 v = ((const float4*)src)[i];
    __half h0 = __float2half_rn(v.x);
    __half h1 = __float2half_rn(v.y);
    __half h2 = __float2half_rn(v.z);
    __half h3 = __float2half_rn(v.w);
    uint2 hp, lp;
    hp.x = ((uint32_t)__half_as_ushort(h1) << 16) | __half_as_ushort(h0);
    hp.y = ((uint32_t)__half_as_ushort(h3) << 16) | __half_as_ushort(h2);
    lp.x = packh(v.x - __half2float(h0), v.y - __half2float(h1));
    lp.y = packh(v.z - __half2float(h2), v.w - __half2float(h3));
    ((uint2*)hi)[i] = hp;
    ((uint2*)lo)[i] = lp;
}

// ---------------------------------------------------------------------------
// Merged tensor-core projections: blockIdx.y selects {Q, K, V}
// K-loop software-pipelined: 5 chunks of k=32, one cp.async group each;
// chunk c computes after wait_group(4-c) -> load/compute overlap.
// ---------------------------------------------------------------------------
#define PSAH 0
#define PSAL 43008
#define PSWH 86016
#define PSWL 139776
#define PROJ_SMEM 193536

__global__ __launch_bounds__(256, 1) void proj_mma(
    const __half* __restrict__ xhi, const __half* __restrict__ xlo,
    const __half* __restrict__ yhi, const __half* __restrict__ ylo,
    const __half* __restrict__ wqh, const __half* __restrict__ wql,
    const __half* __restrict__ wkh, const __half* __restrict__ wkl,
    const __half* __restrict__ wvh, const __half* __restrict__ wvl,
    const float* __restrict__ bq, const float* __restrict__ bk,
    const float* __restrict__ bv,
    __half* __restrict__ qh, __half* __restrict__ ql,
    __half* __restrict__ kh, __half* __restrict__ kl,
    __half* __restrict__ vh)
{
    extern __shared__ char smem[];
    const uint32_t sb = smem_u32(smem);
    const int tid  = threadIdx.x;
    const int lane = tid & 31;
    const int w    = tid >> 5;
    const size_t m0 = (size_t)blockIdx.x * BM;

    const __half *Ahi, *Alo, *Whi, *Wlo;
    const float* bias;
    __half *Chi, *Clo;
    float ascale = 1.0f;
    if (blockIdx.y == 0) {
        Ahi = xhi; Alo = xlo; Whi = wqh; Wlo = wql; bias = bq;
        Chi = qh; Clo = ql; ascale = 1.4426950408889634f;   // log2(e)
    } else if (blockIdx.y == 1) {
        Ahi = yhi; Alo = ylo; Whi = wkh; Wlo = wkl; bias = bk;
        Chi = kh; Clo = kl;
    } else {
        Ahi = yhi; Alo = ylo; Whi = wvh; Wlo = wvl; bias = bv;
        Chi = vh; Clo = nullptr;
    }

    // ---- prologue: issue 5 chunk-groups (A-chunk + W-chunk per group) ----
#pragma unroll
    for (int c = 0; c < 5; c++) {
        // A chunk: 128 rows x 4 x cp16 x 2 halves = 1024
#pragma unroll
        for (int i = 0; i < 4; i++) {
            int idx  = i * 256 + tid;
            int half = idx >> 9;
            int rem  = idx & 511;
            int row  = rem >> 2, c4 = rem & 3;
            cp16(sb + (half ? PSAL : PSAH) + row * ROWB + c * 64 + c4 * 16,
                 (half ? Alo : Ahi) + (m0 + row) * DD + c * 32 + c4 * 8);
        }
        // W chunk: 160 rows x 4 x cp16 x 2 halves = 1280
#pragma unroll
        for (int i = 0; i < 5; i++) {
            int idx  = i * 256 + tid;
            int half = idx / 640;
            int rem  = idx - half * 640;
            int row  = rem >> 2, c4 = rem & 3;
            cp16(sb + (half ? PSWL : PSWH) + row * ROWB + c * 64 + c4 * 16,
                 (half ? Wlo : Whi) + (size_t)row * DD + c * 32 + c4 * 8);
        }
        cp_commit();
    }

    const uint32_t aOff = (uint32_t)((16 * w + (lane & 15)) * ROWB
                                     + ((lane >> 4) << 4));
    const uint32_t bOff = (uint32_t)(((lane & 7) + ((lane >> 4) << 3)) * ROWB
                                     + (((lane >> 3) & 1) << 4));

    float c[20][4];
#pragma unroll
    for (int j = 0; j < 20; j++)
#pragma unroll
        for (int u = 0; u < 4; u++) c[j][u] = 0.f;

    // ---- per-chunk compute: wait for group c, then ks = 2c, 2c+1 ----
#define PROJ_CHUNK(CI, WN)                                                    \
    {                                                                         \
        cp_wait_n<WN>();                                                      \
        __syncthreads();                                                      \
        _Pragma("unroll")                                                     \
        for (int kk = 0; kk < 2; kk++) {                                      \
            const int ks = 2 * (CI) + kk;                                     \
            uint32_t ah[4], al[4];                                            \
            ldsm4(ah, sb + PSAH + aOff + ks * 32);                            \
            ldsm4(al, sb + PSAL + aOff + ks * 32);                            \
            _Pragma("unroll")                                                 \
            for (int nb = 0; nb < 10; nb++) {                                 \
                uint32_t bh[4], bl[4];                                        \
                ldsm4(bh, sb + PSWH + bOff + nb * (16 * ROWB) + ks * 32);     \
                ldsm4(bl, sb + PSWL + bOff + nb * (16 * ROWB) + ks * 32);     \
                mma_f16(c[2 * nb],     ah, bh[0], bh[1]);                     \
                mma_f16(c[2 * nb + 1], ah, bh[2], bh[3]);                     \
                mma_f16(c[2 * nb],     ah, bl[0], bl[1]);                     \
                mma_f16(c[2 * nb + 1], ah, bl[2], bl[3]);                     \
                mma_f16(c[2 * nb],     al, bh[0], bh[1]);                     \
                mma_f16(c[2 * nb + 1], al, bh[2], bh[3]);                     \
            }                                                                 \
        }                                                                     \
    }

    PROJ_CHUNK(0, 4)
    PROJ_CHUNK(1, 3)
    PROJ_CHUNK(2, 2)
    PROJ_CHUNK(3, 1)
    PROJ_CHUNK(4, 0)
#undef PROJ_CHUNK

    const size_t r0 = m0 + 16 * w + (lane >> 2);
    const int cb = 2 * (lane & 3);
#pragma unroll
    for (int j = 0; j < 20; j++) {
        int n = 8 * j + cb;
        float2 bvv = *(const float2*)(bias + n);
        float v0 = (c[j][0] + bvv.x) * ascale, v1 = (c[j][1] + bvv.y) * ascale;
        float v2 = (c[j][2] + bvv.x) * ascale, v3 = (c[j][3] + bvv.y) * ascale;
        __half h0 = __float2half_rn(v0);
        __half h1 = __float2half_rn(v1);
        __half h2 = __float2half_rn(v2);
        __half h3 = __float2half_rn(v3);
        *(uint32_t*)(Chi + r0 * DD + n) =
            ((uint32_t)__half_as_ushort(h1) << 16) | __half_as_ushort(h0);
        *(uint32_t*)(Chi + (r0 + 8) * DD + n) =
            ((uint32_t)__half_as_ushort(h3) << 16) | __half_as_ushort(h2);
        if (Clo) {
            *(uint32_t*)(Clo + r0 * DD + n) =
                packh(v0 - __half2float(h0), v1 - __half2float(h1));
            *(uint32_t*)(Clo + (r0 + 8) * DD + n) =
                packh(v2 - __half2float(h2), v3 - __half2float(h3));
        }
    }
}

// ---------------------------------------------------------------------------
// f16 HMMA flash attention, BN=64 (unchanged from R10):
// Q hi/lo persistent in registers, online max w/ rescale-skip,
// S 3-term, PV 1-term + ones-column (l via MMA), f16x2 exp,
// deferred PV, triple-buffered K/V ring.
// ---------------------------------------------------------------------------
#define SQH   0
#define SQL   43008
#define MKH   0
#define MKL   21504
#define MVH   43008
#define SMEM_TOTAL 193536

__global__ __launch_bounds__(256, 1) void attn_kernel(
    const __half* __restrict__ qhi, const __half* __restrict__ qlo,
    const __half* __restrict__ khi, const __half* __restrict__ klo,
    const __half* __restrict__ vhi,
    const float* __restrict__ gx, float* __restrict__ gout)
{
    extern __shared__ char smem[];
    const uint32_t sb = smem_u32(smem);
    const int tid  = threadIdx.x;
    const int lane = tid & 31;
    const int w    = tid >> 5;
    const int b    = blockIdx.y;
    const int m0   = blockIdx.x * BM;
    const uint32_t bufoff[3] = { 0u, 64512u, 129024u };

    // ---- stage Q (hi/lo) into smem once ----
    {
        const size_t qrow = ((size_t)b * SXX + m0);
#pragma unroll
        for (int i = 0; i < 20; i++) {
            int idx  = i * 256 + tid;
            int half = idx / 2560;
            int rem  = idx - half * 2560;
            int row  = rem / 20, cc = rem - row * 20;
            cp16(sb + (half ? SQL : SQH) + row * ROWB + cc * 16,
                 (half ? qlo : qhi) + (qrow + row) * DD + cc * 8);
        }
    }
    cp_commit();
    cp_wait_all();
    __syncthreads();

    // ---- Q a-frags -> registers (persist across all KV tiles) ----
    const uint32_t qOff = (uint32_t)((16 * w + (lane & 15)) * ROWB
                                     + ((lane >> 4) << 4));
    uint32_t qh_f[10][4], ql_f[10][4];
#pragma unroll
    for (int ks = 0; ks < 10; ks++) {
        ldsm4(qh_f[ks], sb + SQH + qOff + ks * 32);
        ldsm4(ql_f[ks], sb + SQL + qOff + ks * 32);
    }
    __syncthreads();   // staging reads done; smem now owned by KV ring

    // ---- init V pad cols 160-167 of every ring buffer: {1,0,...,0} ----
    if (tid < 192) {
        int bufi = tid / 64, row = tid % 64;
        uint4* p = (uint4*)(smem + bufoff[bufi] + MVH + row * ROWB + 320);
        *p = make_uint4(0x00003C00u, 0u, 0u, 0u);   // half 1.0 at col 160
    }

    const __half* gsrc[3] = {
        khi + (size_t)b * SYY * DD, klo + (size_t)b * SYY * DD,
        vhi + (size_t)b * SYY * DD };
    const int moff[3] = { MKH, MKL, MVH };

    // ---- tile 0 load ----
#pragma unroll
    for (int i = 0; i < 15; i++) {
        int idx = i * 256 + tid;
        int mat = idx / 1280;
        int rem = idx - mat * 1280;
        int row = rem / 20, cc = rem - row * 20;
        cp16(sb + bufoff[0] + moff[mat] + row * ROWB + cc * 16,
             gsrc[mat] + (size_t)row * DD + cc * 8);
    }
    cp_commit();
    cp_wait_all();
    __syncthreads();

    const uint32_t kOff = (uint32_t)(((lane & 7) + ((lane >> 4) << 3)) * ROWB
                                     + (((lane >> 3) & 1) << 4));
    const uint32_t vOff = (uint32_t)(((lane & 7) + (((lane >> 3) & 1) << 3)) * ROWB
                                     + ((lane >> 4) << 4));
    const uint32_t vOff2 = (uint32_t)(((lane & 7) + (((lane >> 3) & 1) << 3)) * ROWB);

    float o[21][4];   // blocks 0..19 = O cols 0..159; block 20 = l (col 160)
#pragma unroll
    for (int j = 0; j < 21; j++)
#pragma unroll
        for (int u = 0; u < 4; u++) o[j][u] = 0.f;

    float mh01 = -INFINITY, mh23 = -INFINITY;
    uint32_t pah[4][4];

    for (int t = 0; t < NT; t++) {
        const uint32_t buf  = sb + bufoff[t % 3];
        const uint32_t pbuf = sb + bufoff[(t + 2) % 3];

        if (t + 1 < NT) {
            const uint32_t nbuf = sb + bufoff[(t + 1) % 3];
            const size_t grow = (size_t)(t + 1) * BN;
#pragma unroll
            for (int i = 0; i < 15; i++) {
                int idx = i * 256 + tid;
                int mat = idx / 1280;
                int rem = idx - mat * 1280;
                int row = rem / 20, cc = rem - row * 20;
                cp16(nbuf + moff[mat] + row * ROWB + cc * 16,
                     gsrc[mat] + (grow + row) * DD + cc * 8);
            }
            cp_commit();
        }

        // ---- S(t) = Q K^T : 3-term f16 hi/lo, Q from registers ----
        float c[8][4];
#pragma unroll
        for (int j = 0; j < 8; j++)
#pragma unroll
            for (int u = 0; u < 4; u++) c[j][u] = 0.f;

#pragma unroll
        for (int ks = 0; ks < 10; ks++) {
#pragma unroll
            for (int nh = 0; nh < 2; nh++) {
                uint32_t bh[8], bl[8];
                uint32_t kb = buf + MKH + kOff + nh * (32 * ROWB) + ks * 32;
                uint32_t lb = buf + MKL + kOff + nh * (32 * ROWB) + ks * 32;
                ldsm4(bh,     kb);
                ldsm4(bh + 4, kb + 16 * ROWB);
                ldsm4(bl,     lb);
                ldsm4(bl + 4, lb + 16 * ROWB);
#pragma unroll
                for (int j = 0; j < 4; j++) {
                    float* cj = c[4 * nh + j];
                    mma_f16(cj, qh_f[ks], bh[2 * j], bh[2 * j + 1]);
                    mma_f16(cj, qh_f[ks], bl[2 * j], bl[2 * j + 1]);
                    mma_f16(cj, ql_f[ks], bh[2 * j], bh[2 * j + 1]);
                }
            }
        }

        // ---- PV(t-1): 1-term (ph*vh) + ones column, k = 64 ----
        if (t > 0) {
#pragma unroll
            for (int ks = 0; ks < 4; ks++) {
#pragma unroll
                for (int jp = 0; jp < 10; jp++) {
                    uint32_t v4h[4];
                    ldsm4t(v4h, pbuf + MVH + vOff + ks * (16 * ROWB) + jp * 32);
                    mma_f16(o[2 * jp],     pah[ks], v4h[0], v4h[1]);
                    mma_f16(o[2 * jp + 1], pah[ks], v4h[2], v4h[3]);
                }
                uint32_t v2[2];
                ldsm2t(v2, pbuf + MVH + vOff2 + ks * (16 * ROWB) + 320);
                mma_f16(o[20], pah[ks], v2[0], v2[1]);
            }
        }

        // ---- online softmax(t): scores in log2 units; exp in f16x2 ----
        float mt01 = fmaxf(c[0][0], c[0][1]);
        float mt23 = fmaxf(c[0][2], c[0][3]);
#pragma unroll
        for (int j = 1; j < 8; j++) {
            mt01 = fmaxf(mt01, fmaxf(c[j][0], c[j][1]));
            mt23 = fmaxf(mt23, fmaxf(c[j][2], c[j][3]));
        }
        mt01 = fmaxf(mt01, __shfl_xor_sync(0xffffffffu, mt01, 1));
        mt01 = fmaxf(mt01, __shfl_xor_sync(0xffffffffu, mt01, 2));
        mt23 = fmaxf(mt23, __shfl_xor_sync(0xffffffffu, mt23, 1));
        mt23 = fmaxf(mt23, __shfl_xor_sync(0xffffffffu, mt23, 2));
        const bool upd = (mt01 > mh01) || (mt23 > mh23);
        float mn01 = fmaxf(mh01, mt01);
        float mn23 = fmaxf(mh23, mt23);
        float a01 = ex2f(mh01 - mn01);
        float a23 = ex2f(mh23 - mn23);
        mh01 = mn01; mh23 = mn23;

#pragma unroll
        for (int j = 0; j < 8; j++) {
            float t0 = c[j][0] - mn01;
            float t1 = c[j][1] - mn01;
            float t2 = c[j][2] - mn23;
            float t3 = c[j][3] - mn23;
            int ks = j >> 1, sl = (j & 1) << 1;
            pah[ks][sl]     = ex2h2(packh(t0, t1));
            pah[ks][sl + 1] = ex2h2(packh(t2, t3));
        }

        if (upd) {   // rescale O (incl. l column) only when max advanced
#pragma unroll
            for (int j = 0; j < 21; j++) {
                o[j][0] *= a01; o[j][1] *= a01;
                o[j][2] *= a23; o[j][3] *= a23;
            }
        }

        cp_wait_all();
        __syncthreads();
    }

    // ---- final PV (tile NT-1) ----
    {
        const uint32_t pbuf = sb + bufoff[(NT - 1) % 3];
#pragma unroll
        for (int ks = 0; ks < 4; ks++) {
#pragma unroll
            for (int jp = 0; jp < 10; jp++) {
                uint32_t v4h[4];
                ldsm4t(v4h, pbuf + MVH + vOff + ks * (16 * ROWB) + jp * 32);
                mma_f16(o[2 * jp],     pah[ks], v4h[0], v4h[1]);
                mma_f16(o[2 * jp + 1], pah[ks], v4h[2], v4h[3]);
            }
            uint32_t v2[2];
            ldsm2t(v2, pbuf + MVH + vOff2 + ks * (16 * ROWB) + 320);
            mma_f16(o[20], pah[ks], v2[0], v2[1]);
        }
    }

    // ---- epilogue: l = O col 160 (held by lanes with lane&3 == 0) ----
    const int srcl = lane & ~3;
    const float l01 = __shfl_sync(0xffffffffu, o[20][0], srcl);
    const float l23 = __shfl_sync(0xffffffffu, o[20][2], srcl);
    const float inv01 = 1.f / l01;
    const float inv23 = 1.f / l23;

    const int r0 = m0 + 16 * w + (lane >> 2);
    const size_t row0 = ((size_t)b * SXX + r0) * DD;
    const size_t row1 = row0 + 8 * DD;
    const int cb = 2 * (lane & 3);
#pragma unroll
    for (int j = 0; j < 20; j++) {
        int cc = 8 * j + cb;
        float2 x0 = *(const float2*)(gx + row0 + cc);
        float2 x1 = *(const float2*)(gx + row1 + cc);
        float2 r0v, r1v;
        r0v.x = o[j][0] * inv01 + x0.x;
        r0v.y = o[j][1] * inv01 + x0.y;
        r1v.x = o[j][2] * inv23 + x1.x;
        r1v.y = o[j][3] * inv23 + x1.y;
        *(float2*)(gout + row0 + cc) = r0v;
        *(float2*)(gout + row1 + cc) = r1v;
    }
}

// ---------------------------------------------------------------------------
extern "C" void kernel_launch(void* const* d_in, const int* in_sizes, int n_in,
                              void* d_out, int out_size)
{
    const float* x  = (const float*)d_in[0];
    const float* y  = (const float*)d_in[1];
    const float* Wq = (const float*)d_in[2];
    const float* bq = (const float*)d_in[3];
    const float* Wk = (const float*)d_in[4];
    const float* bk = (const float*)d_in[5];
    const float* Wv = (const float*)d_in[6];
    const float* bv = (const float*)d_in[7];
    float* out = (float*)d_out;

    __half *xh, *xl, *yh, *yl;
    __half *wqh, *wql, *wkh, *wkl, *wvh, *wvl;
    __half *qh, *ql, *kh, *kl, *vh;
    cudaGetSymbolAddress((void**)&xh, g_xhi);  cudaGetSymbolAddress((void**)&xl, g_xlo);
    cudaGetSymbolAddress((void**)&yh, g_yhi);  cudaGetSymbolAddress((void**)&yl, g_ylo);
    cudaGetSymbolAddress((void**)&wqh, g_wqhi); cudaGetSymbolAddress((void**)&wql, g_wqlo);
    cudaGetSymbolAddress((void**)&wkh, g_wkhi); cudaGetSymbolAddress((void**)&wkl, g_wklo);
    cudaGetSymbolAddress((void**)&wvh, g_wvhi); cudaGetSymbolAddress((void**)&wvl, g_wvlo);
    cudaGetSymbolAddress((void**)&qh, g_qhi);  cudaGetSymbolAddress((void**)&ql, g_qlo);
    cudaGetSymbolAddress((void**)&kh, g_khi);  cudaGetSymbolAddress((void**)&kl, g_klo);
    cudaGetSymbolAddress((void**)&vh, g_vhi);

    split_all<<<20555, 256>>>(x, y, Wq, Wk, Wv,
                              xh, xl, yh, yl,
                              wqh, wql, wkh, wkl, wvh, wvl);

    cudaFuncSetAttribute(proj_mma,
                         cudaFuncAttributeMaxDynamicSharedMemorySize, PROJ_SMEM);
    dim3 pgrid((B_ * SXX) / BM, 3);   // 512 x 3
    proj_mma<<<pgrid, 256, PROJ_SMEM>>>(xh, xl, yh, yl,
                                        wqh, wql, wkh, wkl, wvh, wvl,
                                        bq, bk, bv,
                                        qh, ql, kh, kl, vh);

    cudaFuncSetAttribute(attn_kernel,
                         cudaFuncAttributeMaxDynamicSharedMemorySize, SMEM_TOTAL);
    dim3 grid(SXX / BM, B_);
    attn_kernel<<<grid, 256, SMEM_TOTAL>>>(qh, ql, kh, kl, vh, x, out);
}

// round 12
// speedup vs baseline: 4.7698x; 1.0343x over previous
#include <cuda_runtime.h>
#include <cuda_fp16.h>
#include <math.h>
#include <stdint.h>

#define B_    32
#define SXX   2048
#define SYY   2048
#define DD    160
#define BM    128
#define BN    64
#define NT    (SYY / BN)
#define ROWB  336          // padded row pitch in bytes (168 f16)

// hi/lo f16 projections (natural [b][m][d] layout)
__device__ __half g_qhi[(size_t)B_ * SXX * DD];
__device__ __half g_qlo[(size_t)B_ * SXX * DD];
__device__ __half g_khi[(size_t)B_ * SYY * DD];
__device__ __half g_klo[(size_t)B_ * SYY * DD];
__device__ __half g_vhi[(size_t)B_ * SYY * DD];

// ---------------------------------------------------------------------------
// low-level helpers
// ---------------------------------------------------------------------------
__device__ __forceinline__ uint32_t smem_u32(const void* p) {
    uint32_t r;
    asm("{ .reg .u64 t; cvta.to.shared.u64 t, %1; cvt.u32.u64 %0, t; }"
        : "=r"(r) : "l"(p));
    return r;
}
__device__ __forceinline__ void cp16(uint32_t s, const void* g) {
    asm volatile("cp.async.cg.shared.global [%0], [%1], 16;" :: "r"(s), "l"(g));
}
__device__ __forceinline__ void cp_commit() {
    asm volatile("cp.async.commit_group;" ::: "memory");
}
__device__ __forceinline__ void cp_wait_all() {
    asm volatile("cp.async.wait_group 0;" ::: "memory");
}
__device__ __forceinline__ void ldsm4(uint32_t* r, uint32_t a) {
    asm volatile("ldmatrix.sync.aligned.m8n8.x4.shared.b16 {%0,%1,%2,%3}, [%4];"
                 : "=r"(r[0]), "=r"(r[1]), "=r"(r[2]), "=r"(r[3]) : "r"(a));
}
__device__ __forceinline__ void ldsm4t(uint32_t* r, uint32_t a) {
    asm volatile("ldmatrix.sync.aligned.m8n8.x4.trans.shared.b16 {%0,%1,%2,%3}, [%4];"
                 : "=r"(r[0]), "=r"(r[1]), "=r"(r[2]), "=r"(r[3]) : "r"(a));
}
__device__ __forceinline__ void ldsm2t(uint32_t* r, uint32_t a) {
    asm volatile("ldmatrix.sync.aligned.m8n8.x2.trans.shared.b16 {%0,%1}, [%2];"
                 : "=r"(r[0]), "=r"(r[1]) : "r"(a));
}
__device__ __forceinline__ void mma_f16(float* c, const uint32_t* a,
                                        uint32_t b0, uint32_t b1) {
    asm volatile("mma.sync.aligned.m16n8k16.row.col.f32.f16.f16.f32 "
                 "{%0,%1,%2,%3}, {%4,%5,%6,%7}, {%8,%9}, {%0,%1,%2,%3};"
                 : "+f"(c[0]), "+f"(c[1]), "+f"(c[2]), "+f"(c[3])
                 : "r"(a[0]), "r"(a[1]), "r"(a[2]), "r"(a[3]), "r"(b0), "r"(b1));
}
__device__ __forceinline__ float ex2f(float x) {
    float r;
    asm("ex2.approx.ftz.f32 %0, %1;" : "=f"(r) : "f"(x));
    return r;
}
__device__ __forceinline__ uint32_t ex2h2(uint32_t x) {
    uint32_t r;
    asm("ex2.approx.f16x2 %0, %1;" : "=r"(r) : "r"(x));
    return r;
}
__device__ __forceinline__ uint32_t packh(float a, float b) {
    __half2 t = __floats2half2_rn(a, b);
    return *reinterpret_cast<uint32_t*>(&t);
}
// fp32x4 -> hi/lo f16x2 pairs (identical math to the old split kernel)
__device__ __forceinline__ void cvt_hilo(float4 v, uint2& hp, uint2& lp) {
    __half h0 = __float2half_rn(v.x);
    __half h1 = __float2half_rn(v.y);
    __half h2 = __float2half_rn(v.z);
    __half h3 = __float2half_rn(v.w);
    hp.x = ((uint32_t)__half_as_ushort(h1) << 16) | __half_as_ushort(h0);
    hp.y = ((uint32_t)__half_as_ushort(h3) << 16) | __half_as_ushort(h2);
    lp.x = packh(v.x - __half2float(h0), v.y - __half2float(h1));
    lp.y = packh(v.z - __half2float(h2), v.w - __half2float(h3));
}

// ---------------------------------------------------------------------------
// Merged tensor-core projections with FUSED fp32->f16 hi/lo conversion.
// blockIdx.y selects {Q, K, V}. C[m,n] = (sum_d A[m,d]*W[n,d] + b[n])*ascale
// ---------------------------------------------------------------------------
#define PSAH 0
#define PSAL 43008
#define PSWH 86016
#define PSWL 139776
#define PROJ_SMEM 193536

__global__ __launch_bounds__(256, 1) void proj_mma(
    const float* __restrict__ x, const float* __restrict__ y,
    const float* __restrict__ wq, const float* __restrict__ wk,
    const float* __restrict__ wv,
    const float* __restrict__ bq, const float* __restrict__ bk,
    const float* __restrict__ bv,
    __half* __restrict__ qh, __half* __restrict__ ql,
    __half* __restrict__ kh, __half* __restrict__ kl,
    __half* __restrict__ vh)
{
    extern __shared__ char smem[];
    const uint32_t sb = smem_u32(smem);
    const int tid  = threadIdx.x;
    const int lane = tid & 31;
    const int w    = tid >> 5;
    const size_t m0 = (size_t)blockIdx.x * BM;

    const float *Asrc, *Wsrc, *bias;
    __half *Chi, *Clo;
    float ascale = 1.0f;
    if (blockIdx.y == 0) {
        Asrc = x; Wsrc = wq; bias = bq;
        Chi = qh; Clo = ql; ascale = 1.4426950408889634f;   // log2(e)
    } else if (blockIdx.y == 1) {
        Asrc = y; Wsrc = wk; bias = bk;
        Chi = kh; Clo = kl;
    } else {
        Asrc = y; Wsrc = wv; bias = bv;
        Chi = vh; Clo = nullptr;
    }

    // ---- load A (128 x 160 fp32) -> convert -> smem hi/lo ----
#pragma unroll
    for (int i = 0; i < 20; i++) {
        int idx = i * 256 + tid;          // < 5120
        int row = idx / 40, c4 = idx % 40;
        float4 v = *(const float4*)(Asrc + (m0 + row) * DD + c4 * 4);
        uint2 hp, lp;
        cvt_hilo(v, hp, lp);
        *(uint2*)(smem + PSAH + row * ROWB + c4 * 8) = hp;
        *(uint2*)(smem + PSAL + row * ROWB + c4 * 8) = lp;
    }
    // ---- load W (160 x 160 fp32) -> convert -> smem hi/lo ----
#pragma unroll
    for (int i = 0; i < 25; i++) {
        int idx = i * 256 + tid;          // < 6400
        int row = idx / 40, c4 = idx % 40;
        float4 v = *(const float4*)(Wsrc + (size_t)row * DD + c4 * 4);
        uint2 hp, lp;
        cvt_hilo(v, hp, lp);
        *(uint2*)(smem + PSWH + row * ROWB + c4 * 8) = hp;
        *(uint2*)(smem + PSWL + row * ROWB + c4 * 8) = lp;
    }
    __syncthreads();

    const uint32_t aOff = (uint32_t)((16 * w + (lane & 15)) * ROWB
                                     + ((lane >> 4) << 4));
    const uint32_t bOff = (uint32_t)(((lane & 7) + ((lane >> 4) << 3)) * ROWB
                                     + (((lane >> 3) & 1) << 4));

    float c[20][4];
#pragma unroll
    for (int j = 0; j < 20; j++)
#pragma unroll
        for (int u = 0; u < 4; u++) c[j][u] = 0.f;

#pragma unroll
    for (int ks = 0; ks < 10; ks++) {
        uint32_t ah[4], al[4];
        ldsm4(ah, sb + PSAH + aOff + ks * 32);
        ldsm4(al, sb + PSAL + aOff + ks * 32);
#pragma unroll
        for (int nb = 0; nb < 10; nb++) {
            uint32_t bh[4], bl[4];
            ldsm4(bh, sb + PSWH + bOff + nb * (16 * ROWB) + ks * 32);
            ldsm4(bl, sb + PSWL + bOff + nb * (16 * ROWB) + ks * 32);
            mma_f16(c[2 * nb],     ah, bh[0], bh[1]);
            mma_f16(c[2 * nb + 1], ah, bh[2], bh[3]);
            mma_f16(c[2 * nb],     ah, bl[0], bl[1]);
            mma_f16(c[2 * nb + 1], ah, bl[2], bl[3]);
            mma_f16(c[2 * nb],     al, bh[0], bh[1]);
            mma_f16(c[2 * nb + 1], al, bh[2], bh[3]);
        }
    }

    const size_t r0 = m0 + 16 * w + (lane >> 2);
    const int cb = 2 * (lane & 3);
#pragma unroll
    for (int j = 0; j < 20; j++) {
        int n = 8 * j + cb;
        float2 bvv = *(const float2*)(bias + n);
        float v0 = (c[j][0] + bvv.x) * ascale, v1 = (c[j][1] + bvv.y) * ascale;
        float v2 = (c[j][2] + bvv.x) * ascale, v3 = (c[j][3] + bvv.y) * ascale;
        __half h0 = __float2half_rn(v0);
        __half h1 = __float2half_rn(v1);
        __half h2 = __float2half_rn(v2);
        __half h3 = __float2half_rn(v3);
        *(uint32_t*)(Chi + r0 * DD + n) =
            ((uint32_t)__half_as_ushort(h1) << 16) | __half_as_ushort(h0);
        *(uint32_t*)(Chi + (r0 + 8) * DD + n) =
            ((uint32_t)__half_as_ushort(h3) << 16) | __half_as_ushort(h2);
        if (Clo) {
            *(uint32_t*)(Clo + r0 * DD + n) =
                packh(v0 - __half2float(h0), v1 - __half2float(h1));
            *(uint32_t*)(Clo + (r0 + 8) * DD + n) =
                packh(v2 - __half2float(h2), v3 - __half2float(h3));
        }
    }
}

// ---------------------------------------------------------------------------
// f16 HMMA flash attention, BN=64 (unchanged from R10/R11):
// Q hi/lo persistent in registers, online max w/ rescale-skip,
// S 3-term, PV 1-term + ones-column (l via MMA), f16x2 exp,
// deferred PV, triple-buffered K/V ring.
// ---------------------------------------------------------------------------
#define SQH   0
#define SQL   43008
#define MKH   0
#define MKL   21504
#define MVH   43008
#define SMEM_TOTAL 193536

__global__ __launch_bounds__(256, 1) void attn_kernel(
    const __half* __restrict__ qhi, const __half* __restrict__ qlo,
    const __half* __restrict__ khi, const __half* __restrict__ klo,
    const __half* __restrict__ vhi,
    const float* __restrict__ gx, float* __restrict__ gout)
{
    extern __shared__ char smem[];
    const uint32_t sb = smem_u32(smem);
    const int tid  = threadIdx.x;
    const int lane = tid & 31;
    const int w    = tid >> 5;
    const int b    = blockIdx.y;
    const int m0   = blockIdx.x * BM;
    const uint32_t bufoff[3] = { 0u, 64512u, 129024u };

    // ---- stage Q (hi/lo) into smem once ----
    {
        const size_t qrow = ((size_t)b * SXX + m0);
#pragma unroll
        for (int i = 0; i < 20; i++) {
            int idx  = i * 256 + tid;
            int half = idx / 2560;
            int rem  = idx - half * 2560;
            int row  = rem / 20, cc = rem - row * 20;
            cp16(sb + (half ? SQL : SQH) + row * ROWB + cc * 16,
                 (half ? qlo : qhi) + (qrow + row) * DD + cc * 8);
        }
    }
    cp_commit();
    cp_wait_all();
    __syncthreads();

    // ---- Q a-frags -> registers (persist across all KV tiles) ----
    const uint32_t qOff = (uint32_t)((16 * w + (lane & 15)) * ROWB
                                     + ((lane >> 4) << 4));
    uint32_t qh_f[10][4], ql_f[10][4];
#pragma unroll
    for (int ks = 0; ks < 10; ks++) {
        ldsm4(qh_f[ks], sb + SQH + qOff + ks * 32);
        ldsm4(ql_f[ks], sb + SQL + qOff + ks * 32);
    }
    __syncthreads();   // staging reads done; smem now owned by KV ring

    // ---- init V pad cols 160-167 of every ring buffer: {1,0,...,0} ----
    if (tid < 192) {
        int bufi = tid / 64, row = tid % 64;
        uint4* p = (uint4*)(smem + bufoff[bufi] + MVH + row * ROWB + 320);
        *p = make_uint4(0x00003C00u, 0u, 0u, 0u);   // half 1.0 at col 160
    }

    const __half* gsrc[3] = {
        khi + (size_t)b * SYY * DD, klo + (size_t)b * SYY * DD,
        vhi + (size_t)b * SYY * DD };
    const int moff[3] = { MKH, MKL, MVH };

    // ---- tile 0 load ----
#pragma unroll
    for (int i = 0; i < 15; i++) {
        int idx = i * 256 + tid;
        int mat = idx / 1280;
        int rem = idx - mat * 1280;
        int row = rem / 20, cc = rem - row * 20;
        cp16(sb + bufoff[0] + moff[mat] + row * ROWB + cc * 16,
             gsrc[mat] + (size_t)row * DD + cc * 8);
    }
    cp_commit();
    cp_wait_all();
    __syncthreads();

    const uint32_t kOff = (uint32_t)(((lane & 7) + ((lane >> 4) << 3)) * ROWB
                                     + (((lane >> 3) & 1) << 4));
    const uint32_t vOff = (uint32_t)(((lane & 7) + (((lane >> 3) & 1) << 3)) * ROWB
                                     + ((lane >> 4) << 4));
    const uint32_t vOff2 = (uint32_t)(((lane & 7) + (((lane >> 3) & 1) << 3)) * ROWB);

    float o[21][4];   // blocks 0..19 = O cols 0..159; block 20 = l (col 160)
#pragma unroll
    for (int j = 0; j < 21; j++)
#pragma unroll
        for (int u = 0; u < 4; u++) o[j][u] = 0.f;

    float mh01 = -INFINITY, mh23 = -INFINITY;
    uint32_t pah[4][4];

    for (int t = 0; t < NT; t++) {
        const uint32_t buf  = sb + bufoff[t % 3];
        const uint32_t pbuf = sb + bufoff[(t + 2) % 3];

        if (t + 1 < NT) {
            const uint32_t nbuf = sb + bufoff[(t + 1) % 3];
            const size_t grow = (size_t)(t + 1) * BN;
#pragma unroll
            for (int i = 0; i < 15; i++) {
                int idx = i * 256 + tid;
                int mat = idx / 1280;
                int rem = idx - mat * 1280;
                int row = rem / 20, cc = rem - row * 20;
                cp16(nbuf + moff[mat] + row * ROWB + cc * 16,
                     gsrc[mat] + (grow + row) * DD + cc * 8);
            }
            cp_commit();
        }

        // ---- S(t) = Q K^T : 3-term f16 hi/lo, Q from registers ----
        float c[8][4];
#pragma unroll
        for (int j = 0; j < 8; j++)
#pragma unroll
            for (int u = 0; u < 4; u++) c[j][u] = 0.f;

#pragma unroll
        for (int ks = 0; ks < 10; ks++) {
#pragma unroll
            for (int nh = 0; nh < 2; nh++) {
                uint32_t bh[8], bl[8];
                uint32_t kb = buf + MKH + kOff + nh * (32 * ROWB) + ks * 32;
                uint32_t lb = buf + MKL + kOff + nh * (32 * ROWB) + ks * 32;
                ldsm4(bh,     kb);
                ldsm4(bh + 4, kb + 16 * ROWB);
                ldsm4(bl,     lb);
                ldsm4(bl + 4, lb + 16 * ROWB);
#pragma unroll
                for (int j = 0; j < 4; j++) {
                    float* cj = c[4 * nh + j];
                    mma_f16(cj, qh_f[ks], bh[2 * j], bh[2 * j + 1]);
                    mma_f16(cj, qh_f[ks], bl[2 * j], bl[2 * j + 1]);
                    mma_f16(cj, ql_f[ks], bh[2 * j], bh[2 * j + 1]);
                }
            }
        }

        // ---- PV(t-1): 1-term (ph*vh) + ones column, k = 64 ----
        if (t > 0) {
#pragma unroll
            for (int ks = 0; ks < 4; ks++) {
#pragma unroll
                for (int jp = 0; jp < 10; jp++) {
                    uint32_t v4h[4];
                    ldsm4t(v4h, pbuf + MVH + vOff + ks * (16 * ROWB) + jp * 32);
                    mma_f16(o[2 * jp],     pah[ks], v4h[0], v4h[1]);
                    mma_f16(o[2 * jp + 1], pah[ks], v4h[2], v4h[3]);
                }
                uint32_t v2[2];
                ldsm2t(v2, pbuf + MVH + vOff2 + ks * (16 * ROWB) + 320);
                mma_f16(o[20], pah[ks], v2[0], v2[1]);
            }
        }

        // ---- online softmax(t): scores in log2 units; exp in f16x2 ----
        float mt01 = fmaxf(c[0][0], c[0][1]);
        float mt23 = fmaxf(c[0][2], c[0][3]);
#pragma unroll
        for (int j = 1; j < 8; j++) {
            mt01 = fmaxf(mt01, fmaxf(c[j][0], c[j][1]));
            mt23 = fmaxf(mt23, fmaxf(c[j][2], c[j][3]));
        }
        mt01 = fmaxf(mt01, __shfl_xor_sync(0xffffffffu, mt01, 1));
        mt01 = fmaxf(mt01, __shfl_xor_sync(0xffffffffu, mt01, 2));
        mt23 = fmaxf(mt23, __shfl_xor_sync(0xffffffffu, mt23, 1));
        mt23 = fmaxf(mt23, __shfl_xor_sync(0xffffffffu, mt23, 2));
        const bool upd = (mt01 > mh01) || (mt23 > mh23);
        float mn01 = fmaxf(mh01, mt01);
        float mn23 = fmaxf(mh23, mt23);
        float a01 = ex2f(mh01 - mn01);
        float a23 = ex2f(mh23 - mn23);
        mh01 = mn01; mh23 = mn23;

#pragma unroll
        for (int j = 0; j < 8; j++) {
            float t0 = c[j][0] - mn01;
            float t1 = c[j][1] - mn01;
            float t2 = c[j][2] - mn23;
            float t3 = c[j][3] - mn23;
            int ks = j >> 1, sl = (j & 1) << 1;
            pah[ks][sl]     = ex2h2(packh(t0, t1));
            pah[ks][sl + 1] = ex2h2(packh(t2, t3));
        }

        if (upd) {   // rescale O (incl. l column) only when max advanced
#pragma unroll
            for (int j = 0; j < 21; j++) {
                o[j][0] *= a01; o[j][1] *= a01;
                o[j][2] *= a23; o[j][3] *= a23;
            }
        }

        cp_wait_all();
        __syncthreads();
    }

    // ---- final PV (tile NT-1) ----
    {
        const uint32_t pbuf = sb + bufoff[(NT - 1) % 3];
#pragma unroll
        for (int ks = 0; ks < 4; ks++) {
#pragma unroll
            for (int jp = 0; jp < 10; jp++) {
                uint32_t v4h[4];
                ldsm4t(v4h, pbuf + MVH + vOff + ks * (16 * ROWB) + jp * 32);
                mma_f16(o[2 * jp],     pah[ks], v4h[0], v4h[1]);
                mma_f16(o[2 * jp + 1], pah[ks], v4h[2], v4h[3]);
            }
            uint32_t v2[2];
            ldsm2t(v2, pbuf + MVH + vOff2 + ks * (16 * ROWB) + 320);
            mma_f16(o[20], pah[ks], v2[0], v2[1]);
        }
    }

    // ---- epilogue: l = O col 160 (held by lanes with lane&3 == 0) ----
    const int srcl = lane & ~3;
    const float l01 = __shfl_sync(0xffffffffu, o[20][0], srcl);
    const float l23 = __shfl_sync(0xffffffffu, o[20][2], srcl);
    const float inv01 = 1.f / l01;
    const float inv23 = 1.f / l23;

    const int r0 = m0 + 16 * w + (lane >> 2);
    const size_t row0 = ((size_t)b * SXX + r0) * DD;
    const size_t row1 = row0 + 8 * DD;
    const int cb = 2 * (lane & 3);
#pragma unroll
    for (int j = 0; j < 20; j++) {
        int cc = 8 * j + cb;
        float2 x0 = *(const float2*)(gx + row0 + cc);
        float2 x1 = *(const float2*)(gx + row1 + cc);
        float2 r0v, r1v;
        r0v.x = o[j][0] * inv01 + x0.x;
        r0v.y = o[j][1] * inv01 + x0.y;
        r1v.x = o[j][2] * inv23 + x1.x;
        r1v.y = o[j][3] * inv23 + x1.y;
        *(float2*)(gout + row0 + cc) = r0v;
        *(float2*)(gout + row1 + cc) = r1v;
    }
}

// ---------------------------------------------------------------------------
extern "C" void kernel_launch(void* const* d_in, const int* in_sizes, int n_in,
                              void* d_out, int out_size)
{
    const float* x  = (const float*)d_in[0];
    const float* y  = (const float*)d_in[1];
    const float* Wq = (const float*)d_in[2];
    const float* bq = (const float*)d_in[3];
    const float* Wk = (const float*)d_in[4];
    const float* bk = (const float*)d_in[5];
    const float* Wv = (const float*)d_in[6];
    const float* bv = (const float*)d_in[7];
    float* out = (float*)d_out;

    __half *qh, *ql, *kh, *kl, *vh;
    cudaGetSymbolAddress((void**)&qh, g_qhi);  cudaGetSymbolAddress((void**)&ql, g_qlo);
    cudaGetSymbolAddress((void**)&kh, g_khi);  cudaGetSymbolAddress((void**)&kl, g_klo);
    cudaGetSymbolAddress((void**)&vh, g_vhi);

    cudaFuncSetAttribute(proj_mma,
                         cudaFuncAttributeMaxDynamicSharedMemorySize, PROJ_SMEM);
    dim3 pgrid((B_ * SXX) / BM, 3);   // 512 x 3
    proj_mma<<<pgrid, 256, PROJ_SMEM>>>(x, y, Wq, Wk, Wv,
                                        bq, bk, bv,
                                        qh, ql, kh, kl, vh);

    cudaFuncSetAttribute(attn_kernel,
                         cudaFuncAttributeMaxDynamicSharedMemorySize, SMEM_TOTAL);
    dim3 grid(SXX / BM, B_);
    attn_kernel<<<grid, 256, SMEM_TOTAL>>>(qh, ql, kh, kl, vh, x, out);
}